// round 9
// baseline (speedup 1.0000x reference)
#include <cuda_runtime.h>
#include <cuda_bf16.h>
#include <cstdint>
#include <cstddef>

// ---------------------------------------------------------------------------
// HeteroSAGE on GB300 — Round 9: 128x64 tile, 3 CTAs/SM occupancy push
//  * warp tile 32x32 (acc 32 regs), grid.y = column half, launch_bounds(256,3)
//  * keeps: P=h@Wl dedup, epilogue gather-add, 3-stage cp.async, swizzle
// ---------------------------------------------------------------------------

namespace {
constexpr int H_      = 128;
constexpr int N_TX    = 200000;
constexpr int N_CARD  = 50000;
constexpr int N_MERCH = 10000;
constexpr int N_EDGE  = 200000;
constexpr int A_PLANE = 128 * 64;            // 8192 B
constexpr int B_PLANE = 64 * 64;             // 4096 B
constexpr int STAGE_B = 2 * A_PLANE + 2 * B_PLANE;  // 24576
constexpr int NSTAGE  = 3;
constexpr int SMEM_BYTES = NSTAGE * STAGE_B + 512;  // 74240

constexpr int SZ128 = 2 * 128 * 128;
constexpr int SZ64  = 2 * 128 * 64;
constexpr int OFF_TXW   = 0;
constexpr int OFF_CPROJ = OFF_TXW + SZ128;
constexpr int OFF_MPROJ = OFF_CPROJ + SZ64;
constexpr int OFF_H1    = OFF_MPROJ + SZ64;
constexpr int OFF_L0    = OFF_H1 + SZ128;
constexpr int WT_TOTAL  = OFF_L0 + 14 * SZ128;
__host__ __device__ constexpr int OFF_LAYER(int l, int j) { return OFF_L0 + (l * 7 + j) * SZ128; }
}

// ---------------- scratch ----------------------------------------------------
__device__ __align__(16) __nv_bfloat16 g_atx0[2 * (size_t)N_TX * H_];
__device__ __align__(16) __nv_bfloat16 g_atx1[2 * (size_t)N_TX * H_];
__device__ __align__(16) __nv_bfloat16 g_acard0[2 * (size_t)N_CARD * H_];
__device__ __align__(16) __nv_bfloat16 g_acard1[2 * (size_t)N_CARD * H_];
__device__ __align__(16) __nv_bfloat16 g_amerch0[2 * (size_t)N_MERCH * H_];
__device__ __align__(16) __nv_bfloat16 g_amerch1[2 * (size_t)N_MERCH * H_];
__device__ __align__(16) float g_pcard[(size_t)N_CARD * H_];
__device__ __align__(16) float g_pmerch[(size_t)N_MERCH * H_];
__device__ float g_aggc[(size_t)N_CARD * H_];
__device__ float g_aggm[(size_t)N_MERCH * H_];
__device__ float g_invc[N_CARD];
__device__ float g_invm[N_MERCH];
__device__ float g_bcomb[2 * H_];
__device__ float g_zbias[H_];
__device__ __align__(16) __nv_bfloat16 g_wt[WT_TOTAL];

// ---------------- PTX helpers ------------------------------------------------
__device__ __forceinline__ uint32_t smem_u32(const void* p) {
    uint32_t a;
    asm("{ .reg .u64 t; cvta.to.shared.u64 t, %1; cvt.u32.u64 %0, t; }" : "=r"(a) : "l"(p));
    return a;
}
__device__ __forceinline__ void ldsm_x4(uint32_t* r, uint32_t addr) {
    asm volatile("ldmatrix.sync.aligned.m8n8.x4.shared.b16 {%0,%1,%2,%3}, [%4];"
                 : "=r"(r[0]), "=r"(r[1]), "=r"(r[2]), "=r"(r[3]) : "r"(addr));
}
__device__ __forceinline__ void mma_bf16(float* c, const uint32_t* a, const uint32_t* b) {
    asm volatile(
        "mma.sync.aligned.m16n8k16.row.col.f32.bf16.bf16.f32 "
        "{%0,%1,%2,%3}, {%4,%5,%6,%7}, {%8,%9}, {%0,%1,%2,%3};"
        : "+f"(c[0]), "+f"(c[1]), "+f"(c[2]), "+f"(c[3])
        : "r"(a[0]), "r"(a[1]), "r"(a[2]), "r"(a[3]), "r"(b[0]), "r"(b[1]));
}
__device__ __forceinline__ void cp16(uint32_t dst, const void* src) {
    asm volatile("cp.async.cg.shared.global [%0], [%1], 16;" :: "r"(dst), "l"(src) : "memory");
}
#define CP_COMMIT()  asm volatile("cp.async.commit_group;" ::: "memory")
#define CP_WAIT1()   asm volatile("cp.async.wait_group 1;" ::: "memory")

__device__ __forceinline__ uint32_t swz(int r, int c) {
    return (uint32_t)r * 64u + (uint32_t)(((c ^ (r >> 1)) & 3) * 16);
}

// ---------------- small kernels ----------------------------------------------
__global__ void count_kernel(const int* __restrict__ ec, const int* __restrict__ em,
                             float* __restrict__ cc, float* __restrict__ cm, int E) {
    int i = blockIdx.x * blockDim.x + threadIdx.x;
    if (i < E) {
        atomicAdd(&cc[ec[i]], 1.0f);
        atomicAdd(&cm[em[i]], 1.0f);
    }
}

__global__ void invert_kernel(float* __restrict__ c, int n) {
    int i = blockIdx.x * blockDim.x + threadIdx.x;
    if (i < n) c[i] = 1.0f / fmaxf(c[i], 1.0f);
}

__global__ void combine_bias(const float* __restrict__ bl, float* __restrict__ bc) {
    int i = blockIdx.x * blockDim.x + threadIdx.x;
    if (i < 2 * H_) {
        int l = i >> 7, j = i & 127;
        bc[i] = bl[(l * 4 + 0) * H_ + j] + bl[(l * 4 + 2) * H_ + j];
    }
}

__global__ void init_out(float* __restrict__ out, const float* __restrict__ b2, int n) {
    int i = blockIdx.x * blockDim.x + threadIdx.x;
    if (i < n) out[i] = __ldg(&b2[0]);
}

__global__ void scatter_kernel(const __nv_bfloat16* __restrict__ th,
                               const __nv_bfloat16* __restrict__ tl,
                               const int* __restrict__ ec, const int* __restrict__ em,
                               float* __restrict__ aggc, float* __restrict__ aggm) {
    int idx = blockIdx.x * blockDim.x + threadIdx.x;
    if (idx >= N_EDGE * 32) return;
    int e = idx >> 5, q = idx & 31;
    int f = q * 4;
    const size_t base = (size_t)e * H_ + f;
    uint2 hv = *(const uint2*)(th + base);
    uint2 lv = *(const uint2*)(tl + base);
    __nv_bfloat162 h0 = *reinterpret_cast<__nv_bfloat162*>(&hv.x);
    __nv_bfloat162 h1 = *reinterpret_cast<__nv_bfloat162*>(&hv.y);
    __nv_bfloat162 l0 = *reinterpret_cast<__nv_bfloat162*>(&lv.x);
    __nv_bfloat162 l1 = *reinterpret_cast<__nv_bfloat162*>(&lv.y);
    float v0 = __bfloat162float(h0.x) + __bfloat162float(l0.x);
    float v1 = __bfloat162float(h0.y) + __bfloat162float(l0.y);
    float v2 = __bfloat162float(h1.x) + __bfloat162float(l1.x);
    float v3 = __bfloat162float(h1.y) + __bfloat162float(l1.y);
    float* pc = aggc + (size_t)__ldg(&ec[e]) * H_ + f;
    asm volatile("red.global.add.v4.f32 [%0], {%1,%2,%3,%4};"
                 :: "l"(pc), "f"(v0), "f"(v1), "f"(v2), "f"(v3) : "memory");
    float* pm = aggm + (size_t)__ldg(&em[e]) * H_ + f;
    asm volatile("red.global.add.v4.f32 [%0], {%1,%2,%3,%4};"
                 :: "l"(pm), "f"(v0), "f"(v1), "f"(v2), "f"(v3) : "memory");
}

struct PrepEnt { const float* s1; const float* s2; int K; int off; };
struct PrepArgs { PrepEnt e[18]; };

__global__ void prep_weights(PrepArgs pa, __nv_bfloat16* __restrict__ wt) {
    PrepEnt en = pa.e[blockIdx.x];
    int total = 128 * en.K;
    for (int i = threadIdx.x; i < total; i += blockDim.x) {
        int n = i / en.K, k = i - n * en.K;
        float v = en.s1[(size_t)k * H_ + n];
        if (en.s2) v += en.s2[(size_t)k * H_ + n];
        __nv_bfloat16 h = __float2bfloat16(v);
        float r = v - __bfloat162float(h);
        wt[en.off + (size_t)n * en.K + k] = h;
        wt[en.off + (size_t)128 * en.K + (size_t)n * en.K + k] = __float2bfloat16(r);
    }
}

// ---------------------------------------------------------------------------
// 128x64 tile (grid.y = column half), 256 threads (8 warps: 4 rowG x 2 colG,
// warp tile 32x32), KC=32 chunks, 3-stage pipeline, 3 CTAs/SM.
// ---------------------------------------------------------------------------
__global__ __launch_bounds__(256, 3) void mma_gemm(
    int M,
    const float* __restrict__ A0f, const __nv_bfloat16* __restrict__ A0h,
    const __nv_bfloat16* __restrict__ A0l,
    const int* __restrict__ I0, const float* __restrict__ S0, int w0, int K0,
    const float* __restrict__ A1f, const __nv_bfloat16* __restrict__ A1h,
    const __nv_bfloat16* __restrict__ A1l,
    const int* __restrict__ I1, int w1, int K1,
    const float* __restrict__ A2f, const __nv_bfloat16* __restrict__ A2h,
    const __nv_bfloat16* __restrict__ A2l, int w2, int K2,
    const __nv_bfloat16* __restrict__ wt,
    const float* __restrict__ bias,
    __nv_bfloat16* __restrict__ Ch, __nv_bfloat16* __restrict__ Cl, int doRelu,
    float* __restrict__ Cf,
    const float* __restrict__ GA0, const int* __restrict__ GAI0,
    const float* __restrict__ GA1, const int* __restrict__ GAI1,
    const float* __restrict__ hw2, float* __restrict__ hout) {
    extern __shared__ __align__(16) char smem_raw[];
    const uint32_t sb = smem_u32(smem_raw);
    float* partial = (float*)(smem_raw + NSTAGE * STAGE_B);

    const int tid = threadIdx.x, warp = tid >> 5, lane = tid & 31;
    const int rowG = warp >> 1, colG = warp & 1;
    const int row0 = blockIdx.x * 128;
    const int nby  = blockIdx.y;              // column half (0/1)
    const bool headMode = (hout != nullptr);
    if (headMode && tid < 128) partial[tid] = 0.0f;

    const float* srcF[3] = {A0f, A1f, A2f};
    const __nv_bfloat16* srcH[3] = {A0h, A1h, A2h};
    const __nv_bfloat16* srcL[3] = {A0l, A1l, A2l};
    const int Ks[3] = {K0, K1, K2};
    const int wof[3] = {w0, w1, w2};
    const int nch0 = K0 >> 5, nch1 = K1 >> 5, nch2 = K2 >> 5;
    const int ntot = nch0 + nch1 + nch2;

    const int lrow = tid >> 1, lsel = tid & 1;
    // B loader mapping: plane p = tid&1, row br = (tid>>1)&63, half = tid>>7
    const int bp = tid & 1, br = (tid >> 1) & 63, bhalf = tid >> 7;

    int gi[3];
    float sc_[3];
    {
        int r = row0 + lrow;
        if (r >= M) r = M - 1;
        int g0 = r, g1 = r;
        if (I0) g0 = __ldg(&I0[r]);
        if (I1) g1 = __ldg(&I1[r]);
        gi[0] = g0; gi[1] = g1; gi[2] = r;
        sc_[0] = S0 ? __ldg(&S0[g0]) : 1.0f;
        sc_[1] = 1.0f; sc_[2] = 1.0f;
    }

    float acc[2][4][4];
#pragma unroll
    for (int mt = 0; mt < 2; mt++)
#pragma unroll
        for (int nt = 0; nt < 4; nt++)
#pragma unroll
            for (int j = 0; j < 4; j++) acc[mt][nt][j] = 0.0f;

    auto issue = [&](int c, int stage) {
        int s, kb;
        if (c < nch0) { s = 0; kb = c << 5; }
        else if (c < nch0 + nch1) { s = 1; kb = (c - nch0) << 5; }
        else { s = 2; kb = (c - nch0 - nch1) << 5; }
        const uint32_t base = sb + stage * STAGE_B;
        // B: 64 rows (global n = nby*64 + br), 2 planes, 2 threads per row-plane
        {
            const __nv_bfloat16* bsrc = wt + wof[s] +
                (bp ? (size_t)128 * Ks[s] : 0) + (size_t)(nby * 64 + br) * Ks[s] + kb;
            const uint32_t bpl = base + 2 * A_PLANE + bp * B_PLANE;
#pragma unroll
            for (int j = 0; j < 2; j++) {
                int jj = bhalf * 2 + j;
                cp16(bpl + swz(br, jj), bsrc + jj * 8);
            }
        }
        if (srcF[s] == nullptr) {
            const __nv_bfloat16* asrc =
                (lsel ? srcL[s] : srcH[s]) + (size_t)gi[s] * 128 + kb;
            const uint32_t apl = base + (lsel ? A_PLANE : 0);
#pragma unroll
            for (int j = 0; j < 4; j++) cp16(apl + swz(lrow, j), asrc + j * 8);
        } else {
            const float sc = sc_[s];
            const float* ap = srcF[s] + (size_t)gi[s] * Ks[s] + kb + lsel * 16;
            float4 x = *(const float4*)(ap);
            float4 y = *(const float4*)(ap + 4);
            float4 z = *(const float4*)(ap + 8);
            float4 u = *(const float4*)(ap + 12);
            float v[16] = {x.x, x.y, x.z, x.w, y.x, y.y, y.z, y.w,
                           z.x, z.y, z.z, z.w, u.x, u.y, u.z, u.w};
            uint32_t hw_[8], lw_[8];
#pragma unroll
            for (int j = 0; j < 8; j++) {
                float a0 = v[2 * j] * sc, a1 = v[2 * j + 1] * sc;
                __nv_bfloat16 h0 = __float2bfloat16(a0);
                __nv_bfloat16 h1 = __float2bfloat16(a1);
                __nv_bfloat162 hp; hp.x = h0; hp.y = h1;
                __nv_bfloat162 lp;
                lp.x = __float2bfloat16(a0 - __bfloat162float(h0));
                lp.y = __float2bfloat16(a1 - __bfloat162float(h1));
                hw_[j] = *reinterpret_cast<uint32_t*>(&hp);
                lw_[j] = *reinterpret_cast<uint32_t*>(&lp);
            }
            const uint32_t aH0 = base + swz(lrow, lsel * 2);
            const uint32_t aH1 = base + swz(lrow, lsel * 2 + 1);
            asm volatile("st.shared.v4.b32 [%0], {%1,%2,%3,%4};"
                         :: "r"(aH0), "r"(hw_[0]), "r"(hw_[1]), "r"(hw_[2]), "r"(hw_[3]) : "memory");
            asm volatile("st.shared.v4.b32 [%0], {%1,%2,%3,%4};"
                         :: "r"(aH1), "r"(hw_[4]), "r"(hw_[5]), "r"(hw_[6]), "r"(hw_[7]) : "memory");
            asm volatile("st.shared.v4.b32 [%0], {%1,%2,%3,%4};"
                         :: "r"(aH0 + A_PLANE), "r"(lw_[0]), "r"(lw_[1]), "r"(lw_[2]), "r"(lw_[3]) : "memory");
            asm volatile("st.shared.v4.b32 [%0], {%1,%2,%3,%4};"
                         :: "r"(aH1 + A_PLANE), "r"(lw_[4]), "r"(lw_[5]), "r"(lw_[6]), "r"(lw_[7]) : "memory");
        }
    };

    const int laneR = lane & 15;
    const int xorA = (laneR >> 1) & 3;
    const int cA0  = lane >> 4;
    const int n_off = (((lane >> 4) & 1) * 8) + (lane & 7);
    const int xorB = (n_off >> 1) & 3;
    const int cB0  = (lane >> 3) & 1;

    auto compute = [&](int stage) {
        const uint32_t base = sb + stage * STAGE_B;
        const uint32_t aRow = base + (uint32_t)(rowG * 32 + laneR) * 64;
        const uint32_t bRow = base + 2 * A_PLANE + (uint32_t)(colG * 32 + n_off) * 64;
#pragma unroll
        for (int ks = 0; ks < 2; ks++) {
            const uint32_t aC = (uint32_t)((cA0 + 2 * ks) ^ xorA) * 16;
            const uint32_t bC = (uint32_t)((cB0 + 2 * ks) ^ xorB) * 16;
            uint32_t bh[4][2], bl[4][2];
#pragma unroll
            for (int np = 0; np < 2; np++) {
                uint32_t r4[4];
                ldsm_x4(r4, bRow + np * (16 * 64) + bC);
                bh[np * 2][0] = r4[0]; bh[np * 2][1] = r4[1];
                bh[np * 2 + 1][0] = r4[2]; bh[np * 2 + 1][1] = r4[3];
                ldsm_x4(r4, bRow + B_PLANE + np * (16 * 64) + bC);
                bl[np * 2][0] = r4[0]; bl[np * 2][1] = r4[1];
                bl[np * 2 + 1][0] = r4[2]; bl[np * 2 + 1][1] = r4[3];
            }
#pragma unroll
            for (int mt = 0; mt < 2; mt++) {
                uint32_t ah[4], al[4];
                ldsm_x4(ah, aRow + mt * (16 * 64) + aC);
                ldsm_x4(al, aRow + A_PLANE + mt * (16 * 64) + aC);
#pragma unroll
                for (int nt = 0; nt < 4; nt++) {
                    mma_bf16(acc[mt][nt], ah, bh[nt]);
                    mma_bf16(acc[mt][nt], ah, bl[nt]);
                    mma_bf16(acc[mt][nt], al, bh[nt]);
                }
            }
        }
    };

    issue(0, 0);
    CP_COMMIT();
    if (ntot > 1) issue(1, 1);
    CP_COMMIT();
    int st_ = 0;
#pragma unroll 1
    for (int c = 0; c < ntot; c++) {
        CP_WAIT1();
        __syncthreads();
        if (c + 2 < ntot) {
            int s2 = st_ + 2; if (s2 >= NSTAGE) s2 -= NSTAGE;
            issue(c + 2, s2);
        }
        CP_COMMIT();
        compute(st_);
        if (++st_ == NSTAGE) st_ = 0;
    }

    const int rIn = lane >> 2;
    const int cIn = (lane & 3) * 2;
    if (!headMode) {
#pragma unroll
        for (int mt = 0; mt < 2; mt++) {
            const int r0 = row0 + rowG * 32 + mt * 16 + rIn;
            const int r1 = r0 + 8;
            const bool v0r = r0 < M, v1r = r1 < M;
            const float *g00 = nullptr, *g01 = nullptr, *g10 = nullptr, *g11 = nullptr;
            if (GA0) {
                if (v0r) g00 = GA0 + (size_t)__ldg(&GAI0[r0]) * H_;
                if (v1r) g01 = GA0 + (size_t)__ldg(&GAI0[r1]) * H_;
            }
            if (GA1) {
                if (v0r) g10 = GA1 + (size_t)__ldg(&GAI1[r0]) * H_;
                if (v1r) g11 = GA1 + (size_t)__ldg(&GAI1[r1]) * H_;
            }
#pragma unroll
            for (int nt = 0; nt < 4; nt++) {
                const int col = nby * 64 + colG * 32 + nt * 8 + cIn;
                const float b0 = __ldg(&bias[col]), b1 = __ldg(&bias[col + 1]);
                float o00 = acc[mt][nt][0] + b0, o01 = acc[mt][nt][1] + b1;
                float o10 = acc[mt][nt][2] + b0, o11 = acc[mt][nt][3] + b1;
                if (g00) { float2 g = *(const float2*)(g00 + col); o00 += g.x; o01 += g.y; }
                if (g10) { float2 g = *(const float2*)(g10 + col); o00 += g.x; o01 += g.y; }
                if (g01) { float2 g = *(const float2*)(g01 + col); o10 += g.x; o11 += g.y; }
                if (g11) { float2 g = *(const float2*)(g11 + col); o10 += g.x; o11 += g.y; }
                if (doRelu) {
                    o00 = fmaxf(o00, 0.f); o01 = fmaxf(o01, 0.f);
                    o10 = fmaxf(o10, 0.f); o11 = fmaxf(o11, 0.f);
                }
                if (Cf) {
                    if (v0r) *(float2*)(Cf + (size_t)r0 * H_ + col) = make_float2(o00, o01);
                    if (v1r) *(float2*)(Cf + (size_t)r1 * H_ + col) = make_float2(o10, o11);
                } else {
                    if (v0r) {
                        __nv_bfloat162 hp, lp;
                        hp.x = __float2bfloat16(o00); hp.y = __float2bfloat16(o01);
                        lp.x = __float2bfloat16(o00 - __bfloat162float(hp.x));
                        lp.y = __float2bfloat16(o01 - __bfloat162float(hp.y));
                        *(__nv_bfloat162*)(Ch + (size_t)r0 * H_ + col) = hp;
                        *(__nv_bfloat162*)(Cl + (size_t)r0 * H_ + col) = lp;
                    }
                    if (v1r) {
                        __nv_bfloat162 hp, lp;
                        hp.x = __float2bfloat16(o10); hp.y = __float2bfloat16(o11);
                        lp.x = __float2bfloat16(o10 - __bfloat162float(hp.x));
                        lp.y = __float2bfloat16(o11 - __bfloat162float(hp.y));
                        *(__nv_bfloat162*)(Ch + (size_t)r1 * H_ + col) = hp;
                        *(__nv_bfloat162*)(Cl + (size_t)r1 * H_ + col) = lp;
                    }
                }
            }
        }
    } else {
        // head: partial dot over this CTA's 64 cols; global atomicAdd to hout
        float h0[2], h1[2];
#pragma unroll
        for (int mt = 0; mt < 2; mt++) { h0[mt] = 0.f; h1[mt] = 0.f; }
#pragma unroll
        for (int mt = 0; mt < 2; mt++)
#pragma unroll
            for (int nt = 0; nt < 4; nt++) {
                const int col = nby * 64 + colG * 32 + nt * 8 + cIn;
                const float b0 = __ldg(&bias[col]), b1 = __ldg(&bias[col + 1]);
                const float w20 = __ldg(&hw2[col]), w21 = __ldg(&hw2[col + 1]);
                h0[mt] = fmaf(fmaxf(acc[mt][nt][0] + b0, 0.f), w20, h0[mt]);
                h0[mt] = fmaf(fmaxf(acc[mt][nt][1] + b1, 0.f), w21, h0[mt]);
                h1[mt] = fmaf(fmaxf(acc[mt][nt][2] + b0, 0.f), w20, h1[mt]);
                h1[mt] = fmaf(fmaxf(acc[mt][nt][3] + b1, 0.f), w21, h1[mt]);
            }
#pragma unroll
        for (int mt = 0; mt < 2; mt++) {
            h0[mt] += __shfl_xor_sync(0xffffffffu, h0[mt], 1);
            h0[mt] += __shfl_xor_sync(0xffffffffu, h0[mt], 2);
            h1[mt] += __shfl_xor_sync(0xffffffffu, h1[mt], 1);
            h1[mt] += __shfl_xor_sync(0xffffffffu, h1[mt], 2);
        }
        if ((lane & 3) == 0) {
#pragma unroll
            for (int mt = 0; mt < 2; mt++) {
                atomicAdd(&partial[rowG * 32 + mt * 16 + rIn], h0[mt]);
                atomicAdd(&partial[rowG * 32 + mt * 16 + rIn + 8], h1[mt]);
            }
        }
        __syncthreads();
        if (tid < 128) {
            const int r = row0 + tid;
            if (r < M) atomicAdd(&hout[r], partial[tid]);
        }
    }
}

// ---------------------------------------------------------------------------
extern "C" void kernel_launch(void* const* d_in, const int* in_sizes, int n_in,
                              void* d_out, int out_size) {
    const float* tx_x         = (const float*)d_in[0];
    const int*   e_card       = (const int*)d_in[3];
    const int*   e_merch      = (const int*)d_in[5];
    const float* card_emb     = (const float*)d_in[7];
    const float* merch_emb    = (const float*)d_in[8];
    const float* card_proj_W  = (const float*)d_in[9];
    const float* card_proj_b  = (const float*)d_in[10];
    const float* merch_proj_W = (const float*)d_in[11];
    const float* merch_proj_b = (const float*)d_in[12];
    const float* tx_W         = (const float*)d_in[13];
    const float* tx_b         = (const float*)d_in[14];
    const float* conv_Wl      = (const float*)d_in[15];
    const float* conv_bl      = (const float*)d_in[16];
    const float* conv_Wr      = (const float*)d_in[17];
    const float* h1_W         = (const float*)d_in[18];
    const float* h1_b         = (const float*)d_in[19];
    const float* h2_W         = (const float*)d_in[20];
    const float* h2_b         = (const float*)d_in[21];
    float* out = (float*)d_out;

    __nv_bfloat16 *atx[2], *acard[2], *amerch[2], *wt;
    float *pcard, *pmerch, *aggc, *aggm, *invc, *invm, *bcomb, *zbias;
    cudaGetSymbolAddress((void**)&atx[0],    g_atx0);
    cudaGetSymbolAddress((void**)&atx[1],    g_atx1);
    cudaGetSymbolAddress((void**)&acard[0],  g_acard0);
    cudaGetSymbolAddress((void**)&acard[1],  g_acard1);
    cudaGetSymbolAddress((void**)&amerch[0], g_amerch0);
    cudaGetSymbolAddress((void**)&amerch[1], g_amerch1);
    cudaGetSymbolAddress((void**)&pcard,  g_pcard);
    cudaGetSymbolAddress((void**)&pmerch, g_pmerch);
    cudaGetSymbolAddress((void**)&aggc,   g_aggc);
    cudaGetSymbolAddress((void**)&aggm,   g_aggm);
    cudaGetSymbolAddress((void**)&invc,   g_invc);
    cudaGetSymbolAddress((void**)&invm,   g_invm);
    cudaGetSymbolAddress((void**)&bcomb,  g_bcomb);
    cudaGetSymbolAddress((void**)&zbias,  g_zbias);
    cudaGetSymbolAddress((void**)&wt,     g_wt);

    const size_t PTX = (size_t)N_TX * H_;
    const size_t PCD = (size_t)N_CARD * H_;
    const size_t PMR = (size_t)N_MERCH * H_;

    cudaFuncSetAttribute(mma_gemm, cudaFuncAttributeMaxDynamicSharedMemorySize, SMEM_BYTES);

    cudaStream_t st = 0;
    const int E = in_sizes[3];

    PrepArgs pa;
    {
        int i = 0;
        auto ent = [&](const float* s1, const float* s2, int K, int off) {
            pa.e[i].s1 = s1; pa.e[i].s2 = s2; pa.e[i].K = K; pa.e[i].off = off; i++;
        };
        const size_t WSZ = (size_t)H_ * H_;
        ent(tx_W,         nullptr, 128, OFF_TXW);
        ent(card_proj_W,  nullptr,  64, OFF_CPROJ);
        ent(merch_proj_W, nullptr,  64, OFF_MPROJ);
        ent(h1_W,         nullptr, 128, OFF_H1);
        for (int l = 0; l < 2; l++) {
            const float* Wl0 = conv_Wl + (size_t)(l * 4 + 0) * WSZ;
            const float* Wl1 = conv_Wl + (size_t)(l * 4 + 1) * WSZ;
            const float* Wl2 = conv_Wl + (size_t)(l * 4 + 2) * WSZ;
            const float* Wl3 = conv_Wl + (size_t)(l * 4 + 3) * WSZ;
            const float* Wr0 = conv_Wr + (size_t)(l * 4 + 0) * WSZ;
            const float* Wr1 = conv_Wr + (size_t)(l * 4 + 1) * WSZ;
            const float* Wr2 = conv_Wr + (size_t)(l * 4 + 2) * WSZ;
            const float* Wr3 = conv_Wr + (size_t)(l * 4 + 3) * WSZ;
            ent(Wl0, nullptr, 128, OFF_LAYER(l, 0));
            ent(Wl2, nullptr, 128, OFF_LAYER(l, 1));
            ent(Wr0, Wr2,     128, OFF_LAYER(l, 2));
            ent(Wl1, nullptr, 128, OFF_LAYER(l, 3));
            ent(Wr1, nullptr, 128, OFF_LAYER(l, 4));
            ent(Wl3, nullptr, 128, OFF_LAYER(l, 5));
            ent(Wr3, nullptr, 128, OFF_LAYER(l, 6));
        }
    }

    auto grid = [](int m) { return dim3((unsigned)((m + 127) / 128), 2, 1); };
    const __nv_bfloat16* NB = nullptr;
    const float* NF = nullptr;
    const int* NI = nullptr;

    // positions 0..4, then the big tx GEMM at launch index 5 (ncu -s 5 -c 1)
    prep_weights<<<18, 256, 0, st>>>(pa, wt);                                   // 0
    combine_bias<<<1, 256, 0, st>>>(conv_bl, bcomb);                            // 1
    cudaMemsetAsync(invc, 0, N_CARD * sizeof(float), st);                       // 2
    cudaMemsetAsync(invm, 0, N_MERCH * sizeof(float), st);                      // 3
    count_kernel<<<(E + 255) / 256, 256, 0, st>>>(e_card, e_merch, invc, invm, E); // 4
    mma_gemm<<<grid(N_TX), 256, SMEM_BYTES, st>>>(N_TX,                         // 5 <- profiled
        tx_x, NB, NB, nullptr, nullptr, OFF_TXW, 128,
        nullptr, NB, NB, nullptr, 0, 0,
        nullptr, NB, NB, 0, 0,
        wt, tx_b, atx[0], atx[0] + PTX, 1, nullptr,
        NF, NI, NF, NI, nullptr, nullptr);
    init_out<<<(N_TX + 255) / 256, 256, 0, st>>>(out, h2_b, N_TX);
    invert_kernel<<<(N_CARD + 255) / 256, 256, 0, st>>>(invc, N_CARD);
    invert_kernel<<<(N_MERCH + 255) / 256, 256, 0, st>>>(invm, N_MERCH);
    mma_gemm<<<grid(N_CARD), 256, SMEM_BYTES, st>>>(N_CARD,
        card_emb, NB, NB, nullptr, nullptr, OFF_CPROJ, 64,
        nullptr, NB, NB, nullptr, 0, 0,
        nullptr, NB, NB, 0, 0,
        wt, card_proj_b, acard[0], acard[0] + PCD, 0, nullptr,
        NF, NI, NF, NI, nullptr, nullptr);
    mma_gemm<<<grid(N_MERCH), 256, SMEM_BYTES, st>>>(N_MERCH,
        merch_emb, NB, NB, nullptr, nullptr, OFF_MPROJ, 64,
        nullptr, NB, NB, nullptr, 0, 0,
        nullptr, NB, NB, 0, 0,
        wt, merch_proj_b, amerch[0], amerch[0] + PMR, 0, nullptr,
        NF, NI, NF, NI, nullptr, nullptr);

    int cur = 0;
    for (int l = 0; l < 2; l++) {
        int nxt = cur ^ 1;
        cudaMemsetAsync(aggc, 0, PCD * sizeof(float), st);
        cudaMemsetAsync(aggm, 0, PMR * sizeof(float), st);
        scatter_kernel<<<(N_EDGE * 32 + 255) / 256, 256, 0, st>>>(
            atx[cur], atx[cur] + PTX, e_card, e_merch, aggc, aggm);

        const float* bl1 = conv_bl + (l * 4 + 1) * H_;
        const float* bl3 = conv_bl + (l * 4 + 3) * H_;

        // P_card = h_card @ Wl0 (fp32 out, zero bias)
        mma_gemm<<<grid(N_CARD), 256, SMEM_BYTES, st>>>(N_CARD,
            nullptr, acard[cur], acard[cur] + PCD, nullptr, nullptr, OFF_LAYER(l, 0), 128,
            nullptr, NB, NB, nullptr, 0, 0,
            nullptr, NB, NB, 0, 0,
            wt, zbias, nullptr, nullptr, 0, pcard,
            NF, NI, NF, NI, nullptr, nullptr);
        // P_merch = h_merch @ Wl2
        mma_gemm<<<grid(N_MERCH), 256, SMEM_BYTES, st>>>(N_MERCH,
            nullptr, amerch[cur], amerch[cur] + PMR, nullptr, nullptr, OFF_LAYER(l, 1), 128,
            nullptr, NB, NB, nullptr, 0, 0,
            nullptr, NB, NB, 0, 0,
            wt, zbias, nullptr, nullptr, 0, pmerch,
            NF, NI, NF, NI, nullptr, nullptr);
        // tx: h_tx@Wcomb + gather(P_card) + gather(P_merch) + bcomb, relu
        mma_gemm<<<grid(N_TX), 256, SMEM_BYTES, st>>>(N_TX,
            nullptr, atx[cur], atx[cur] + PTX, nullptr, nullptr, OFF_LAYER(l, 2), 128,
            nullptr, NB, NB, nullptr, 0, 0,
            nullptr, NB, NB, 0, 0,
            wt, bcomb + l * H_, atx[nxt], atx[nxt] + PTX, 1, nullptr,
            pcard, e_card, pmerch, e_merch, nullptr, nullptr);
        // card: (agg*inv)@Wl1 + h_card@Wr1 + bl1, relu
        mma_gemm<<<grid(N_CARD), 256, SMEM_BYTES, st>>>(N_CARD,
            aggc, NB, NB, nullptr, invc, OFF_LAYER(l, 3), 128,
            nullptr, acard[cur], acard[cur] + PCD, nullptr, OFF_LAYER(l, 4), 128,
            nullptr, NB, NB, 0, 0,
            wt, bl1, acard[nxt], acard[nxt] + PCD, 1, nullptr,
            NF, NI, NF, NI, nullptr, nullptr);
        // merch
        mma_gemm<<<grid(N_MERCH), 256, SMEM_BYTES, st>>>(N_MERCH,
            aggm, NB, NB, nullptr, invm, OFF_LAYER(l, 5), 128,
            nullptr, amerch[cur], amerch[cur] + PMR, nullptr, OFF_LAYER(l, 6), 128,
            nullptr, NB, NB, 0, 0,
            wt, bl3, amerch[nxt], amerch[nxt] + PMR, 1, nullptr,
            NF, NI, NF, NI, nullptr, nullptr);
        cur = nxt;
    }

    // head: relu(h@h1_W+b1) @ h2_W (+ b2 via init_out), atomicAdd across halves
    mma_gemm<<<grid(N_TX), 256, SMEM_BYTES, st>>>(N_TX,
        nullptr, atx[cur], atx[cur] + PTX, nullptr, nullptr, OFF_H1, 128,
        nullptr, NB, NB, nullptr, 0, 0,
        nullptr, NB, NB, 0, 0,
        wt, h1_b, nullptr, nullptr, 0, nullptr,
        NF, NI, NF, NI, h2_W, out);
}

// round 10
// speedup vs baseline: 1.1327x; 1.1327x over previous
#include <cuda_runtime.h>
#include <cuda_bf16.h>
#include <cstdint>
#include <cstddef>

// ---------------------------------------------------------------------------
// HeteroSAGE on GB300 — Round 10: R8 GEMM shape + scatter fused into epilogue
//  * 128x128 tile, 2 CTAs/SM, 3-stage cp.async pipeline (proven R8 core)
//  * tx-producing GEMMs scatter post-relu fp32 rows into agg via red.v2
//    (deletes both scatter kernels and their 204MB of re-reads)
//  * double-buffered agg arrays decouple layer l writes from layer l-1 reads
// ---------------------------------------------------------------------------

namespace {
constexpr int H_      = 128;
constexpr int N_TX    = 200000;
constexpr int N_CARD  = 50000;
constexpr int N_MERCH = 10000;
constexpr int PLANE_B = 128 * 64;            // 8192 B (128 rows x 64B swizzled)
constexpr int STAGE_B = 4 * PLANE_B;         // 32768 (AH, AL, BH, BL)
constexpr int NSTAGE  = 3;
constexpr int SMEM_BYTES = NSTAGE * STAGE_B + 512;

constexpr int SZ128 = 2 * 128 * 128;
constexpr int SZ64  = 2 * 128 * 64;
constexpr int OFF_TXW   = 0;
constexpr int OFF_CPROJ = OFF_TXW + SZ128;
constexpr int OFF_MPROJ = OFF_CPROJ + SZ64;
constexpr int OFF_H1    = OFF_MPROJ + SZ64;
constexpr int OFF_L0    = OFF_H1 + SZ128;
constexpr int WT_TOTAL  = OFF_L0 + 14 * SZ128;
__host__ __device__ constexpr int OFF_LAYER(int l, int j) { return OFF_L0 + (l * 7 + j) * SZ128; }
}

// ---------------- scratch ----------------------------------------------------
__device__ __align__(16) __nv_bfloat16 g_atx0[2 * (size_t)N_TX * H_];
__device__ __align__(16) __nv_bfloat16 g_atx1[2 * (size_t)N_TX * H_];
__device__ __align__(16) __nv_bfloat16 g_acard0[2 * (size_t)N_CARD * H_];
__device__ __align__(16) __nv_bfloat16 g_acard1[2 * (size_t)N_CARD * H_];
__device__ __align__(16) __nv_bfloat16 g_amerch0[2 * (size_t)N_MERCH * H_];
__device__ __align__(16) __nv_bfloat16 g_amerch1[2 * (size_t)N_MERCH * H_];
__device__ __align__(16) float g_pcard[(size_t)N_CARD * H_];
__device__ __align__(16) float g_pmerch[(size_t)N_MERCH * H_];
__device__ float g_aggc0[(size_t)N_CARD * H_];
__device__ float g_aggc1[(size_t)N_CARD * H_];
__device__ float g_aggm0[(size_t)N_MERCH * H_];
__device__ float g_aggm1[(size_t)N_MERCH * H_];
__device__ float g_invc[N_CARD];
__device__ float g_invm[N_MERCH];
__device__ float g_bcomb[2 * H_];
__device__ float g_zbias[H_];
__device__ __align__(16) __nv_bfloat16 g_wt[WT_TOTAL];

// ---------------- PTX helpers ------------------------------------------------
__device__ __forceinline__ uint32_t smem_u32(const void* p) {
    uint32_t a;
    asm("{ .reg .u64 t; cvta.to.shared.u64 t, %1; cvt.u32.u64 %0, t; }" : "=r"(a) : "l"(p));
    return a;
}
__device__ __forceinline__ void ldsm_x4(uint32_t* r, uint32_t addr) {
    asm volatile("ldmatrix.sync.aligned.m8n8.x4.shared.b16 {%0,%1,%2,%3}, [%4];"
                 : "=r"(r[0]), "=r"(r[1]), "=r"(r[2]), "=r"(r[3]) : "r"(addr));
}
__device__ __forceinline__ void mma_bf16(float* c, const uint32_t* a, const uint32_t* b) {
    asm volatile(
        "mma.sync.aligned.m16n8k16.row.col.f32.bf16.bf16.f32 "
        "{%0,%1,%2,%3}, {%4,%5,%6,%7}, {%8,%9}, {%0,%1,%2,%3};"
        : "+f"(c[0]), "+f"(c[1]), "+f"(c[2]), "+f"(c[3])
        : "r"(a[0]), "r"(a[1]), "r"(a[2]), "r"(a[3]), "r"(b[0]), "r"(b[1]));
}
__device__ __forceinline__ void cp16(uint32_t dst, const void* src) {
    asm volatile("cp.async.cg.shared.global [%0], [%1], 16;" :: "r"(dst), "l"(src) : "memory");
}
#define CP_COMMIT()  asm volatile("cp.async.commit_group;" ::: "memory")
#define CP_WAIT1()   asm volatile("cp.async.wait_group 1;" ::: "memory")

__device__ __forceinline__ uint32_t swz(int r, int c) {
    return (uint32_t)r * 64u + (uint32_t)(((c ^ (r >> 1)) & 3) * 16);
}
__device__ __forceinline__ void red2(float* p, float a, float b) {
    asm volatile("red.global.add.v2.f32 [%0], {%1,%2};" :: "l"(p), "f"(a), "f"(b) : "memory");
}

// ---------------- small kernels ----------------------------------------------
__global__ void count_kernel(const int* __restrict__ ec, const int* __restrict__ em,
                             float* __restrict__ cc, float* __restrict__ cm, int E) {
    int i = blockIdx.x * blockDim.x + threadIdx.x;
    if (i < E) {
        atomicAdd(&cc[ec[i]], 1.0f);
        atomicAdd(&cm[em[i]], 1.0f);
    }
}

__global__ void invert_kernel(float* __restrict__ c, int n) {
    int i = blockIdx.x * blockDim.x + threadIdx.x;
    if (i < n) c[i] = 1.0f / fmaxf(c[i], 1.0f);
}

__global__ void combine_bias(const float* __restrict__ bl, float* __restrict__ bc) {
    int i = blockIdx.x * blockDim.x + threadIdx.x;
    if (i < 2 * H_) {
        int l = i >> 7, j = i & 127;
        bc[i] = bl[(l * 4 + 0) * H_ + j] + bl[(l * 4 + 2) * H_ + j];
    }
}

struct PrepEnt { const float* s1; const float* s2; int K; int off; };
struct PrepArgs { PrepEnt e[18]; };

__global__ void prep_weights(PrepArgs pa, __nv_bfloat16* __restrict__ wt) {
    PrepEnt en = pa.e[blockIdx.x];
    int total = 128 * en.K;
    for (int i = threadIdx.x; i < total; i += blockDim.x) {
        int n = i / en.K, k = i - n * en.K;
        float v = en.s1[(size_t)k * H_ + n];
        if (en.s2) v += en.s2[(size_t)k * H_ + n];
        __nv_bfloat16 h = __float2bfloat16(v);
        float r = v - __bfloat162float(h);
        wt[en.off + (size_t)n * en.K + k] = h;
        wt[en.off + (size_t)128 * en.K + (size_t)n * en.K + k] = __float2bfloat16(r);
    }
}

// ---------------------------------------------------------------------------
// 128x128 tile, 256 threads, KC=32 chunks, 3-stage cp.async pipeline.
// Outputs: presplit bf16 (Ch/Cl), fp32 (Cf), or head mode (hout).
// Optional epilogue gather-add: + GA0[GAI0[r]] + GA1[GAI1[r]].
// Optional epilogue scatter-add: red.v2 of post-relu rows into
//   SCc[SEc[r]*128+col] and SCm[SEm[r]*128+col].
// ---------------------------------------------------------------------------
__global__ __launch_bounds__(256, 2) void mma_gemm(
    int M,
    const float* __restrict__ A0f, const __nv_bfloat16* __restrict__ A0h,
    const __nv_bfloat16* __restrict__ A0l,
    const int* __restrict__ I0, const float* __restrict__ S0, int w0, int K0,
    const float* __restrict__ A1f, const __nv_bfloat16* __restrict__ A1h,
    const __nv_bfloat16* __restrict__ A1l,
    const int* __restrict__ I1, int w1, int K1,
    const float* __restrict__ A2f, const __nv_bfloat16* __restrict__ A2h,
    const __nv_bfloat16* __restrict__ A2l, int w2, int K2,
    const __nv_bfloat16* __restrict__ wt,
    const float* __restrict__ bias,
    __nv_bfloat16* __restrict__ Ch, __nv_bfloat16* __restrict__ Cl, int doRelu,
    float* __restrict__ Cf,
    const float* __restrict__ GA0, const int* __restrict__ GAI0,
    const float* __restrict__ GA1, const int* __restrict__ GAI1,
    const int* __restrict__ SEc, const int* __restrict__ SEm,
    float* __restrict__ SCc, float* __restrict__ SCm,
    const float* __restrict__ hw2, const float* __restrict__ hb2,
    float* __restrict__ hout) {
    extern __shared__ __align__(16) char smem_raw[];
    const uint32_t sb = smem_u32(smem_raw);
    float* partial = (float*)(smem_raw + NSTAGE * STAGE_B);

    const int tid = threadIdx.x, warp = tid >> 5, lane = tid & 31;
    const int rowG = warp >> 2, colG = warp & 3;
    const int row0 = blockIdx.x * 128;
    const bool headMode = (hout != nullptr);
    if (headMode && tid < 128) partial[tid] = 0.0f;

    const float* srcF[3] = {A0f, A1f, A2f};
    const __nv_bfloat16* srcH[3] = {A0h, A1h, A2h};
    const __nv_bfloat16* srcL[3] = {A0l, A1l, A2l};
    const int Ks[3] = {K0, K1, K2};
    const int wof[3] = {w0, w1, w2};
    const int nch0 = K0 >> 5, nch1 = K1 >> 5, nch2 = K2 >> 5;
    const int ntot = nch0 + nch1 + nch2;

    const int lrow = tid >> 1, lsel = tid & 1;
    int gi[3];
    float sc_[3];
    {
        int r = row0 + lrow;
        if (r >= M) r = M - 1;
        int g0 = r, g1 = r;
        if (I0) g0 = __ldg(&I0[r]);
        if (I1) g1 = __ldg(&I1[r]);
        gi[0] = g0; gi[1] = g1; gi[2] = r;
        sc_[0] = S0 ? __ldg(&S0[g0]) : 1.0f;
        sc_[1] = 1.0f; sc_[2] = 1.0f;
    }

    float acc[4][4][4];
#pragma unroll
    for (int mt = 0; mt < 4; mt++)
#pragma unroll
        for (int nt = 0; nt < 4; nt++)
#pragma unroll
            for (int j = 0; j < 4; j++) acc[mt][nt][j] = 0.0f;

    auto issue = [&](int c, int stage) {
        int s, kb;
        if (c < nch0) { s = 0; kb = c << 5; }
        else if (c < nch0 + nch1) { s = 1; kb = (c - nch0) << 5; }
        else { s = 2; kb = (c - nch0 - nch1) << 5; }
        const uint32_t base = sb + stage * STAGE_B;
        {
            const __nv_bfloat16* bsrc = wt + wof[s] +
                (lsel ? (size_t)128 * Ks[s] : 0) + (size_t)lrow * Ks[s] + kb;
            const uint32_t bpl = base + (lsel ? 3 : 2) * PLANE_B;
#pragma unroll
            for (int j = 0; j < 4; j++) cp16(bpl + swz(lrow, j), bsrc + j * 8);
        }
        if (srcF[s] == nullptr) {
            const __nv_bfloat16* asrc =
                (lsel ? srcL[s] : srcH[s]) + (size_t)gi[s] * 128 + kb;
            const uint32_t apl = base + (lsel ? PLANE_B : 0);
#pragma unroll
            for (int j = 0; j < 4; j++) cp16(apl + swz(lrow, j), asrc + j * 8);
        } else {
            const float sc = sc_[s];
            const float* ap = srcF[s] + (size_t)gi[s] * Ks[s] + kb + lsel * 16;
            float4 x = *(const float4*)(ap);
            float4 y = *(const float4*)(ap + 4);
            float4 z = *(const float4*)(ap + 8);
            float4 u = *(const float4*)(ap + 12);
            float v[16] = {x.x, x.y, x.z, x.w, y.x, y.y, y.z, y.w,
                           z.x, z.y, z.z, z.w, u.x, u.y, u.z, u.w};
            uint32_t hw_[8], lw_[8];
#pragma unroll
            for (int j = 0; j < 8; j++) {
                float a0 = v[2 * j] * sc, a1 = v[2 * j + 1] * sc;
                __nv_bfloat16 h0 = __float2bfloat16(a0);
                __nv_bfloat16 h1 = __float2bfloat16(a1);
                __nv_bfloat162 hp; hp.x = h0; hp.y = h1;
                __nv_bfloat162 lp;
                lp.x = __float2bfloat16(a0 - __bfloat162float(h0));
                lp.y = __float2bfloat16(a1 - __bfloat162float(h1));
                hw_[j] = *reinterpret_cast<uint32_t*>(&hp);
                lw_[j] = *reinterpret_cast<uint32_t*>(&lp);
            }
            const uint32_t aH0 = base + swz(lrow, lsel * 2);
            const uint32_t aH1 = base + swz(lrow, lsel * 2 + 1);
            asm volatile("st.shared.v4.b32 [%0], {%1,%2,%3,%4};"
                         :: "r"(aH0), "r"(hw_[0]), "r"(hw_[1]), "r"(hw_[2]), "r"(hw_[3]) : "memory");
            asm volatile("st.shared.v4.b32 [%0], {%1,%2,%3,%4};"
                         :: "r"(aH1), "r"(hw_[4]), "r"(hw_[5]), "r"(hw_[6]), "r"(hw_[7]) : "memory");
            asm volatile("st.shared.v4.b32 [%0], {%1,%2,%3,%4};"
                         :: "r"(aH0 + PLANE_B), "r"(lw_[0]), "r"(lw_[1]), "r"(lw_[2]), "r"(lw_[3]) : "memory");
            asm volatile("st.shared.v4.b32 [%0], {%1,%2,%3,%4};"
                         :: "r"(aH1 + PLANE_B), "r"(lw_[4]), "r"(lw_[5]), "r"(lw_[6]), "r"(lw_[7]) : "memory");
        }
    };

    const int laneR = lane & 15;
    const int xorA = (laneR >> 1) & 3;
    const int cA0  = lane >> 4;
    const int n_off = (((lane >> 4) & 1) * 8) + (lane & 7);
    const int xorB = (n_off >> 1) & 3;
    const int cB0  = (lane >> 3) & 1;

    auto compute = [&](int stage) {
        const uint32_t base = sb + stage * STAGE_B;
        const uint32_t aRow = base + (uint32_t)(rowG * 64 + laneR) * 64;
        const uint32_t bRow = base + 2 * PLANE_B + (uint32_t)(colG * 32 + n_off) * 64;
#pragma unroll
        for (int ks = 0; ks < 2; ks++) {
            const uint32_t aC = (uint32_t)((cA0 + 2 * ks) ^ xorA) * 16;
            const uint32_t bC = (uint32_t)((cB0 + 2 * ks) ^ xorB) * 16;
            uint32_t bh[4][2], bl[4][2];
#pragma unroll
            for (int np = 0; np < 2; np++) {
                uint32_t r4[4];
                ldsm_x4(r4, bRow + np * (16 * 64) + bC);
                bh[np * 2][0] = r4[0]; bh[np * 2][1] = r4[1];
                bh[np * 2 + 1][0] = r4[2]; bh[np * 2 + 1][1] = r4[3];
                ldsm_x4(r4, bRow + PLANE_B + np * (16 * 64) + bC);
                bl[np * 2][0] = r4[0]; bl[np * 2][1] = r4[1];
                bl[np * 2 + 1][0] = r4[2]; bl[np * 2 + 1][1] = r4[3];
            }
#pragma unroll
            for (int mt = 0; mt < 4; mt++) {
                uint32_t ah[4], al[4];
                ldsm_x4(ah, aRow + mt * (16 * 64) + aC);
                ldsm_x4(al, aRow + PLANE_B + mt * (16 * 64) + aC);
#pragma unroll
                for (int nt = 0; nt < 4; nt++) {
                    mma_bf16(acc[mt][nt], ah, bh[nt]);
                    mma_bf16(acc[mt][nt], ah, bl[nt]);
                    mma_bf16(acc[mt][nt], al, bh[nt]);
                }
            }
        }
    };

    issue(0, 0);
    CP_COMMIT();
    if (ntot > 1) issue(1, 1);
    CP_COMMIT();
    int st_ = 0;
#pragma unroll 1
    for (int c = 0; c < ntot; c++) {
        CP_WAIT1();
        __syncthreads();
        if (c + 2 < ntot) {
            int s2 = st_ + 2; if (s2 >= NSTAGE) s2 -= NSTAGE;
            issue(c + 2, s2);
        }
        CP_COMMIT();
        compute(st_);
        if (++st_ == NSTAGE) st_ = 0;
    }

    const int rIn = lane >> 2;
    const int cIn = (lane & 3) * 2;
    if (!headMode) {
#pragma unroll
        for (int mt = 0; mt < 4; mt++) {
            const int r0 = row0 + rowG * 64 + mt * 16 + rIn;
            const int r1 = r0 + 8;
            const bool v0r = r0 < M, v1r = r1 < M;
            const float *g00 = nullptr, *g01 = nullptr, *g10 = nullptr, *g11 = nullptr;
            if (GA0) {
                if (v0r) g00 = GA0 + (size_t)__ldg(&GAI0[r0]) * H_;
                if (v1r) g01 = GA0 + (size_t)__ldg(&GAI0[r1]) * H_;
            }
            if (GA1) {
                if (v0r) g10 = GA1 + (size_t)__ldg(&GAI1[r0]) * H_;
                if (v1r) g11 = GA1 + (size_t)__ldg(&GAI1[r1]) * H_;
            }
            // scatter destinations (fused aggregation)
            float *sc0 = nullptr, *sc1 = nullptr, *sm0 = nullptr, *sm1 = nullptr;
            if (SCc) {
                if (v0r) {
                    sc0 = SCc + (size_t)__ldg(&SEc[r0]) * H_;
                    sm0 = SCm + (size_t)__ldg(&SEm[r0]) * H_;
                }
                if (v1r) {
                    sc1 = SCc + (size_t)__ldg(&SEc[r1]) * H_;
                    sm1 = SCm + (size_t)__ldg(&SEm[r1]) * H_;
                }
            }
#pragma unroll
            for (int nt = 0; nt < 4; nt++) {
                const int col = colG * 32 + nt * 8 + cIn;
                const float b0 = __ldg(&bias[col]), b1 = __ldg(&bias[col + 1]);
                float o00 = acc[mt][nt][0] + b0, o01 = acc[mt][nt][1] + b1;
                float o10 = acc[mt][nt][2] + b0, o11 = acc[mt][nt][3] + b1;
                if (g00) { float2 g = *(const float2*)(g00 + col); o00 += g.x; o01 += g.y; }
                if (g10) { float2 g = *(const float2*)(g10 + col); o00 += g.x; o01 += g.y; }
                if (g01) { float2 g = *(const float2*)(g01 + col); o10 += g.x; o11 += g.y; }
                if (g11) { float2 g = *(const float2*)(g11 + col); o10 += g.x; o11 += g.y; }
                if (doRelu) {
                    o00 = fmaxf(o00, 0.f); o01 = fmaxf(o01, 0.f);
                    o10 = fmaxf(o10, 0.f); o11 = fmaxf(o11, 0.f);
                }
                if (sc0) { red2(sc0 + col, o00, o01); red2(sm0 + col, o00, o01); }
                if (sc1) { red2(sc1 + col, o10, o11); red2(sm1 + col, o10, o11); }
                if (Cf) {
                    if (v0r) *(float2*)(Cf + (size_t)r0 * H_ + col) = make_float2(o00, o01);
                    if (v1r) *(float2*)(Cf + (size_t)r1 * H_ + col) = make_float2(o10, o11);
                } else {
                    if (v0r) {
                        __nv_bfloat162 hp, lp;
                        hp.x = __float2bfloat16(o00); hp.y = __float2bfloat16(o01);
                        lp.x = __float2bfloat16(o00 - __bfloat162float(hp.x));
                        lp.y = __float2bfloat16(o01 - __bfloat162float(hp.y));
                        *(__nv_bfloat162*)(Ch + (size_t)r0 * H_ + col) = hp;
                        *(__nv_bfloat162*)(Cl + (size_t)r0 * H_ + col) = lp;
                    }
                    if (v1r) {
                        __nv_bfloat162 hp, lp;
                        hp.x = __float2bfloat16(o10); hp.y = __float2bfloat16(o11);
                        lp.x = __float2bfloat16(o10 - __bfloat162float(hp.x));
                        lp.y = __float2bfloat16(o11 - __bfloat162float(hp.y));
                        *(__nv_bfloat162*)(Ch + (size_t)r1 * H_ + col) = hp;
                        *(__nv_bfloat162*)(Cl + (size_t)r1 * H_ + col) = lp;
                    }
                }
            }
        }
    } else {
        float h0[4], h1[4];
#pragma unroll
        for (int mt = 0; mt < 4; mt++) { h0[mt] = 0.f; h1[mt] = 0.f; }
#pragma unroll
        for (int mt = 0; mt < 4; mt++)
#pragma unroll
            for (int nt = 0; nt < 4; nt++) {
                const int col = colG * 32 + nt * 8 + cIn;
                const float b0 = __ldg(&bias[col]), b1 = __ldg(&bias[col + 1]);
                const float w20 = __ldg(&hw2[col]), w21 = __ldg(&hw2[col + 1]);
                h0[mt] = fmaf(fmaxf(acc[mt][nt][0] + b0, 0.f), w20, h0[mt]);
                h0[mt] = fmaf(fmaxf(acc[mt][nt][1] + b1, 0.f), w21, h0[mt]);
                h1[mt] = fmaf(fmaxf(acc[mt][nt][2] + b0, 0.f), w20, h1[mt]);
                h1[mt] = fmaf(fmaxf(acc[mt][nt][3] + b1, 0.f), w21, h1[mt]);
            }
#pragma unroll
        for (int mt = 0; mt < 4; mt++) {
            h0[mt] += __shfl_xor_sync(0xffffffffu, h0[mt], 1);
            h0[mt] += __shfl_xor_sync(0xffffffffu, h0[mt], 2);
            h1[mt] += __shfl_xor_sync(0xffffffffu, h1[mt], 1);
            h1[mt] += __shfl_xor_sync(0xffffffffu, h1[mt], 2);
        }
        if ((lane & 3) == 0) {
#pragma unroll
            for (int mt = 0; mt < 4; mt++) {
                atomicAdd(&partial[rowG * 64 + mt * 16 + rIn], h0[mt]);
                atomicAdd(&partial[rowG * 64 + mt * 16 + rIn + 8], h1[mt]);
            }
        }
        __syncthreads();
        if (tid < 128) {
            const int r = row0 + tid;
            if (r < M) hout[r] = partial[tid] + __ldg(&hb2[0]);
        }
    }
}

// ---------------------------------------------------------------------------
extern "C" void kernel_launch(void* const* d_in, const int* in_sizes, int n_in,
                              void* d_out, int out_size) {
    const float* tx_x         = (const float*)d_in[0];
    const int*   e_card       = (const int*)d_in[3];
    const int*   e_merch      = (const int*)d_in[5];
    const float* card_emb     = (const float*)d_in[7];
    const float* merch_emb    = (const float*)d_in[8];
    const float* card_proj_W  = (const float*)d_in[9];
    const float* card_proj_b  = (const float*)d_in[10];
    const float* merch_proj_W = (const float*)d_in[11];
    const float* merch_proj_b = (const float*)d_in[12];
    const float* tx_W         = (const float*)d_in[13];
    const float* tx_b         = (const float*)d_in[14];
    const float* conv_Wl      = (const float*)d_in[15];
    const float* conv_bl      = (const float*)d_in[16];
    const float* conv_Wr      = (const float*)d_in[17];
    const float* h1_W         = (const float*)d_in[18];
    const float* h1_b         = (const float*)d_in[19];
    const float* h2_W         = (const float*)d_in[20];
    const float* h2_b         = (const float*)d_in[21];
    float* out = (float*)d_out;

    __nv_bfloat16 *atx[2], *acard[2], *amerch[2], *wt;
    float *pcard, *pmerch, *invc, *invm, *bcomb, *zbias;
    float *aggc[2], *aggm[2];
    cudaGetSymbolAddress((void**)&atx[0],    g_atx0);
    cudaGetSymbolAddress((void**)&atx[1],    g_atx1);
    cudaGetSymbolAddress((void**)&acard[0],  g_acard0);
    cudaGetSymbolAddress((void**)&acard[1],  g_acard1);
    cudaGetSymbolAddress((void**)&amerch[0], g_amerch0);
    cudaGetSymbolAddress((void**)&amerch[1], g_amerch1);
    cudaGetSymbolAddress((void**)&pcard,   g_pcard);
    cudaGetSymbolAddress((void**)&pmerch,  g_pmerch);
    cudaGetSymbolAddress((void**)&aggc[0], g_aggc0);
    cudaGetSymbolAddress((void**)&aggc[1], g_aggc1);
    cudaGetSymbolAddress((void**)&aggm[0], g_aggm0);
    cudaGetSymbolAddress((void**)&aggm[1], g_aggm1);
    cudaGetSymbolAddress((void**)&invc,    g_invc);
    cudaGetSymbolAddress((void**)&invm,    g_invm);
    cudaGetSymbolAddress((void**)&bcomb,   g_bcomb);
    cudaGetSymbolAddress((void**)&zbias,   g_zbias);
    cudaGetSymbolAddress((void**)&wt,      g_wt);

    const size_t PTX = (size_t)N_TX * H_;
    const size_t PCD = (size_t)N_CARD * H_;
    const size_t PMR = (size_t)N_MERCH * H_;

    cudaFuncSetAttribute(mma_gemm, cudaFuncAttributeMaxDynamicSharedMemorySize, SMEM_BYTES);

    cudaStream_t st = 0;
    const int E = in_sizes[3];

    PrepArgs pa;
    {
        int i = 0;
        auto ent = [&](const float* s1, const float* s2, int K, int off) {
            pa.e[i].s1 = s1; pa.e[i].s2 = s2; pa.e[i].K = K; pa.e[i].off = off; i++;
        };
        const size_t WSZ = (size_t)H_ * H_;
        ent(tx_W,         nullptr, 128, OFF_TXW);
        ent(card_proj_W,  nullptr,  64, OFF_CPROJ);
        ent(merch_proj_W, nullptr,  64, OFF_MPROJ);
        ent(h1_W,         nullptr, 128, OFF_H1);
        for (int l = 0; l < 2; l++) {
            const float* Wl0 = conv_Wl + (size_t)(l * 4 + 0) * WSZ;
            const float* Wl1 = conv_Wl + (size_t)(l * 4 + 1) * WSZ;
            const float* Wl2 = conv_Wl + (size_t)(l * 4 + 2) * WSZ;
            const float* Wl3 = conv_Wl + (size_t)(l * 4 + 3) * WSZ;
            const float* Wr0 = conv_Wr + (size_t)(l * 4 + 0) * WSZ;
            const float* Wr1 = conv_Wr + (size_t)(l * 4 + 1) * WSZ;
            const float* Wr2 = conv_Wr + (size_t)(l * 4 + 2) * WSZ;
            const float* Wr3 = conv_Wr + (size_t)(l * 4 + 3) * WSZ;
            ent(Wl0, nullptr, 128, OFF_LAYER(l, 0));
            ent(Wl2, nullptr, 128, OFF_LAYER(l, 1));
            ent(Wr0, Wr2,     128, OFF_LAYER(l, 2));
            ent(Wl1, nullptr, 128, OFF_LAYER(l, 3));
            ent(Wr1, nullptr, 128, OFF_LAYER(l, 4));
            ent(Wl3, nullptr, 128, OFF_LAYER(l, 5));
            ent(Wr3, nullptr, 128, OFF_LAYER(l, 6));
        }
    }

    auto blocks = [](int m) { return (m + 127) / 128; };
    const __nv_bfloat16* NB = nullptr;
    const float* NF = nullptr;
    const int* NI = nullptr;
    float* NFo = nullptr;

    // launches 0..4 then encoder tx GEMM at index 5 (ncu -s 5 -c 1)
    prep_weights<<<18, 256, 0, st>>>(pa, wt);                                   // 0
    cudaMemsetAsync(invc, 0, N_CARD * sizeof(float), st);                       // 1
    cudaMemsetAsync(invm, 0, N_MERCH * sizeof(float), st);                      // 2
    cudaMemsetAsync(aggc[0], 0, PCD * sizeof(float), st);                       // 3
    cudaMemsetAsync(aggm[0], 0, PMR * sizeof(float), st);                       // 4
    // encoder tx GEMM: relu(tx_x@txW+b) -> atx0 planes, fused scatter -> agg0
    mma_gemm<<<blocks(N_TX), 256, SMEM_BYTES, st>>>(N_TX,                       // 5 <- profiled
        tx_x, NB, NB, nullptr, nullptr, OFF_TXW, 128,
        nullptr, NB, NB, nullptr, 0, 0,
        nullptr, NB, NB, 0, 0,
        wt, tx_b, atx[0], atx[0] + PTX, 1, nullptr,
        NF, NI, NF, NI,
        e_card, e_merch, aggc[0], aggm[0],
        nullptr, nullptr, nullptr);
    count_kernel<<<(E + 255) / 256, 256, 0, st>>>(e_card, e_merch, invc, invm, E);
    invert_kernel<<<(N_CARD + 255) / 256, 256, 0, st>>>(invc, N_CARD);
    invert_kernel<<<(N_MERCH + 255) / 256, 256, 0, st>>>(invm, N_MERCH);
    combine_bias<<<1, 256, 0, st>>>(conv_bl, bcomb);
    cudaMemsetAsync(aggc[1], 0, PCD * sizeof(float), st);
    cudaMemsetAsync(aggm[1], 0, PMR * sizeof(float), st);
    mma_gemm<<<blocks(N_CARD), 256, SMEM_BYTES, st>>>(N_CARD,
        card_emb, NB, NB, nullptr, nullptr, OFF_CPROJ, 64,
        nullptr, NB, NB, nullptr, 0, 0,
        nullptr, NB, NB, 0, 0,
        wt, card_proj_b, acard[0], acard[0] + PCD, 0, nullptr,
        NF, NI, NF, NI, NI, NI, NFo, NFo, nullptr, nullptr, nullptr);
    mma_gemm<<<blocks(N_MERCH), 256, SMEM_BYTES, st>>>(N_MERCH,
        merch_emb, NB, NB, nullptr, nullptr, OFF_MPROJ, 64,
        nullptr, NB, NB, nullptr, 0, 0,
        nullptr, NB, NB, 0, 0,
        wt, merch_proj_b, amerch[0], amerch[0] + PMR, 0, nullptr,
        NF, NI, NF, NI, NI, NI, NFo, NFo, nullptr, nullptr, nullptr);

    int cur = 0;
    for (int l = 0; l < 2; l++) {
        int nxt = cur ^ 1;
        const float* bl1 = conv_bl + (l * 4 + 1) * H_;
        const float* bl3 = conv_bl + (l * 4 + 3) * H_;

        // P_card = h_card @ Wl0 (fp32, zero bias)
        mma_gemm<<<blocks(N_CARD), 256, SMEM_BYTES, st>>>(N_CARD,
            nullptr, acard[cur], acard[cur] + PCD, nullptr, nullptr, OFF_LAYER(l, 0), 128,
            nullptr, NB, NB, nullptr, 0, 0,
            nullptr, NB, NB, 0, 0,
            wt, zbias, nullptr, nullptr, 0, pcard,
            NF, NI, NF, NI, NI, NI, NFo, NFo, nullptr, nullptr, nullptr);
        // P_merch = h_merch @ Wl2
        mma_gemm<<<blocks(N_MERCH), 256, SMEM_BYTES, st>>>(N_MERCH,
            nullptr, amerch[cur], amerch[cur] + PMR, nullptr, nullptr, OFF_LAYER(l, 1), 128,
            nullptr, NB, NB, nullptr, 0, 0,
            nullptr, NB, NB, 0, 0,
            wt, zbias, nullptr, nullptr, 0, pmerch,
            NF, NI, NF, NI, NI, NI, NFo, NFo, nullptr, nullptr, nullptr);
        // tx: h_tx@Wcomb + gather(P_card) + gather(P_merch) + bcomb, relu
        //     layer 0 additionally scatters h_tx^1 into agg[1] for layer 1
        mma_gemm<<<blocks(N_TX), 256, SMEM_BYTES, st>>>(N_TX,
            nullptr, atx[cur], atx[cur] + PTX, nullptr, nullptr, OFF_LAYER(l, 2), 128,
            nullptr, NB, NB, nullptr, 0, 0,
            nullptr, NB, NB, 0, 0,
            wt, bcomb + l * H_, atx[nxt], atx[nxt] + PTX, 1, nullptr,
            pcard, e_card, pmerch, e_merch,
            (l == 0) ? e_card : NI, (l == 0) ? e_merch : NI,
            (l == 0) ? aggc[1] : NFo, (l == 0) ? aggm[1] : NFo,
            nullptr, nullptr, nullptr);
        // card: (agg[l]*inv)@Wl1 + h_card@Wr1 + bl1, relu
        mma_gemm<<<blocks(N_CARD), 256, SMEM_BYTES, st>>>(N_CARD,
            aggc[l], NB, NB, nullptr, invc, OFF_LAYER(l, 3), 128,
            nullptr, acard[cur], acard[cur] + PCD, nullptr, OFF_LAYER(l, 4), 128,
            nullptr, NB, NB, 0, 0,
            wt, bl1, acard[nxt], acard[nxt] + PCD, 1, nullptr,
            NF, NI, NF, NI, NI, NI, NFo, NFo, nullptr, nullptr, nullptr);
        // merch
        mma_gemm<<<blocks(N_MERCH), 256, SMEM_BYTES, st>>>(N_MERCH,
            aggm[l], NB, NB, nullptr, invm, OFF_LAYER(l, 5), 128,
            nullptr, amerch[cur], amerch[cur] + PMR, nullptr, OFF_LAYER(l, 6), 128,
            nullptr, NB, NB, 0, 0,
            wt, bl3, amerch[nxt], amerch[nxt] + PMR, 1, nullptr,
            NF, NI, NF, NI, NI, NI, NFo, NFo, nullptr, nullptr, nullptr);
        cur = nxt;
    }

    // head: relu(h@h1_W+b1) @ h2_W + b2 (fused epilogue)
    mma_gemm<<<blocks(N_TX), 256, SMEM_BYTES, st>>>(N_TX,
        nullptr, atx[cur], atx[cur] + PTX, nullptr, nullptr, OFF_H1, 128,
        nullptr, NB, NB, nullptr, 0, 0,
        nullptr, NB, NB, 0, 0,
        wt, h1_b, nullptr, nullptr, 0, nullptr,
        NF, NI, NF, NI, NI, NI, NFo, NFo, h2_W, h2_b, out);
}

// round 11
// speedup vs baseline: 1.1367x; 1.0035x over previous
#include <cuda_runtime.h>
#include <cuda_bf16.h>
#include <cstdint>
#include <cstddef>

// ---------------------------------------------------------------------------
// HeteroSAGE on GB300 — Round 11: fused scatter with red.v4 via quad shuffle
//  * 128x128 tile, 2 CTAs/SM, 3-stage cp.async pipeline (R8 core)
//  * epilogue scatter: shfl_xor(1) pairs adjacent col-pairs -> even lanes
//    issue red.global.add.v4.f32 (same op count as standalone scatter,
//    no re-read, no extra launches)
// ---------------------------------------------------------------------------

namespace {
constexpr int H_      = 128;
constexpr int N_TX    = 200000;
constexpr int N_CARD  = 50000;
constexpr int N_MERCH = 10000;
constexpr int PLANE_B = 128 * 64;
constexpr int STAGE_B = 4 * PLANE_B;
constexpr int NSTAGE  = 3;
constexpr int SMEM_BYTES = NSTAGE * STAGE_B + 512;

constexpr int SZ128 = 2 * 128 * 128;
constexpr int SZ64  = 2 * 128 * 64;
constexpr int OFF_TXW   = 0;
constexpr int OFF_CPROJ = OFF_TXW + SZ128;
constexpr int OFF_MPROJ = OFF_CPROJ + SZ64;
constexpr int OFF_H1    = OFF_MPROJ + SZ64;
constexpr int OFF_L0    = OFF_H1 + SZ128;
constexpr int WT_TOTAL  = OFF_L0 + 14 * SZ128;
__host__ __device__ constexpr int OFF_LAYER(int l, int j) { return OFF_L0 + (l * 7 + j) * SZ128; }
}

// ---------------- scratch ----------------------------------------------------
__device__ __align__(16) __nv_bfloat16 g_atx0[2 * (size_t)N_TX * H_];
__device__ __align__(16) __nv_bfloat16 g_atx1[2 * (size_t)N_TX * H_];
__device__ __align__(16) __nv_bfloat16 g_acard0[2 * (size_t)N_CARD * H_];
__device__ __align__(16) __nv_bfloat16 g_acard1[2 * (size_t)N_CARD * H_];
__device__ __align__(16) __nv_bfloat16 g_amerch0[2 * (size_t)N_MERCH * H_];
__device__ __align__(16) __nv_bfloat16 g_amerch1[2 * (size_t)N_MERCH * H_];
__device__ __align__(16) float g_pcard[(size_t)N_CARD * H_];
__device__ __align__(16) float g_pmerch[(size_t)N_MERCH * H_];
__device__ float g_aggc0[(size_t)N_CARD * H_];
__device__ float g_aggc1[(size_t)N_CARD * H_];
__device__ float g_aggm0[(size_t)N_MERCH * H_];
__device__ float g_aggm1[(size_t)N_MERCH * H_];
__device__ float g_invc[N_CARD];
__device__ float g_invm[N_MERCH];
__device__ float g_bcomb[2 * H_];
__device__ float g_zbias[H_];
__device__ __align__(16) __nv_bfloat16 g_wt[WT_TOTAL];

// ---------------- PTX helpers ------------------------------------------------
__device__ __forceinline__ uint32_t smem_u32(const void* p) {
    uint32_t a;
    asm("{ .reg .u64 t; cvta.to.shared.u64 t, %1; cvt.u32.u64 %0, t; }" : "=r"(a) : "l"(p));
    return a;
}
__device__ __forceinline__ void ldsm_x4(uint32_t* r, uint32_t addr) {
    asm volatile("ldmatrix.sync.aligned.m8n8.x4.shared.b16 {%0,%1,%2,%3}, [%4];"
                 : "=r"(r[0]), "=r"(r[1]), "=r"(r[2]), "=r"(r[3]) : "r"(addr));
}
__device__ __forceinline__ void mma_bf16(float* c, const uint32_t* a, const uint32_t* b) {
    asm volatile(
        "mma.sync.aligned.m16n8k16.row.col.f32.bf16.bf16.f32 "
        "{%0,%1,%2,%3}, {%4,%5,%6,%7}, {%8,%9}, {%0,%1,%2,%3};"
        : "+f"(c[0]), "+f"(c[1]), "+f"(c[2]), "+f"(c[3])
        : "r"(a[0]), "r"(a[1]), "r"(a[2]), "r"(a[3]), "r"(b[0]), "r"(b[1]));
}
__device__ __forceinline__ void cp16(uint32_t dst, const void* src) {
    asm volatile("cp.async.cg.shared.global [%0], [%1], 16;" :: "r"(dst), "l"(src) : "memory");
}
#define CP_COMMIT()  asm volatile("cp.async.commit_group;" ::: "memory")
#define CP_WAIT1()   asm volatile("cp.async.wait_group 1;" ::: "memory")

__device__ __forceinline__ uint32_t swz(int r, int c) {
    return (uint32_t)r * 64u + (uint32_t)(((c ^ (r >> 1)) & 3) * 16);
}
__device__ __forceinline__ void red4(float* p, float a, float b, float c, float d) {
    asm volatile("red.global.add.v4.f32 [%0], {%1,%2,%3,%4};"
                 :: "l"(p), "f"(a), "f"(b), "f"(c), "f"(d) : "memory");
}

// ---------------- small kernels ----------------------------------------------
__global__ void count_kernel(const int* __restrict__ ec, const int* __restrict__ em,
                             float* __restrict__ cc, float* __restrict__ cm, int E) {
    int i = blockIdx.x * blockDim.x + threadIdx.x;
    if (i < E) {
        atomicAdd(&cc[ec[i]], 1.0f);
        atomicAdd(&cm[em[i]], 1.0f);
    }
}

__global__ void invert_kernel(float* __restrict__ c, int n) {
    int i = blockIdx.x * blockDim.x + threadIdx.x;
    if (i < n) c[i] = 1.0f / fmaxf(c[i], 1.0f);
}

__global__ void combine_bias(const float* __restrict__ bl, float* __restrict__ bc) {
    int i = blockIdx.x * blockDim.x + threadIdx.x;
    if (i < 2 * H_) {
        int l = i >> 7, j = i & 127;
        bc[i] = bl[(l * 4 + 0) * H_ + j] + bl[(l * 4 + 2) * H_ + j];
    }
}

struct PrepEnt { const float* s1; const float* s2; int K; int off; };
struct PrepArgs { PrepEnt e[18]; };

__global__ void prep_weights(PrepArgs pa, __nv_bfloat16* __restrict__ wt) {
    PrepEnt en = pa.e[blockIdx.x];
    int total = 128 * en.K;
    for (int i = threadIdx.x; i < total; i += blockDim.x) {
        int n = i / en.K, k = i - n * en.K;
        float v = en.s1[(size_t)k * H_ + n];
        if (en.s2) v += en.s2[(size_t)k * H_ + n];
        __nv_bfloat16 h = __float2bfloat16(v);
        float r = v - __bfloat162float(h);
        wt[en.off + (size_t)n * en.K + k] = h;
        wt[en.off + (size_t)128 * en.K + (size_t)n * en.K + k] = __float2bfloat16(r);
    }
}

// ---------------------------------------------------------------------------
// 128x128 tile, 256 threads, KC=32 chunks, 3-stage cp.async pipeline.
// Outputs: presplit bf16 (Ch/Cl), fp32 (Cf), or head mode (hout).
// Optional epilogue gather-add (GA*) and scatter-add (SE*/SC*, red.v4).
// ---------------------------------------------------------------------------
__global__ __launch_bounds__(256, 2) void mma_gemm(
    int M,
    const float* __restrict__ A0f, const __nv_bfloat16* __restrict__ A0h,
    const __nv_bfloat16* __restrict__ A0l,
    const int* __restrict__ I0, const float* __restrict__ S0, int w0, int K0,
    const float* __restrict__ A1f, const __nv_bfloat16* __restrict__ A1h,
    const __nv_bfloat16* __restrict__ A1l,
    const int* __restrict__ I1, int w1, int K1,
    const float* __restrict__ A2f, const __nv_bfloat16* __restrict__ A2h,
    const __nv_bfloat16* __restrict__ A2l, int w2, int K2,
    const __nv_bfloat16* __restrict__ wt,
    const float* __restrict__ bias,
    __nv_bfloat16* __restrict__ Ch, __nv_bfloat16* __restrict__ Cl, int doRelu,
    float* __restrict__ Cf,
    const float* __restrict__ GA0, const int* __restrict__ GAI0,
    const float* __restrict__ GA1, const int* __restrict__ GAI1,
    const int* __restrict__ SEc, const int* __restrict__ SEm,
    float* __restrict__ SCc, float* __restrict__ SCm,
    const float* __restrict__ hw2, const float* __restrict__ hb2,
    float* __restrict__ hout) {
    extern __shared__ __align__(16) char smem_raw[];
    const uint32_t sb = smem_u32(smem_raw);
    float* partial = (float*)(smem_raw + NSTAGE * STAGE_B);

    const int tid = threadIdx.x, warp = tid >> 5, lane = tid & 31;
    const int rowG = warp >> 2, colG = warp & 3;
    const int row0 = blockIdx.x * 128;
    const bool headMode = (hout != nullptr);
    if (headMode && tid < 128) partial[tid] = 0.0f;

    const float* srcF[3] = {A0f, A1f, A2f};
    const __nv_bfloat16* srcH[3] = {A0h, A1h, A2h};
    const __nv_bfloat16* srcL[3] = {A0l, A1l, A2l};
    const int Ks[3] = {K0, K1, K2};
    const int wof[3] = {w0, w1, w2};
    const int nch0 = K0 >> 5, nch1 = K1 >> 5, nch2 = K2 >> 5;
    const int ntot = nch0 + nch1 + nch2;

    const int lrow = tid >> 1, lsel = tid & 1;
    int gi[3];
    float sc_[3];
    {
        int r = row0 + lrow;
        if (r >= M) r = M - 1;
        int g0 = r, g1 = r;
        if (I0) g0 = __ldg(&I0[r]);
        if (I1) g1 = __ldg(&I1[r]);
        gi[0] = g0; gi[1] = g1; gi[2] = r;
        sc_[0] = S0 ? __ldg(&S0[g0]) : 1.0f;
        sc_[1] = 1.0f; sc_[2] = 1.0f;
    }

    float acc[4][4][4];
#pragma unroll
    for (int mt = 0; mt < 4; mt++)
#pragma unroll
        for (int nt = 0; nt < 4; nt++)
#pragma unroll
            for (int j = 0; j < 4; j++) acc[mt][nt][j] = 0.0f;

    auto issue = [&](int c, int stage) {
        int s, kb;
        if (c < nch0) { s = 0; kb = c << 5; }
        else if (c < nch0 + nch1) { s = 1; kb = (c - nch0) << 5; }
        else { s = 2; kb = (c - nch0 - nch1) << 5; }
        const uint32_t base = sb + stage * STAGE_B;
        {
            const __nv_bfloat16* bsrc = wt + wof[s] +
                (lsel ? (size_t)128 * Ks[s] : 0) + (size_t)lrow * Ks[s] + kb;
            const uint32_t bpl = base + (lsel ? 3 : 2) * PLANE_B;
#pragma unroll
            for (int j = 0; j < 4; j++) cp16(bpl + swz(lrow, j), bsrc + j * 8);
        }
        if (srcF[s] == nullptr) {
            const __nv_bfloat16* asrc =
                (lsel ? srcL[s] : srcH[s]) + (size_t)gi[s] * 128 + kb;
            const uint32_t apl = base + (lsel ? PLANE_B : 0);
#pragma unroll
            for (int j = 0; j < 4; j++) cp16(apl + swz(lrow, j), asrc + j * 8);
        } else {
            const float sc = sc_[s];
            const float* ap = srcF[s] + (size_t)gi[s] * Ks[s] + kb + lsel * 16;
            float4 x = *(const float4*)(ap);
            float4 y = *(const float4*)(ap + 4);
            float4 z = *(const float4*)(ap + 8);
            float4 u = *(const float4*)(ap + 12);
            float v[16] = {x.x, x.y, x.z, x.w, y.x, y.y, y.z, y.w,
                           z.x, z.y, z.z, z.w, u.x, u.y, u.z, u.w};
            uint32_t hw_[8], lw_[8];
#pragma unroll
            for (int j = 0; j < 8; j++) {
                float a0 = v[2 * j] * sc, a1 = v[2 * j + 1] * sc;
                __nv_bfloat16 h0 = __float2bfloat16(a0);
                __nv_bfloat16 h1 = __float2bfloat16(a1);
                __nv_bfloat162 hp; hp.x = h0; hp.y = h1;
                __nv_bfloat162 lp;
                lp.x = __float2bfloat16(a0 - __bfloat162float(h0));
                lp.y = __float2bfloat16(a1 - __bfloat162float(h1));
                hw_[j] = *reinterpret_cast<uint32_t*>(&hp);
                lw_[j] = *reinterpret_cast<uint32_t*>(&lp);
            }
            const uint32_t aH0 = base + swz(lrow, lsel * 2);
            const uint32_t aH1 = base + swz(lrow, lsel * 2 + 1);
            asm volatile("st.shared.v4.b32 [%0], {%1,%2,%3,%4};"
                         :: "r"(aH0), "r"(hw_[0]), "r"(hw_[1]), "r"(hw_[2]), "r"(hw_[3]) : "memory");
            asm volatile("st.shared.v4.b32 [%0], {%1,%2,%3,%4};"
                         :: "r"(aH1), "r"(hw_[4]), "r"(hw_[5]), "r"(hw_[6]), "r"(hw_[7]) : "memory");
            asm volatile("st.shared.v4.b32 [%0], {%1,%2,%3,%4};"
                         :: "r"(aH0 + PLANE_B), "r"(lw_[0]), "r"(lw_[1]), "r"(lw_[2]), "r"(lw_[3]) : "memory");
            asm volatile("st.shared.v4.b32 [%0], {%1,%2,%3,%4};"
                         :: "r"(aH1 + PLANE_B), "r"(lw_[4]), "r"(lw_[5]), "r"(lw_[6]), "r"(lw_[7]) : "memory");
        }
    };

    const int laneR = lane & 15;
    const int xorA = (laneR >> 1) & 3;
    const int cA0  = lane >> 4;
    const int n_off = (((lane >> 4) & 1) * 8) + (lane & 7);
    const int xorB = (n_off >> 1) & 3;
    const int cB0  = (lane >> 3) & 1;

    auto compute = [&](int stage) {
        const uint32_t base = sb + stage * STAGE_B;
        const uint32_t aRow = base + (uint32_t)(rowG * 64 + laneR) * 64;
        const uint32_t bRow = base + 2 * PLANE_B + (uint32_t)(colG * 32 + n_off) * 64;
#pragma unroll
        for (int ks = 0; ks < 2; ks++) {
            const uint32_t aC = (uint32_t)((cA0 + 2 * ks) ^ xorA) * 16;
            const uint32_t bC = (uint32_t)((cB0 + 2 * ks) ^ xorB) * 16;
            uint32_t bh[4][2], bl[4][2];
#pragma unroll
            for (int np = 0; np < 2; np++) {
                uint32_t r4[4];
                ldsm_x4(r4, bRow + np * (16 * 64) + bC);
                bh[np * 2][0] = r4[0]; bh[np * 2][1] = r4[1];
                bh[np * 2 + 1][0] = r4[2]; bh[np * 2 + 1][1] = r4[3];
                ldsm_x4(r4, bRow + PLANE_B + np * (16 * 64) + bC);
                bl[np * 2][0] = r4[0]; bl[np * 2][1] = r4[1];
                bl[np * 2 + 1][0] = r4[2]; bl[np * 2 + 1][1] = r4[3];
            }
#pragma unroll
            for (int mt = 0; mt < 4; mt++) {
                uint32_t ah[4], al[4];
                ldsm_x4(ah, aRow + mt * (16 * 64) + aC);
                ldsm_x4(al, aRow + PLANE_B + mt * (16 * 64) + aC);
#pragma unroll
                for (int nt = 0; nt < 4; nt++) {
                    mma_bf16(acc[mt][nt], ah, bh[nt]);
                    mma_bf16(acc[mt][nt], ah, bl[nt]);
                    mma_bf16(acc[mt][nt], al, bh[nt]);
                }
            }
        }
    };

    issue(0, 0);
    CP_COMMIT();
    if (ntot > 1) issue(1, 1);
    CP_COMMIT();
    int st_ = 0;
#pragma unroll 1
    for (int c = 0; c < ntot; c++) {
        CP_WAIT1();
        __syncthreads();
        if (c + 2 < ntot) {
            int s2 = st_ + 2; if (s2 >= NSTAGE) s2 -= NSTAGE;
            issue(c + 2, s2);
        }
        CP_COMMIT();
        compute(st_);
        if (++st_ == NSTAGE) st_ = 0;
    }

    const int rIn = lane >> 2;
    const int cIn = (lane & 3) * 2;
    if (!headMode) {
#pragma unroll
        for (int mt = 0; mt < 4; mt++) {
            const int r0 = row0 + rowG * 64 + mt * 16 + rIn;
            const int r1 = r0 + 8;
            const bool v0r = r0 < M, v1r = r1 < M;
            const float *g00 = nullptr, *g01 = nullptr, *g10 = nullptr, *g11 = nullptr;
            if (GA0) {
                if (v0r) g00 = GA0 + (size_t)__ldg(&GAI0[r0]) * H_;
                if (v1r) g01 = GA0 + (size_t)__ldg(&GAI0[r1]) * H_;
            }
            if (GA1) {
                if (v0r) g10 = GA1 + (size_t)__ldg(&GAI1[r0]) * H_;
                if (v1r) g11 = GA1 + (size_t)__ldg(&GAI1[r1]) * H_;
            }
            float *sc0 = nullptr, *sc1 = nullptr, *sm0 = nullptr, *sm1 = nullptr;
            if (SCc) {
                if (v0r) {
                    sc0 = SCc + (size_t)__ldg(&SEc[r0]) * H_;
                    sm0 = SCm + (size_t)__ldg(&SEm[r0]) * H_;
                }
                if (v1r) {
                    sc1 = SCc + (size_t)__ldg(&SEc[r1]) * H_;
                    sm1 = SCm + (size_t)__ldg(&SEm[r1]) * H_;
                }
            }
#pragma unroll
            for (int nt = 0; nt < 4; nt++) {
                const int col = colG * 32 + nt * 8 + cIn;
                const float b0 = __ldg(&bias[col]), b1 = __ldg(&bias[col + 1]);
                float o00 = acc[mt][nt][0] + b0, o01 = acc[mt][nt][1] + b1;
                float o10 = acc[mt][nt][2] + b0, o11 = acc[mt][nt][3] + b1;
                if (g00) { float2 g = *(const float2*)(g00 + col); o00 += g.x; o01 += g.y; }
                if (g10) { float2 g = *(const float2*)(g10 + col); o00 += g.x; o01 += g.y; }
                if (g01) { float2 g = *(const float2*)(g01 + col); o10 += g.x; o11 += g.y; }
                if (g11) { float2 g = *(const float2*)(g11 + col); o10 += g.x; o11 += g.y; }
                if (doRelu) {
                    o00 = fmaxf(o00, 0.f); o01 = fmaxf(o01, 0.f);
                    o10 = fmaxf(o10, 0.f); o11 = fmaxf(o11, 0.f);
                }
                if (SCc) {
                    // pair adjacent lanes' col-pairs -> even lanes issue red.v4
                    float x2 = __shfl_xor_sync(0xffffffffu, o00, 1);
                    float x3 = __shfl_xor_sync(0xffffffffu, o01, 1);
                    float y2 = __shfl_xor_sync(0xffffffffu, o10, 1);
                    float y3 = __shfl_xor_sync(0xffffffffu, o11, 1);
                    if ((lane & 1) == 0) {
                        if (sc0) { red4(sc0 + col, o00, o01, x2, x3);
                                   red4(sm0 + col, o00, o01, x2, x3); }
                        if (sc1) { red4(sc1 + col, o10, o11, y2, y3);
                                   red4(sm1 + col, o10, o11, y2, y3); }
                    }
                }
                if (Cf) {
                    if (v0r) *(float2*)(Cf + (size_t)r0 * H_ + col) = make_float2(o00, o01);
                    if (v1r) *(float2*)(Cf + (size_t)r1 * H_ + col) = make_float2(o10, o11);
                } else {
                    if (v0r) {
                        __nv_bfloat162 hp, lp;
                        hp.x = __float2bfloat16(o00); hp.y = __float2bfloat16(o01);
                        lp.x = __float2bfloat16(o00 - __bfloat162float(hp.x));
                        lp.y = __float2bfloat16(o01 - __bfloat162float(hp.y));
                        *(__nv_bfloat162*)(Ch + (size_t)r0 * H_ + col) = hp;
                        *(__nv_bfloat162*)(Cl + (size_t)r0 * H_ + col) = lp;
                    }
                    if (v1r) {
                        __nv_bfloat162 hp, lp;
                        hp.x = __float2bfloat16(o10); hp.y = __float2bfloat16(o11);
                        lp.x = __float2bfloat16(o10 - __bfloat162float(hp.x));
                        lp.y = __float2bfloat16(o11 - __bfloat162float(hp.y));
                        *(__nv_bfloat162*)(Ch + (size_t)r1 * H_ + col) = hp;
                        *(__nv_bfloat162*)(Cl + (size_t)r1 * H_ + col) = lp;
                    }
                }
            }
        }
    } else {
        float h0[4], h1[4];
#pragma unroll
        for (int mt = 0; mt < 4; mt++) { h0[mt] = 0.f; h1[mt] = 0.f; }
#pragma unroll
        for (int mt = 0; mt < 4; mt++)
#pragma unroll
            for (int nt = 0; nt < 4; nt++) {
                const int col = colG * 32 + nt * 8 + cIn;
                const float b0 = __ldg(&bias[col]), b1 = __ldg(&bias[col + 1]);
                const float w20 = __ldg(&hw2[col]), w21 = __ldg(&hw2[col + 1]);
                h0[mt] = fmaf(fmaxf(acc[mt][nt][0] + b0, 0.f), w20, h0[mt]);
                h0[mt] = fmaf(fmaxf(acc[mt][nt][1] + b1, 0.f), w21, h0[mt]);
                h1[mt] = fmaf(fmaxf(acc[mt][nt][2] + b0, 0.f), w20, h1[mt]);
                h1[mt] = fmaf(fmaxf(acc[mt][nt][3] + b1, 0.f), w21, h1[mt]);
            }
#pragma unroll
        for (int mt = 0; mt < 4; mt++) {
            h0[mt] += __shfl_xor_sync(0xffffffffu, h0[mt], 1);
            h0[mt] += __shfl_xor_sync(0xffffffffu, h0[mt], 2);
            h1[mt] += __shfl_xor_sync(0xffffffffu, h1[mt], 1);
            h1[mt] += __shfl_xor_sync(0xffffffffu, h1[mt], 2);
        }
        if ((lane & 3) == 0) {
#pragma unroll
            for (int mt = 0; mt < 4; mt++) {
                atomicAdd(&partial[rowG * 64 + mt * 16 + rIn], h0[mt]);
                atomicAdd(&partial[rowG * 64 + mt * 16 + rIn + 8], h1[mt]);
            }
        }
        __syncthreads();
        if (tid < 128) {
            const int r = row0 + tid;
            if (r < M) hout[r] = partial[tid] + __ldg(&hb2[0]);
        }
    }
}

// ---------------------------------------------------------------------------
extern "C" void kernel_launch(void* const* d_in, const int* in_sizes, int n_in,
                              void* d_out, int out_size) {
    const float* tx_x         = (const float*)d_in[0];
    const int*   e_card       = (const int*)d_in[3];
    const int*   e_merch      = (const int*)d_in[5];
    const float* card_emb     = (const float*)d_in[7];
    const float* merch_emb    = (const float*)d_in[8];
    const float* card_proj_W  = (const float*)d_in[9];
    const float* card_proj_b  = (const float*)d_in[10];
    const float* merch_proj_W = (const float*)d_in[11];
    const float* merch_proj_b = (const float*)d_in[12];
    const float* tx_W         = (const float*)d_in[13];
    const float* tx_b         = (const float*)d_in[14];
    const float* conv_Wl      = (const float*)d_in[15];
    const float* conv_bl      = (const float*)d_in[16];
    const float* conv_Wr      = (const float*)d_in[17];
    const float* h1_W         = (const float*)d_in[18];
    const float* h1_b         = (const float*)d_in[19];
    const float* h2_W         = (const float*)d_in[20];
    const float* h2_b         = (const float*)d_in[21];
    float* out = (float*)d_out;

    __nv_bfloat16 *atx[2], *acard[2], *amerch[2], *wt;
    float *pcard, *pmerch, *invc, *invm, *bcomb, *zbias;
    float *aggc[2], *aggm[2];
    cudaGetSymbolAddress((void**)&atx[0],    g_atx0);
    cudaGetSymbolAddress((void**)&atx[1],    g_atx1);
    cudaGetSymbolAddress((void**)&acard[0],  g_acard0);
    cudaGetSymbolAddress((void**)&acard[1],  g_acard1);
    cudaGetSymbolAddress((void**)&amerch[0], g_amerch0);
    cudaGetSymbolAddress((void**)&amerch[1], g_amerch1);
    cudaGetSymbolAddress((void**)&pcard,   g_pcard);
    cudaGetSymbolAddress((void**)&pmerch,  g_pmerch);
    cudaGetSymbolAddress((void**)&aggc[0], g_aggc0);
    cudaGetSymbolAddress((void**)&aggc[1], g_aggc1);
    cudaGetSymbolAddress((void**)&aggm[0], g_aggm0);
    cudaGetSymbolAddress((void**)&aggm[1], g_aggm1);
    cudaGetSymbolAddress((void**)&invc,    g_invc);
    cudaGetSymbolAddress((void**)&invm,    g_invm);
    cudaGetSymbolAddress((void**)&bcomb,   g_bcomb);
    cudaGetSymbolAddress((void**)&zbias,   g_zbias);
    cudaGetSymbolAddress((void**)&wt,      g_wt);

    const size_t PTX = (size_t)N_TX * H_;
    const size_t PCD = (size_t)N_CARD * H_;
    const size_t PMR = (size_t)N_MERCH * H_;

    cudaFuncSetAttribute(mma_gemm, cudaFuncAttributeMaxDynamicSharedMemorySize, SMEM_BYTES);

    cudaStream_t st = 0;
    const int E = in_sizes[3];

    PrepArgs pa;
    {
        int i = 0;
        auto ent = [&](const float* s1, const float* s2, int K, int off) {
            pa.e[i].s1 = s1; pa.e[i].s2 = s2; pa.e[i].K = K; pa.e[i].off = off; i++;
        };
        const size_t WSZ = (size_t)H_ * H_;
        ent(tx_W,         nullptr, 128, OFF_TXW);
        ent(card_proj_W,  nullptr,  64, OFF_CPROJ);
        ent(merch_proj_W, nullptr,  64, OFF_MPROJ);
        ent(h1_W,         nullptr, 128, OFF_H1);
        for (int l = 0; l < 2; l++) {
            const float* Wl0 = conv_Wl + (size_t)(l * 4 + 0) * WSZ;
            const float* Wl1 = conv_Wl + (size_t)(l * 4 + 1) * WSZ;
            const float* Wl2 = conv_Wl + (size_t)(l * 4 + 2) * WSZ;
            const float* Wl3 = conv_Wl + (size_t)(l * 4 + 3) * WSZ;
            const float* Wr0 = conv_Wr + (size_t)(l * 4 + 0) * WSZ;
            const float* Wr1 = conv_Wr + (size_t)(l * 4 + 1) * WSZ;
            const float* Wr2 = conv_Wr + (size_t)(l * 4 + 2) * WSZ;
            const float* Wr3 = conv_Wr + (size_t)(l * 4 + 3) * WSZ;
            ent(Wl0, nullptr, 128, OFF_LAYER(l, 0));
            ent(Wl2, nullptr, 128, OFF_LAYER(l, 1));
            ent(Wr0, Wr2,     128, OFF_LAYER(l, 2));
            ent(Wl1, nullptr, 128, OFF_LAYER(l, 3));
            ent(Wr1, nullptr, 128, OFF_LAYER(l, 4));
            ent(Wl3, nullptr, 128, OFF_LAYER(l, 5));
            ent(Wr3, nullptr, 128, OFF_LAYER(l, 6));
        }
    }

    auto blocks = [](int m) { return (m + 127) / 128; };
    const __nv_bfloat16* NB = nullptr;
    const float* NF = nullptr;
    const int* NI = nullptr;
    float* NFo = nullptr;

    // launches 0..4 then encoder tx GEMM at index 5 (ncu -s 5 -c 1)
    prep_weights<<<18, 256, 0, st>>>(pa, wt);                                   // 0
    cudaMemsetAsync(invc, 0, N_CARD * sizeof(float), st);                       // 1
    cudaMemsetAsync(invm, 0, N_MERCH * sizeof(float), st);                      // 2
    cudaMemsetAsync(aggc[0], 0, PCD * sizeof(float), st);                       // 3
    cudaMemsetAsync(aggm[0], 0, PMR * sizeof(float), st);                       // 4
    // encoder tx GEMM: relu(tx_x@txW+b) -> atx0 planes, fused scatter -> agg0
    mma_gemm<<<blocks(N_TX), 256, SMEM_BYTES, st>>>(N_TX,                       // 5 <- profiled
        tx_x, NB, NB, nullptr, nullptr, OFF_TXW, 128,
        nullptr, NB, NB, nullptr, 0, 0,
        nullptr, NB, NB, 0, 0,
        wt, tx_b, atx[0], atx[0] + PTX, 1, nullptr,
        NF, NI, NF, NI,
        e_card, e_merch, aggc[0], aggm[0],
        nullptr, nullptr, nullptr);
    count_kernel<<<(E + 255) / 256, 256, 0, st>>>(e_card, e_merch, invc, invm, E);
    invert_kernel<<<(N_CARD + 255) / 256, 256, 0, st>>>(invc, N_CARD);
    invert_kernel<<<(N_MERCH + 255) / 256, 256, 0, st>>>(invm, N_MERCH);
    combine_bias<<<1, 256, 0, st>>>(conv_bl, bcomb);
    cudaMemsetAsync(aggc[1], 0, PCD * sizeof(float), st);
    cudaMemsetAsync(aggm[1], 0, PMR * sizeof(float), st);
    mma_gemm<<<blocks(N_CARD), 256, SMEM_BYTES, st>>>(N_CARD,
        card_emb, NB, NB, nullptr, nullptr, OFF_CPROJ, 64,
        nullptr, NB, NB, nullptr, 0, 0,
        nullptr, NB, NB, 0, 0,
        wt, card_proj_b, acard[0], acard[0] + PCD, 0, nullptr,
        NF, NI, NF, NI, NI, NI, NFo, NFo, nullptr, nullptr, nullptr);
    mma_gemm<<<blocks(N_MERCH), 256, SMEM_BYTES, st>>>(N_MERCH,
        merch_emb, NB, NB, nullptr, nullptr, OFF_MPROJ, 64,
        nullptr, NB, NB, nullptr, 0, 0,
        nullptr, NB, NB, 0, 0,
        wt, merch_proj_b, amerch[0], amerch[0] + PMR, 0, nullptr,
        NF, NI, NF, NI, NI, NI, NFo, NFo, nullptr, nullptr, nullptr);

    int cur = 0;
    for (int l = 0; l < 2; l++) {
        int nxt = cur ^ 1;
        const float* bl1 = conv_bl + (l * 4 + 1) * H_;
        const float* bl3 = conv_bl + (l * 4 + 3) * H_;

        // P_card = h_card @ Wl0 (fp32, zero bias)
        mma_gemm<<<blocks(N_CARD), 256, SMEM_BYTES, st>>>(N_CARD,
            nullptr, acard[cur], acard[cur] + PCD, nullptr, nullptr, OFF_LAYER(l, 0), 128,
            nullptr, NB, NB, nullptr, 0, 0,
            nullptr, NB, NB, 0, 0,
            wt, zbias, nullptr, nullptr, 0, pcard,
            NF, NI, NF, NI, NI, NI, NFo, NFo, nullptr, nullptr, nullptr);
        // P_merch = h_merch @ Wl2
        mma_gemm<<<blocks(N_MERCH), 256, SMEM_BYTES, st>>>(N_MERCH,
            nullptr, amerch[cur], amerch[cur] + PMR, nullptr, nullptr, OFF_LAYER(l, 1), 128,
            nullptr, NB, NB, nullptr, 0, 0,
            nullptr, NB, NB, 0, 0,
            wt, zbias, nullptr, nullptr, 0, pmerch,
            NF, NI, NF, NI, NI, NI, NFo, NFo, nullptr, nullptr, nullptr);
        // tx: h_tx@Wcomb + gather(P_card) + gather(P_merch) + bcomb, relu
        //     layer 0 additionally scatters h_tx^1 into agg[1] for layer 1
        mma_gemm<<<blocks(N_TX), 256, SMEM_BYTES, st>>>(N_TX,
            nullptr, atx[cur], atx[cur] + PTX, nullptr, nullptr, OFF_LAYER(l, 2), 128,
            nullptr, NB, NB, nullptr, 0, 0,
            nullptr, NB, NB, 0, 0,
            wt, bcomb + l * H_, atx[nxt], atx[nxt] + PTX, 1, nullptr,
            pcard, e_card, pmerch, e_merch,
            (l == 0) ? e_card : NI, (l == 0) ? e_merch : NI,
            (l == 0) ? aggc[1] : NFo, (l == 0) ? aggm[1] : NFo,
            nullptr, nullptr, nullptr);
        // card: (agg[l]*inv)@Wl1 + h_card@Wr1 + bl1, relu
        mma_gemm<<<blocks(N_CARD), 256, SMEM_BYTES, st>>>(N_CARD,
            aggc[l], NB, NB, nullptr, invc, OFF_LAYER(l, 3), 128,
            nullptr, acard[cur], acard[cur] + PCD, nullptr, OFF_LAYER(l, 4), 128,
            nullptr, NB, NB, 0, 0,
            wt, bl1, acard[nxt], acard[nxt] + PCD, 1, nullptr,
            NF, NI, NF, NI, NI, NI, NFo, NFo, nullptr, nullptr, nullptr);
        // merch
        mma_gemm<<<blocks(N_MERCH), 256, SMEM_BYTES, st>>>(N_MERCH,
            aggm[l], NB, NB, nullptr, invm, OFF_LAYER(l, 5), 128,
            nullptr, amerch[cur], amerch[cur] + PMR, nullptr, OFF_LAYER(l, 6), 128,
            nullptr, NB, NB, 0, 0,
            wt, bl3, amerch[nxt], amerch[nxt] + PMR, 1, nullptr,
            NF, NI, NF, NI, NI, NI, NFo, NFo, nullptr, nullptr, nullptr);
        cur = nxt;
    }

    // head: relu(h@h1_W+b1) @ h2_W + b2 (fused epilogue)
    mma_gemm<<<blocks(N_TX), 256, SMEM_BYTES, st>>>(N_TX,
        nullptr, atx[cur], atx[cur] + PTX, nullptr, nullptr, OFF_H1, 128,
        nullptr, NB, NB, nullptr, 0, 0,
        nullptr, NB, NB, 0, 0,
        wt, h1_b, nullptr, nullptr, 0, nullptr,
        NF, NI, NF, NI, NI, NI, NFo, NFo, h2_W, h2_b, out);
}

// round 12
// speedup vs baseline: 1.4152x; 1.2450x over previous
#include <cuda_runtime.h>
#include <cuda_bf16.h>
#include <cstdint>
#include <cstddef>

// ---------------------------------------------------------------------------
// HeteroSAGE on GB300 — Round 12: dead-code elimination + fused head
//  * R8 GEMM core (128x128, 2 CTAs/SM, 3-stage cp.async), standalone scatter
//  * deleted: layer-1 card/merch GEMMs, 2nd scatter, 2nd agg memsets (unused)
//  * head fused into layer-1 tx GEMM: tile -> smem planes -> @h1_W -> relu
//    -> dot h2_W -> logits. h_tx2 never hits DRAM.
// ---------------------------------------------------------------------------

namespace {
constexpr int H_      = 128;
constexpr int N_TX    = 200000;
constexpr int N_CARD  = 50000;
constexpr int N_MERCH = 10000;
constexpr int N_EDGE  = 200000;
constexpr int PLANE_B = 128 * 64;            // 8192 B
constexpr int STAGE_B = 4 * PLANE_B;         // 32768
constexpr int NSTAGE  = 3;
constexpr int SMEM_BYTES = NSTAGE * STAGE_B + 512;

constexpr int SZ128 = 2 * 128 * 128;
constexpr int SZ64  = 2 * 128 * 64;
constexpr int OFF_TXW   = 0;
constexpr int OFF_CPROJ = OFF_TXW + SZ128;
constexpr int OFF_MPROJ = OFF_CPROJ + SZ64;
constexpr int OFF_H1    = OFF_MPROJ + SZ64;
constexpr int OFF_L0    = OFF_H1 + SZ128;
constexpr int WT_TOTAL  = OFF_L0 + 14 * SZ128;
__host__ __device__ constexpr int OFF_LAYER(int l, int j) { return OFF_L0 + (l * 7 + j) * SZ128; }
}

// ---------------- scratch ----------------------------------------------------
__device__ __align__(16) __nv_bfloat16 g_atx0[2 * (size_t)N_TX * H_];
__device__ __align__(16) __nv_bfloat16 g_atx1[2 * (size_t)N_TX * H_];
__device__ __align__(16) __nv_bfloat16 g_acard0[2 * (size_t)N_CARD * H_];
__device__ __align__(16) __nv_bfloat16 g_acard1[2 * (size_t)N_CARD * H_];
__device__ __align__(16) __nv_bfloat16 g_amerch0[2 * (size_t)N_MERCH * H_];
__device__ __align__(16) __nv_bfloat16 g_amerch1[2 * (size_t)N_MERCH * H_];
__device__ __align__(16) float g_pcard[(size_t)N_CARD * H_];
__device__ __align__(16) float g_pmerch[(size_t)N_MERCH * H_];
__device__ float g_aggc[(size_t)N_CARD * H_];
__device__ float g_aggm[(size_t)N_MERCH * H_];
__device__ float g_invc[N_CARD];
__device__ float g_invm[N_MERCH];
__device__ float g_bcomb[2 * H_];
__device__ float g_zbias[H_];
__device__ __align__(16) __nv_bfloat16 g_wt[WT_TOTAL];

// ---------------- PTX helpers ------------------------------------------------
__device__ __forceinline__ uint32_t smem_u32(const void* p) {
    uint32_t a;
    asm("{ .reg .u64 t; cvta.to.shared.u64 t, %1; cvt.u32.u64 %0, t; }" : "=r"(a) : "l"(p));
    return a;
}
__device__ __forceinline__ void ldsm_x4(uint32_t* r, uint32_t addr) {
    asm volatile("ldmatrix.sync.aligned.m8n8.x4.shared.b16 {%0,%1,%2,%3}, [%4];"
                 : "=r"(r[0]), "=r"(r[1]), "=r"(r[2]), "=r"(r[3]) : "r"(addr));
}
__device__ __forceinline__ void mma_bf16(float* c, const uint32_t* a, const uint32_t* b) {
    asm volatile(
        "mma.sync.aligned.m16n8k16.row.col.f32.bf16.bf16.f32 "
        "{%0,%1,%2,%3}, {%4,%5,%6,%7}, {%8,%9}, {%0,%1,%2,%3};"
        : "+f"(c[0]), "+f"(c[1]), "+f"(c[2]), "+f"(c[3])
        : "r"(a[0]), "r"(a[1]), "r"(a[2]), "r"(a[3]), "r"(b[0]), "r"(b[1]));
}
__device__ __forceinline__ void cp16(uint32_t dst, const void* src) {
    asm volatile("cp.async.cg.shared.global [%0], [%1], 16;" :: "r"(dst), "l"(src) : "memory");
}
#define CP_COMMIT()  asm volatile("cp.async.commit_group;" ::: "memory")
#define CP_WAIT1()   asm volatile("cp.async.wait_group 1;" ::: "memory")
#define CP_WAIT0()   asm volatile("cp.async.wait_group 0;" ::: "memory")

__device__ __forceinline__ uint32_t swz(int r, int c) {
    return (uint32_t)r * 64u + (uint32_t)(((c ^ (r >> 1)) & 3) * 16);
}

// ---------------- small kernels ----------------------------------------------
__global__ void count_kernel(const int* __restrict__ ec, const int* __restrict__ em,
                             float* __restrict__ cc, float* __restrict__ cm, int E) {
    int i = blockIdx.x * blockDim.x + threadIdx.x;
    if (i < E) {
        atomicAdd(&cc[ec[i]], 1.0f);
        atomicAdd(&cm[em[i]], 1.0f);
    }
}

__global__ void invert_kernel(float* __restrict__ c, int n) {
    int i = blockIdx.x * blockDim.x + threadIdx.x;
    if (i < n) c[i] = 1.0f / fmaxf(c[i], 1.0f);
}

__global__ void combine_bias(const float* __restrict__ bl, float* __restrict__ bc) {
    int i = blockIdx.x * blockDim.x + threadIdx.x;
    if (i < 2 * H_) {
        int l = i >> 7, j = i & 127;
        bc[i] = bl[(l * 4 + 0) * H_ + j] + bl[(l * 4 + 2) * H_ + j];
    }
}

// standalone scatter (R8 version): reads bf16 hi/lo planes, red.v4
__global__ void scatter_kernel(const __nv_bfloat16* __restrict__ th,
                               const __nv_bfloat16* __restrict__ tl,
                               const int* __restrict__ ec, const int* __restrict__ em,
                               float* __restrict__ aggc, float* __restrict__ aggm) {
    int idx = blockIdx.x * blockDim.x + threadIdx.x;
    if (idx >= N_EDGE * 32) return;
    int e = idx >> 5, q = idx & 31;
    int f = q * 4;
    const size_t base = (size_t)e * H_ + f;
    uint2 hv = *(const uint2*)(th + base);
    uint2 lv = *(const uint2*)(tl + base);
    __nv_bfloat162 h0 = *reinterpret_cast<__nv_bfloat162*>(&hv.x);
    __nv_bfloat162 h1 = *reinterpret_cast<__nv_bfloat162*>(&hv.y);
    __nv_bfloat162 l0 = *reinterpret_cast<__nv_bfloat162*>(&lv.x);
    __nv_bfloat162 l1 = *reinterpret_cast<__nv_bfloat162*>(&lv.y);
    float v0 = __bfloat162float(h0.x) + __bfloat162float(l0.x);
    float v1 = __bfloat162float(h0.y) + __bfloat162float(l0.y);
    float v2 = __bfloat162float(h1.x) + __bfloat162float(l1.x);
    float v3 = __bfloat162float(h1.y) + __bfloat162float(l1.y);
    float* pc = aggc + (size_t)__ldg(&ec[e]) * H_ + f;
    asm volatile("red.global.add.v4.f32 [%0], {%1,%2,%3,%4};"
                 :: "l"(pc), "f"(v0), "f"(v1), "f"(v2), "f"(v3) : "memory");
    float* pm = aggm + (size_t)__ldg(&em[e]) * H_ + f;
    asm volatile("red.global.add.v4.f32 [%0], {%1,%2,%3,%4};"
                 :: "l"(pm), "f"(v0), "f"(v1), "f"(v2), "f"(v3) : "memory");
}

struct PrepEnt { const float* s1; const float* s2; int K; int off; };
struct PrepArgs { PrepEnt e[18]; };

__global__ void prep_weights(PrepArgs pa, __nv_bfloat16* __restrict__ wt) {
    PrepEnt en = pa.e[blockIdx.x];
    int total = 128 * en.K;
    for (int i = threadIdx.x; i < total; i += blockDim.x) {
        int n = i / en.K, k = i - n * en.K;
        float v = en.s1[(size_t)k * H_ + n];
        if (en.s2) v += en.s2[(size_t)k * H_ + n];
        __nv_bfloat16 h = __float2bfloat16(v);
        float r = v - __bfloat162float(h);
        wt[en.off + (size_t)n * en.K + k] = h;
        wt[en.off + (size_t)128 * en.K + (size_t)n * en.K + k] = __float2bfloat16(r);
    }
}

// ---------------------------------------------------------------------------
// 128x128 tile, 256 threads, KC=32 chunks, 3-stage cp.async pipeline.
// Outputs: presplit bf16 (Ch/Cl), fp32 (Cf), or FUSED HEAD (hout != null):
//   tile -> smem planes -> second GEMM vs wt[fhW1] (h1_W) -> +fhB1, relu,
//   dot hw2 -> hout[r] = dot + hb2.
// Optional epilogue gather-add: + GA0[GAI0[r]] + GA1[GAI1[r]].
// ---------------------------------------------------------------------------
__global__ __launch_bounds__(256, 2) void mma_gemm(
    int M,
    const float* __restrict__ A0f, const __nv_bfloat16* __restrict__ A0h,
    const __nv_bfloat16* __restrict__ A0l,
    const int* __restrict__ I0, const float* __restrict__ S0, int w0, int K0,
    const float* __restrict__ A1f, const __nv_bfloat16* __restrict__ A1h,
    const __nv_bfloat16* __restrict__ A1l,
    const int* __restrict__ I1, int w1, int K1,
    const float* __restrict__ A2f, const __nv_bfloat16* __restrict__ A2h,
    const __nv_bfloat16* __restrict__ A2l, int w2, int K2,
    const __nv_bfloat16* __restrict__ wt,
    const float* __restrict__ bias,
    __nv_bfloat16* __restrict__ Ch, __nv_bfloat16* __restrict__ Cl, int doRelu,
    float* __restrict__ Cf,
    const float* __restrict__ GA0, const int* __restrict__ GAI0,
    const float* __restrict__ GA1, const int* __restrict__ GAI1,
    int fhW1, const float* __restrict__ fhB1,
    const float* __restrict__ hw2, const float* __restrict__ hb2,
    float* __restrict__ hout) {
    extern __shared__ __align__(16) char smem_raw[];
    const uint32_t sb = smem_u32(smem_raw);
    float* partial = (float*)(smem_raw + NSTAGE * STAGE_B);

    const int tid = threadIdx.x, warp = tid >> 5, lane = tid & 31;
    const int rowG = warp >> 2, colG = warp & 3;
    const int row0 = blockIdx.x * 128;
    const bool fused = (hout != nullptr);
    if (fused && tid < 128) partial[tid] = 0.0f;

    const float* srcF[3] = {A0f, A1f, A2f};
    const __nv_bfloat16* srcH[3] = {A0h, A1h, A2h};
    const __nv_bfloat16* srcL[3] = {A0l, A1l, A2l};
    const int Ks[3] = {K0, K1, K2};
    const int wof[3] = {w0, w1, w2};
    const int nch0 = K0 >> 5, nch1 = K1 >> 5, nch2 = K2 >> 5;
    const int ntot = nch0 + nch1 + nch2;

    const int lrow = tid >> 1, lsel = tid & 1;
    int gi[3];
    float sc_[3];
    {
        int r = row0 + lrow;
        if (r >= M) r = M - 1;
        int g0 = r, g1 = r;
        if (I0) g0 = __ldg(&I0[r]);
        if (I1) g1 = __ldg(&I1[r]);
        gi[0] = g0; gi[1] = g1; gi[2] = r;
        sc_[0] = S0 ? __ldg(&S0[g0]) : 1.0f;
        sc_[1] = 1.0f; sc_[2] = 1.0f;
    }

    float acc[4][4][4];
#pragma unroll
    for (int mt = 0; mt < 4; mt++)
#pragma unroll
        for (int nt = 0; nt < 4; nt++)
#pragma unroll
            for (int j = 0; j < 4; j++) acc[mt][nt][j] = 0.0f;

    auto issue = [&](int c, int stage) {
        int s, kb;
        if (c < nch0) { s = 0; kb = c << 5; }
        else if (c < nch0 + nch1) { s = 1; kb = (c - nch0) << 5; }
        else { s = 2; kb = (c - nch0 - nch1) << 5; }
        const uint32_t base = sb + stage * STAGE_B;
        {
            const __nv_bfloat16* bsrc = wt + wof[s] +
                (lsel ? (size_t)128 * Ks[s] : 0) + (size_t)lrow * Ks[s] + kb;
            const uint32_t bpl = base + (lsel ? 3 : 2) * PLANE_B;
#pragma unroll
            for (int j = 0; j < 4; j++) cp16(bpl + swz(lrow, j), bsrc + j * 8);
        }
        if (srcF[s] == nullptr) {
            const __nv_bfloat16* asrc =
                (lsel ? srcL[s] : srcH[s]) + (size_t)gi[s] * 128 + kb;
            const uint32_t apl = base + (lsel ? PLANE_B : 0);
#pragma unroll
            for (int j = 0; j < 4; j++) cp16(apl + swz(lrow, j), asrc + j * 8);
        } else {
            const float sc = sc_[s];
            const float* ap = srcF[s] + (size_t)gi[s] * Ks[s] + kb + lsel * 16;
            float4 x = *(const float4*)(ap);
            float4 y = *(const float4*)(ap + 4);
            float4 z = *(const float4*)(ap + 8);
            float4 u = *(const float4*)(ap + 12);
            float v[16] = {x.x, x.y, x.z, x.w, y.x, y.y, y.z, y.w,
                           z.x, z.y, z.z, z.w, u.x, u.y, u.z, u.w};
            uint32_t hw_[8], lw_[8];
#pragma unroll
            for (int j = 0; j < 8; j++) {
                float a0 = v[2 * j] * sc, a1 = v[2 * j + 1] * sc;
                __nv_bfloat16 h0 = __float2bfloat16(a0);
                __nv_bfloat16 h1 = __float2bfloat16(a1);
                __nv_bfloat162 hp; hp.x = h0; hp.y = h1;
                __nv_bfloat162 lp;
                lp.x = __float2bfloat16(a0 - __bfloat162float(h0));
                lp.y = __float2bfloat16(a1 - __bfloat162float(h1));
                hw_[j] = *reinterpret_cast<uint32_t*>(&hp);
                lw_[j] = *reinterpret_cast<uint32_t*>(&lp);
            }
            const uint32_t aH0 = base + swz(lrow, lsel * 2);
            const uint32_t aH1 = base + swz(lrow, lsel * 2 + 1);
            asm volatile("st.shared.v4.b32 [%0], {%1,%2,%3,%4};"
                         :: "r"(aH0), "r"(hw_[0]), "r"(hw_[1]), "r"(hw_[2]), "r"(hw_[3]) : "memory");
            asm volatile("st.shared.v4.b32 [%0], {%1,%2,%3,%4};"
                         :: "r"(aH1), "r"(hw_[4]), "r"(hw_[5]), "r"(hw_[6]), "r"(hw_[7]) : "memory");
            asm volatile("st.shared.v4.b32 [%0], {%1,%2,%3,%4};"
                         :: "r"(aH0 + PLANE_B), "r"(lw_[0]), "r"(lw_[1]), "r"(lw_[2]), "r"(lw_[3]) : "memory");
            asm volatile("st.shared.v4.b32 [%0], {%1,%2,%3,%4};"
                         :: "r"(aH1 + PLANE_B), "r"(lw_[4]), "r"(lw_[5]), "r"(lw_[6]), "r"(lw_[7]) : "memory");
        }
    };

    const int laneR = lane & 15;
    const int xorA = (laneR >> 1) & 3;
    const int cA0  = lane >> 4;
    const int n_off = (((lane >> 4) & 1) * 8) + (lane & 7);
    const int xorB = (n_off >> 1) & 3;
    const int cB0  = (lane >> 3) & 1;

    auto computeAt = [&](uint32_t aHiB, uint32_t aLoB, uint32_t bHiB, uint32_t bLoB) {
        const uint32_t aRow = aHiB + (uint32_t)(rowG * 64 + laneR) * 64;
        const uint32_t aRowL = aLoB + (uint32_t)(rowG * 64 + laneR) * 64;
        const uint32_t bRow = bHiB + (uint32_t)(colG * 32 + n_off) * 64;
        const uint32_t bRowL = bLoB + (uint32_t)(colG * 32 + n_off) * 64;
#pragma unroll
        for (int ks = 0; ks < 2; ks++) {
            const uint32_t aC = (uint32_t)((cA0 + 2 * ks) ^ xorA) * 16;
            const uint32_t bC = (uint32_t)((cB0 + 2 * ks) ^ xorB) * 16;
            uint32_t bh[4][2], bl[4][2];
#pragma unroll
            for (int np = 0; np < 2; np++) {
                uint32_t r4[4];
                ldsm_x4(r4, bRow + np * (16 * 64) + bC);
                bh[np * 2][0] = r4[0]; bh[np * 2][1] = r4[1];
                bh[np * 2 + 1][0] = r4[2]; bh[np * 2 + 1][1] = r4[3];
                ldsm_x4(r4, bRowL + np * (16 * 64) + bC);
                bl[np * 2][0] = r4[0]; bl[np * 2][1] = r4[1];
                bl[np * 2 + 1][0] = r4[2]; bl[np * 2 + 1][1] = r4[3];
            }
#pragma unroll
            for (int mt = 0; mt < 4; mt++) {
                uint32_t ah[4], al[4];
                ldsm_x4(ah, aRow + mt * (16 * 64) + aC);
                ldsm_x4(al, aRowL + mt * (16 * 64) + aC);
#pragma unroll
                for (int nt = 0; nt < 4; nt++) {
                    mma_bf16(acc[mt][nt], ah, bh[nt]);
                    mma_bf16(acc[mt][nt], ah, bl[nt]);
                    mma_bf16(acc[mt][nt], al, bh[nt]);
                }
            }
        }
    };

    issue(0, 0);
    CP_COMMIT();
    if (ntot > 1) issue(1, 1);
    CP_COMMIT();
    int st_ = 0;
#pragma unroll 1
    for (int c = 0; c < ntot; c++) {
        CP_WAIT1();
        __syncthreads();
        if (c + 2 < ntot) {
            int s2 = st_ + 2; if (s2 >= NSTAGE) s2 -= NSTAGE;
            issue(c + 2, s2);
        }
        CP_COMMIT();
        const uint32_t base = sb + st_ * STAGE_B;
        computeAt(base, base + PLANE_B, base + 2 * PLANE_B, base + 3 * PLANE_B);
        if (++st_ == NSTAGE) st_ = 0;
    }

    // ---- epilogue ----
    const int rIn = lane >> 2;
    const int cIn = (lane & 3) * 2;

    // in fused mode, all pipeline reads must finish before reusing planes
    if (fused) __syncthreads();

#pragma unroll
    for (int mt = 0; mt < 4; mt++) {
        const int r0 = row0 + rowG * 64 + mt * 16 + rIn;
        const int r1 = r0 + 8;
        const bool v0r = r0 < M, v1r = r1 < M;
        const float *g00 = nullptr, *g01 = nullptr, *g10 = nullptr, *g11 = nullptr;
        if (GA0) {
            if (v0r) g00 = GA0 + (size_t)__ldg(&GAI0[r0]) * H_;
            if (v1r) g01 = GA0 + (size_t)__ldg(&GAI0[r1]) * H_;
        }
        if (GA1) {
            if (v0r) g10 = GA1 + (size_t)__ldg(&GAI1[r0]) * H_;
            if (v1r) g11 = GA1 + (size_t)__ldg(&GAI1[r1]) * H_;
        }
#pragma unroll
        for (int nt = 0; nt < 4; nt++) {
            const int col = colG * 32 + nt * 8 + cIn;
            const float b0 = __ldg(&bias[col]), b1 = __ldg(&bias[col + 1]);
            float o00 = acc[mt][nt][0] + b0, o01 = acc[mt][nt][1] + b1;
            float o10 = acc[mt][nt][2] + b0, o11 = acc[mt][nt][3] + b1;
            if (g00) { float2 g = *(const float2*)(g00 + col); o00 += g.x; o01 += g.y; }
            if (g10) { float2 g = *(const float2*)(g10 + col); o00 += g.x; o01 += g.y; }
            if (g01) { float2 g = *(const float2*)(g01 + col); o10 += g.x; o11 += g.y; }
            if (g11) { float2 g = *(const float2*)(g11 + col); o10 += g.x; o11 += g.y; }
            if (doRelu) {
                o00 = fmaxf(o00, 0.f); o01 = fmaxf(o01, 0.f);
                o10 = fmaxf(o10, 0.f); o11 = fmaxf(o11, 0.f);
            }
            if (fused) {
                // store hi/lo pairs into head A planes: hi plane = colG, lo = 4+colG
                const int la0 = rowG * 64 + mt * 16 + rIn;
                const int la1 = la0 + 8;
                const uint32_t pHi = sb + (uint32_t)colG * PLANE_B;
                const uint32_t pLo = pHi + 4u * PLANE_B;
                __nv_bfloat162 hp, lp;
                hp.x = __float2bfloat16(o00); hp.y = __float2bfloat16(o01);
                lp.x = __float2bfloat16(o00 - __bfloat162float(hp.x));
                lp.y = __float2bfloat16(o01 - __bfloat162float(hp.y));
                uint32_t a0 = swz(la0, nt) + (uint32_t)cIn * 2;
                asm volatile("st.shared.b32 [%0], %1;" :: "r"(pHi + a0), "r"(*(uint32_t*)&hp) : "memory");
                asm volatile("st.shared.b32 [%0], %1;" :: "r"(pLo + a0), "r"(*(uint32_t*)&lp) : "memory");
                hp.x = __float2bfloat16(o10); hp.y = __float2bfloat16(o11);
                lp.x = __float2bfloat16(o10 - __bfloat162float(hp.x));
                lp.y = __float2bfloat16(o11 - __bfloat162float(hp.y));
                uint32_t a1 = swz(la1, nt) + (uint32_t)cIn * 2;
                asm volatile("st.shared.b32 [%0], %1;" :: "r"(pHi + a1), "r"(*(uint32_t*)&hp) : "memory");
                asm volatile("st.shared.b32 [%0], %1;" :: "r"(pLo + a1), "r"(*(uint32_t*)&lp) : "memory");
            } else if (Cf) {
                if (v0r) *(float2*)(Cf + (size_t)r0 * H_ + col) = make_float2(o00, o01);
                if (v1r) *(float2*)(Cf + (size_t)r1 * H_ + col) = make_float2(o10, o11);
            } else {
                if (v0r) {
                    __nv_bfloat162 hp, lp;
                    hp.x = __float2bfloat16(o00); hp.y = __float2bfloat16(o01);
                    lp.x = __float2bfloat16(o00 - __bfloat162float(hp.x));
                    lp.y = __float2bfloat16(o01 - __bfloat162float(hp.y));
                    *(__nv_bfloat162*)(Ch + (size_t)r0 * H_ + col) = hp;
                    *(__nv_bfloat162*)(Cl + (size_t)r0 * H_ + col) = lp;
                }
                if (v1r) {
                    __nv_bfloat162 hp, lp;
                    hp.x = __float2bfloat16(o10); hp.y = __float2bfloat16(o11);
                    lp.x = __float2bfloat16(o10 - __bfloat162float(hp.x));
                    lp.y = __float2bfloat16(o11 - __bfloat162float(hp.y));
                    *(__nv_bfloat162*)(Ch + (size_t)r1 * H_ + col) = hp;
                    *(__nv_bfloat162*)(Cl + (size_t)r1 * H_ + col) = lp;
                }
            }
        }
    }

    if (!fused) return;

    // ---- fused head: D2 = tile @ h1_W, relu(+b1), dot h2_W -------------------
    auto issueHeadB = [&](int j) {
        const __nv_bfloat16* bsrc = wt + fhW1 +
            (lsel ? (size_t)128 * 128 : 0) + (size_t)lrow * 128 + j * 32;
        const uint32_t bpl = sb + (uint32_t)(8 + (j & 1) * 2 + lsel) * PLANE_B;
#pragma unroll
        for (int jj = 0; jj < 4; jj++) cp16(bpl + swz(lrow, jj), bsrc + jj * 8);
    };

#pragma unroll
    for (int mt = 0; mt < 4; mt++)
#pragma unroll
        for (int nt = 0; nt < 4; nt++)
#pragma unroll
            for (int j = 0; j < 4; j++) acc[mt][nt][j] = 0.0f;

    issueHeadB(0); CP_COMMIT();
    issueHeadB(1); CP_COMMIT();
    CP_WAIT1();
    __syncthreads();            // A-tile stores + B0 visible
#pragma unroll 1
    for (int j = 0; j < 4; j++) {
        if (j > 0) {
            __syncthreads();    // all warps done reading previous B buffer
            if (j + 1 < 4) { issueHeadB(j + 1); CP_COMMIT(); CP_WAIT1(); }
            else CP_WAIT0();
            __syncthreads();    // Bj visible
        }
        const uint32_t aHi = sb + (uint32_t)j * PLANE_B;
        const uint32_t bHi = sb + (uint32_t)(8 + (j & 1) * 2) * PLANE_B;
        computeAt(aHi, aHi + 4 * PLANE_B, bHi, bHi + PLANE_B);
    }

    // head dot epilogue
    {
        float h0[4], h1[4];
#pragma unroll
        for (int mt = 0; mt < 4; mt++) { h0[mt] = 0.f; h1[mt] = 0.f; }
#pragma unroll
        for (int mt = 0; mt < 4; mt++)
#pragma unroll
            for (int nt = 0; nt < 4; nt++) {
                const int col = colG * 32 + nt * 8 + cIn;
                const float b0 = __ldg(&fhB1[col]), b1 = __ldg(&fhB1[col + 1]);
                const float w20 = __ldg(&hw2[col]), w21 = __ldg(&hw2[col + 1]);
                h0[mt] = fmaf(fmaxf(acc[mt][nt][0] + b0, 0.f), w20, h0[mt]);
                h0[mt] = fmaf(fmaxf(acc[mt][nt][1] + b1, 0.f), w21, h0[mt]);
                h1[mt] = fmaf(fmaxf(acc[mt][nt][2] + b0, 0.f), w20, h1[mt]);
                h1[mt] = fmaf(fmaxf(acc[mt][nt][3] + b1, 0.f), w21, h1[mt]);
            }
#pragma unroll
        for (int mt = 0; mt < 4; mt++) {
            h0[mt] += __shfl_xor_sync(0xffffffffu, h0[mt], 1);
            h0[mt] += __shfl_xor_sync(0xffffffffu, h0[mt], 2);
            h1[mt] += __shfl_xor_sync(0xffffffffu, h1[mt], 1);
            h1[mt] += __shfl_xor_sync(0xffffffffu, h1[mt], 2);
        }
        __syncthreads();        // partial[] zeroed at start; ensure all past uses done
        if ((lane & 3) == 0) {
#pragma unroll
            for (int mt = 0; mt < 4; mt++) {
                atomicAdd(&partial[rowG * 64 + mt * 16 + rIn], h0[mt]);
                atomicAdd(&partial[rowG * 64 + mt * 16 + rIn + 8], h1[mt]);
            }
        }
        __syncthreads();
        if (tid < 128) {
            const int r = row0 + tid;
            if (r < M) hout[r] = partial[tid] + __ldg(&hb2[0]);
        }
    }
}

// ---------------------------------------------------------------------------
extern "C" void kernel_launch(void* const* d_in, const int* in_sizes, int n_in,
                              void* d_out, int out_size) {
    const float* tx_x         = (const float*)d_in[0];
    const int*   e_card       = (const int*)d_in[3];
    const int*   e_merch      = (const int*)d_in[5];
    const float* card_emb     = (const float*)d_in[7];
    const float* merch_emb    = (const float*)d_in[8];
    const float* card_proj_W  = (const float*)d_in[9];
    const float* card_proj_b  = (const float*)d_in[10];
    const float* merch_proj_W = (const float*)d_in[11];
    const float* merch_proj_b = (const float*)d_in[12];
    const float* tx_W         = (const float*)d_in[13];
    const float* tx_b         = (const float*)d_in[14];
    const float* conv_Wl      = (const float*)d_in[15];
    const float* conv_bl      = (const float*)d_in[16];
    const float* conv_Wr      = (const float*)d_in[17];
    const float* h1_W         = (const float*)d_in[18];
    const float* h1_b         = (const float*)d_in[19];
    const float* h2_W         = (const float*)d_in[20];
    const float* h2_b         = (const float*)d_in[21];
    float* out = (float*)d_out;

    __nv_bfloat16 *atx[2], *acard[2], *amerch[2], *wt;
    float *pcard, *pmerch, *aggc, *aggm, *invc, *invm, *bcomb, *zbias;
    cudaGetSymbolAddress((void**)&atx[0],    g_atx0);
    cudaGetSymbolAddress((void**)&atx[1],    g_atx1);
    cudaGetSymbolAddress((void**)&acard[0],  g_acard0);
    cudaGetSymbolAddress((void**)&acard[1],  g_acard1);
    cudaGetSymbolAddress((void**)&amerch[0], g_amerch0);
    cudaGetSymbolAddress((void**)&amerch[1], g_amerch1);
    cudaGetSymbolAddress((void**)&pcard,  g_pcard);
    cudaGetSymbolAddress((void**)&pmerch, g_pmerch);
    cudaGetSymbolAddress((void**)&aggc,   g_aggc);
    cudaGetSymbolAddress((void**)&aggm,   g_aggm);
    cudaGetSymbolAddress((void**)&invc,   g_invc);
    cudaGetSymbolAddress((void**)&invm,   g_invm);
    cudaGetSymbolAddress((void**)&bcomb,  g_bcomb);
    cudaGetSymbolAddress((void**)&zbias,  g_zbias);
    cudaGetSymbolAddress((void**)&wt,     g_wt);

    const size_t PTX = (size_t)N_TX * H_;
    const size_t PCD = (size_t)N_CARD * H_;
    const size_t PMR = (size_t)N_MERCH * H_;

    cudaFuncSetAttribute(mma_gemm, cudaFuncAttributeMaxDynamicSharedMemorySize, SMEM_BYTES);

    cudaStream_t st = 0;
    const int E = in_sizes[3];

    PrepArgs pa;
    {
        int i = 0;
        auto ent = [&](const float* s1, const float* s2, int K, int off) {
            pa.e[i].s1 = s1; pa.e[i].s2 = s2; pa.e[i].K = K; pa.e[i].off = off; i++;
        };
        const size_t WSZ = (size_t)H_ * H_;
        ent(tx_W,         nullptr, 128, OFF_TXW);
        ent(card_proj_W,  nullptr,  64, OFF_CPROJ);
        ent(merch_proj_W, nullptr,  64, OFF_MPROJ);
        ent(h1_W,         nullptr, 128, OFF_H1);
        for (int l = 0; l < 2; l++) {
            const float* Wl0 = conv_Wl + (size_t)(l * 4 + 0) * WSZ;
            const float* Wl1 = conv_Wl + (size_t)(l * 4 + 1) * WSZ;
            const float* Wl2 = conv_Wl + (size_t)(l * 4 + 2) * WSZ;
            const float* Wl3 = conv_Wl + (size_t)(l * 4 + 3) * WSZ;
            const float* Wr0 = conv_Wr + (size_t)(l * 4 + 0) * WSZ;
            const float* Wr1 = conv_Wr + (size_t)(l * 4 + 1) * WSZ;
            const float* Wr2 = conv_Wr + (size_t)(l * 4 + 2) * WSZ;
            const float* Wr3 = conv_Wr + (size_t)(l * 4 + 3) * WSZ;
            ent(Wl0, nullptr, 128, OFF_LAYER(l, 0));
            ent(Wl2, nullptr, 128, OFF_LAYER(l, 1));
            ent(Wr0, Wr2,     128, OFF_LAYER(l, 2));
            ent(Wl1, nullptr, 128, OFF_LAYER(l, 3));
            ent(Wr1, nullptr, 128, OFF_LAYER(l, 4));
            ent(Wl3, nullptr, 128, OFF_LAYER(l, 5));
            ent(Wr3, nullptr, 128, OFF_LAYER(l, 6));
        }
    }

    auto blocks = [](int m) { return (m + 127) / 128; };
    const __nv_bfloat16* NB = nullptr;
    const float* NF = nullptr;
    const int* NI = nullptr;

    // launches 0..4 then encoder tx GEMM at index 5 (ncu -s 5 -c 1)
    prep_weights<<<18, 256, 0, st>>>(pa, wt);                                   // 0
    cudaMemsetAsync(invc, 0, N_CARD * sizeof(float), st);                       // 1
    cudaMemsetAsync(invm, 0, N_MERCH * sizeof(float), st);                      // 2
    cudaMemsetAsync(aggc, 0, PCD * sizeof(float), st);                          // 3
    cudaMemsetAsync(aggm, 0, PMR * sizeof(float), st);                          // 4
    mma_gemm<<<blocks(N_TX), 256, SMEM_BYTES, st>>>(N_TX,                       // 5 <- profiled
        tx_x, NB, NB, nullptr, nullptr, OFF_TXW, 128,
        nullptr, NB, NB, nullptr, 0, 0,
        nullptr, NB, NB, 0, 0,
        wt, tx_b, atx[0], atx[0] + PTX, 1, nullptr,
        NF, NI, NF, NI, 0, nullptr, nullptr, nullptr, nullptr);
    count_kernel<<<(E + 255) / 256, 256, 0, st>>>(e_card, e_merch, invc, invm, E);
    invert_kernel<<<(N_CARD + 255) / 256, 256, 0, st>>>(invc, N_CARD);
    invert_kernel<<<(N_MERCH + 255) / 256, 256, 0, st>>>(invm, N_MERCH);
    combine_bias<<<1, 256, 0, st>>>(conv_bl, bcomb);
    mma_gemm<<<blocks(N_CARD), 256, SMEM_BYTES, st>>>(N_CARD,
        card_emb, NB, NB, nullptr, nullptr, OFF_CPROJ, 64,
        nullptr, NB, NB, nullptr, 0, 0,
        nullptr, NB, NB, 0, 0,
        wt, card_proj_b, acard[0], acard[0] + PCD, 0, nullptr,
        NF, NI, NF, NI, 0, nullptr, nullptr, nullptr, nullptr);
    mma_gemm<<<blocks(N_MERCH), 256, SMEM_BYTES, st>>>(N_MERCH,
        merch_emb, NB, NB, nullptr, nullptr, OFF_MPROJ, 64,
        nullptr, NB, NB, nullptr, 0, 0,
        nullptr, NB, NB, 0, 0,
        wt, merch_proj_b, amerch[0], amerch[0] + PMR, 0, nullptr,
        NF, NI, NF, NI, 0, nullptr, nullptr, nullptr, nullptr);
    // single scatter: h_tx0 -> agg (feeds layer-0 card/merch updates)
    scatter_kernel<<<(N_EDGE * 32 + 255) / 256, 256, 0, st>>>(
        atx[0], atx[0] + PTX, e_card, e_merch, aggc, aggm);

    // ---- layer 0 (full update) ----
    mma_gemm<<<blocks(N_CARD), 256, SMEM_BYTES, st>>>(N_CARD,
        nullptr, acard[0], acard[0] + PCD, nullptr, nullptr, OFF_LAYER(0, 0), 128,
        nullptr, NB, NB, nullptr, 0, 0,
        nullptr, NB, NB, 0, 0,
        wt, zbias, nullptr, nullptr, 0, pcard,
        NF, NI, NF, NI, 0, nullptr, nullptr, nullptr, nullptr);
    mma_gemm<<<blocks(N_MERCH), 256, SMEM_BYTES, st>>>(N_MERCH,
        nullptr, amerch[0], amerch[0] + PMR, nullptr, nullptr, OFF_LAYER(0, 1), 128,
        nullptr, NB, NB, nullptr, 0, 0,
        nullptr, NB, NB, 0, 0,
        wt, zbias, nullptr, nullptr, 0, pmerch,
        NF, NI, NF, NI, 0, nullptr, nullptr, nullptr, nullptr);
    mma_gemm<<<blocks(N_TX), 256, SMEM_BYTES, st>>>(N_TX,
        nullptr, atx[0], atx[0] + PTX, nullptr, nullptr, OFF_LAYER(0, 2), 128,
        nullptr, NB, NB, nullptr, 0, 0,
        nullptr, NB, NB, 0, 0,
        wt, bcomb, atx[1], atx[1] + PTX, 1, nullptr,
        pcard, e_card, pmerch, e_merch, 0, nullptr, nullptr, nullptr, nullptr);
    mma_gemm<<<blocks(N_CARD), 256, SMEM_BYTES, st>>>(N_CARD,
        aggc, NB, NB, nullptr, invc, OFF_LAYER(0, 3), 128,
        nullptr, acard[0], acard[0] + PCD, nullptr, OFF_LAYER(0, 4), 128,
        nullptr, NB, NB, 0, 0,
        wt, conv_bl + 1 * H_, acard[1], acard[1] + PCD, 1, nullptr,
        NF, NI, NF, NI, 0, nullptr, nullptr, nullptr, nullptr);
    mma_gemm<<<blocks(N_MERCH), 256, SMEM_BYTES, st>>>(N_MERCH,
        aggm, NB, NB, nullptr, invm, OFF_LAYER(0, 5), 128,
        nullptr, amerch[0], amerch[0] + PMR, nullptr, OFF_LAYER(0, 6), 128,
        nullptr, NB, NB, 0, 0,
        wt, conv_bl + 3 * H_, amerch[1], amerch[1] + PMR, 1, nullptr,
        NF, NI, NF, NI, 0, nullptr, nullptr, nullptr, nullptr);

    // ---- layer 1 (only tx needed) + fused head ----
    mma_gemm<<<blocks(N_CARD), 256, SMEM_BYTES, st>>>(N_CARD,
        nullptr, acard[1], acard[1] + PCD, nullptr, nullptr, OFF_LAYER(1, 0), 128,
        nullptr, NB, NB, nullptr, 0, 0,
        nullptr, NB, NB, 0, 0,
        wt, zbias, nullptr, nullptr, 0, pcard,
        NF, NI, NF, NI, 0, nullptr, nullptr, nullptr, nullptr);
    mma_gemm<<<blocks(N_MERCH), 256, SMEM_BYTES, st>>>(N_MERCH,
        nullptr, amerch[1], amerch[1] + PMR, nullptr, nullptr, OFF_LAYER(1, 1), 128,
        nullptr, NB, NB, nullptr, 0, 0,
        nullptr, NB, NB, 0, 0,
        wt, zbias, nullptr, nullptr, 0, pmerch,
        NF, NI, NF, NI, 0, nullptr, nullptr, nullptr, nullptr);
    // tx2 + fused head: logits written directly
    mma_gemm<<<blocks(N_TX), 256, SMEM_BYTES, st>>>(N_TX,
        nullptr, atx[1], atx[1] + PTX, nullptr, nullptr, OFF_LAYER(1, 2), 128,
        nullptr, NB, NB, nullptr, 0, 0,
        nullptr, NB, NB, 0, 0,
        wt, bcomb + H_, nullptr, nullptr, 1, nullptr,
        pcard, e_card, pmerch, e_merch,
        OFF_H1, h1_b, h2_W, h2_b, out);
}

// round 13
// speedup vs baseline: 1.6650x; 1.1765x over previous
#include <cuda_runtime.h>
#include <cuda_bf16.h>
#include <cstdint>
#include <cstddef>

// ---------------------------------------------------------------------------
// HeteroSAGE on GB300 — Round 13: full tx-spine chain in one kernel
//  * mega kernel: relu(atx0@Wcomb0 +P0 +b0) -> smem -> relu(@Wcomb1 +P1 +b1)
//    -> smem -> @h1_W +b, relu, dot h2_W -> logits.  atx1 never exists.
//  * R8 GEMM core (128x128, 2 CTAs/SM, 3-stage cp.async), standalone scatter
// ---------------------------------------------------------------------------

namespace {
constexpr int H_      = 128;
constexpr int N_TX    = 200000;
constexpr int N_CARD  = 50000;
constexpr int N_MERCH = 10000;
constexpr int N_EDGE  = 200000;
constexpr int PLANE_B = 128 * 64;            // 8192 B
constexpr int STAGE_B = 4 * PLANE_B;         // 32768
constexpr int NSTAGE  = 3;
constexpr int SMEM_BYTES = NSTAGE * STAGE_B + 512;

constexpr int SZ128 = 2 * 128 * 128;
constexpr int SZ64  = 2 * 128 * 64;
constexpr int OFF_TXW   = 0;
constexpr int OFF_CPROJ = OFF_TXW + SZ128;
constexpr int OFF_MPROJ = OFF_CPROJ + SZ64;
constexpr int OFF_H1    = OFF_MPROJ + SZ64;
constexpr int OFF_L0    = OFF_H1 + SZ128;
constexpr int WT_TOTAL  = OFF_L0 + 14 * SZ128;
__host__ __device__ constexpr int OFF_LAYER(int l, int j) { return OFF_L0 + (l * 7 + j) * SZ128; }
}

// ---------------- scratch ----------------------------------------------------
__device__ __align__(16) __nv_bfloat16 g_atx0[2 * (size_t)N_TX * H_];
__device__ __align__(16) __nv_bfloat16 g_acard0[2 * (size_t)N_CARD * H_];
__device__ __align__(16) __nv_bfloat16 g_acard1[2 * (size_t)N_CARD * H_];
__device__ __align__(16) __nv_bfloat16 g_amerch0[2 * (size_t)N_MERCH * H_];
__device__ __align__(16) __nv_bfloat16 g_amerch1[2 * (size_t)N_MERCH * H_];
__device__ __align__(16) float g_pcard0[(size_t)N_CARD * H_];
__device__ __align__(16) float g_pmerch0[(size_t)N_MERCH * H_];
__device__ __align__(16) float g_pcard1[(size_t)N_CARD * H_];
__device__ __align__(16) float g_pmerch1[(size_t)N_MERCH * H_];
__device__ float g_aggc[(size_t)N_CARD * H_];
__device__ float g_aggm[(size_t)N_MERCH * H_];
__device__ float g_invc[N_CARD];
__device__ float g_invm[N_MERCH];
__device__ float g_bcomb[2 * H_];
__device__ float g_zbias[H_];
__device__ __align__(16) __nv_bfloat16 g_wt[WT_TOTAL];

// ---------------- PTX helpers ------------------------------------------------
__device__ __forceinline__ uint32_t smem_u32(const void* p) {
    uint32_t a;
    asm("{ .reg .u64 t; cvta.to.shared.u64 t, %1; cvt.u32.u64 %0, t; }" : "=r"(a) : "l"(p));
    return a;
}
__device__ __forceinline__ void ldsm_x4(uint32_t* r, uint32_t addr) {
    asm volatile("ldmatrix.sync.aligned.m8n8.x4.shared.b16 {%0,%1,%2,%3}, [%4];"
                 : "=r"(r[0]), "=r"(r[1]), "=r"(r[2]), "=r"(r[3]) : "r"(addr));
}
__device__ __forceinline__ void mma_bf16(float* c, const uint32_t* a, const uint32_t* b) {
    asm volatile(
        "mma.sync.aligned.m16n8k16.row.col.f32.bf16.bf16.f32 "
        "{%0,%1,%2,%3}, {%4,%5,%6,%7}, {%8,%9}, {%0,%1,%2,%3};"
        : "+f"(c[0]), "+f"(c[1]), "+f"(c[2]), "+f"(c[3])
        : "r"(a[0]), "r"(a[1]), "r"(a[2]), "r"(a[3]), "r"(b[0]), "r"(b[1]));
}
__device__ __forceinline__ void cp16(uint32_t dst, const void* src) {
    asm volatile("cp.async.cg.shared.global [%0], [%1], 16;" :: "r"(dst), "l"(src) : "memory");
}
#define CP_COMMIT()  asm volatile("cp.async.commit_group;" ::: "memory")
#define CP_WAIT1()   asm volatile("cp.async.wait_group 1;" ::: "memory")
#define CP_WAIT0()   asm volatile("cp.async.wait_group 0;" ::: "memory")

__device__ __forceinline__ uint32_t swz(int r, int c) {
    return (uint32_t)r * 64u + (uint32_t)(((c ^ (r >> 1)) & 3) * 16);
}

// ---------------- small kernels ----------------------------------------------
__global__ void count_kernel(const int* __restrict__ ec, const int* __restrict__ em,
                             float* __restrict__ cc, float* __restrict__ cm, int E) {
    int i = blockIdx.x * blockDim.x + threadIdx.x;
    if (i < E) {
        atomicAdd(&cc[ec[i]], 1.0f);
        atomicAdd(&cm[em[i]], 1.0f);
    }
}

__global__ void invert_kernel(float* __restrict__ c, int n) {
    int i = blockIdx.x * blockDim.x + threadIdx.x;
    if (i < n) c[i] = 1.0f / fmaxf(c[i], 1.0f);
}

__global__ void combine_bias(const float* __restrict__ bl, float* __restrict__ bc) {
    int i = blockIdx.x * blockDim.x + threadIdx.x;
    if (i < 2 * H_) {
        int l = i >> 7, j = i & 127;
        bc[i] = bl[(l * 4 + 0) * H_ + j] + bl[(l * 4 + 2) * H_ + j];
    }
}

__global__ void scatter_kernel(const __nv_bfloat16* __restrict__ th,
                               const __nv_bfloat16* __restrict__ tl,
                               const int* __restrict__ ec, const int* __restrict__ em,
                               float* __restrict__ aggc, float* __restrict__ aggm) {
    int idx = blockIdx.x * blockDim.x + threadIdx.x;
    if (idx >= N_EDGE * 32) return;
    int e = idx >> 5, q = idx & 31;
    int f = q * 4;
    const size_t base = (size_t)e * H_ + f;
    uint2 hv = *(const uint2*)(th + base);
    uint2 lv = *(const uint2*)(tl + base);
    __nv_bfloat162 h0 = *reinterpret_cast<__nv_bfloat162*>(&hv.x);
    __nv_bfloat162 h1 = *reinterpret_cast<__nv_bfloat162*>(&hv.y);
    __nv_bfloat162 l0 = *reinterpret_cast<__nv_bfloat162*>(&lv.x);
    __nv_bfloat162 l1 = *reinterpret_cast<__nv_bfloat162*>(&lv.y);
    float v0 = __bfloat162float(h0.x) + __bfloat162float(l0.x);
    float v1 = __bfloat162float(h0.y) + __bfloat162float(l0.y);
    float v2 = __bfloat162float(h1.x) + __bfloat162float(l1.x);
    float v3 = __bfloat162float(h1.y) + __bfloat162float(l1.y);
    float* pc = aggc + (size_t)__ldg(&ec[e]) * H_ + f;
    asm volatile("red.global.add.v4.f32 [%0], {%1,%2,%3,%4};"
                 :: "l"(pc), "f"(v0), "f"(v1), "f"(v2), "f"(v3) : "memory");
    float* pm = aggm + (size_t)__ldg(&em[e]) * H_ + f;
    asm volatile("red.global.add.v4.f32 [%0], {%1,%2,%3,%4};"
                 :: "l"(pm), "f"(v0), "f"(v1), "f"(v2), "f"(v3) : "memory");
}

struct PrepEnt { const float* s1; const float* s2; int K; int off; };
struct PrepArgs { PrepEnt e[18]; };

__global__ void prep_weights(PrepArgs pa, __nv_bfloat16* __restrict__ wt) {
    PrepEnt en = pa.e[blockIdx.x];
    int total = 128 * en.K;
    for (int i = threadIdx.x; i < total; i += blockDim.x) {
        int n = i / en.K, k = i - n * en.K;
        float v = en.s1[(size_t)k * H_ + n];
        if (en.s2) v += en.s2[(size_t)k * H_ + n];
        __nv_bfloat16 h = __float2bfloat16(v);
        float r = v - __bfloat162float(h);
        wt[en.off + (size_t)n * en.K + k] = h;
        wt[en.off + (size_t)128 * en.K + (size_t)n * en.K + k] = __float2bfloat16(r);
    }
}

// ---------------------------------------------------------------------------
// 128x128 tile, 256 threads, KC=32 chunks, 3-stage cp.async pipeline.
// Normal modes: presplit bf16 (Ch/Cl) or fp32 (Cf) output, optional gathers.
// Chain mode (hout != null): mainloop epilogue -> smem tile; then
//   stage2: tile@wt[cW] (+cB +gathers cGA*), relu -> smem tile;
//   stage3: tile@wt[fhW1] (+fhB1), relu, dot hw2 -> hout = . + hb2.
// ---------------------------------------------------------------------------
__global__ __launch_bounds__(256, 2) void mma_gemm(
    int M,
    const float* __restrict__ A0f, const __nv_bfloat16* __restrict__ A0h,
    const __nv_bfloat16* __restrict__ A0l,
    const int* __restrict__ I0, const float* __restrict__ S0, int w0, int K0,
    const float* __restrict__ A1f, const __nv_bfloat16* __restrict__ A1h,
    const __nv_bfloat16* __restrict__ A1l,
    const int* __restrict__ I1, int w1, int K1,
    const float* __restrict__ A2f, const __nv_bfloat16* __restrict__ A2h,
    const __nv_bfloat16* __restrict__ A2l, int w2, int K2,
    const __nv_bfloat16* __restrict__ wt,
    const float* __restrict__ bias,
    __nv_bfloat16* __restrict__ Ch, __nv_bfloat16* __restrict__ Cl, int doRelu,
    float* __restrict__ Cf,
    const float* __restrict__ GA0, const int* __restrict__ GAI0,
    const float* __restrict__ GA1, const int* __restrict__ GAI1,
    int cW, const float* __restrict__ cB,
    const float* __restrict__ cGA0, const int* __restrict__ cGAI0,
    const float* __restrict__ cGA1, const int* __restrict__ cGAI1,
    int fhW1, const float* __restrict__ fhB1,
    const float* __restrict__ hw2, const float* __restrict__ hb2,
    float* __restrict__ hout) {
    extern __shared__ __align__(16) char smem_raw[];
    const uint32_t sb = smem_u32(smem_raw);
    float* partial = (float*)(smem_raw + NSTAGE * STAGE_B);

    const int tid = threadIdx.x, warp = tid >> 5, lane = tid & 31;
    const int rowG = warp >> 2, colG = warp & 3;
    const int row0 = blockIdx.x * 128;
    const bool fused = (hout != nullptr);
    if (fused && tid < 128) partial[tid] = 0.0f;

    const float* srcF[3] = {A0f, A1f, A2f};
    const __nv_bfloat16* srcH[3] = {A0h, A1h, A2h};
    const __nv_bfloat16* srcL[3] = {A0l, A1l, A2l};
    const int Ks[3] = {K0, K1, K2};
    const int wof[3] = {w0, w1, w2};
    const int nch0 = K0 >> 5, nch1 = K1 >> 5, nch2 = K2 >> 5;
    const int ntot = nch0 + nch1 + nch2;

    const int lrow = tid >> 1, lsel = tid & 1;
    int gi[3];
    float sc_[3];
    {
        int r = row0 + lrow;
        if (r >= M) r = M - 1;
        int g0 = r, g1 = r;
        if (I0) g0 = __ldg(&I0[r]);
        if (I1) g1 = __ldg(&I1[r]);
        gi[0] = g0; gi[1] = g1; gi[2] = r;
        sc_[0] = S0 ? __ldg(&S0[g0]) : 1.0f;
        sc_[1] = 1.0f; sc_[2] = 1.0f;
    }

    float acc[4][4][4];
#pragma unroll
    for (int mt = 0; mt < 4; mt++)
#pragma unroll
        for (int nt = 0; nt < 4; nt++)
#pragma unroll
            for (int j = 0; j < 4; j++) acc[mt][nt][j] = 0.0f;

    auto issue = [&](int c, int stage) {
        int s, kb;
        if (c < nch0) { s = 0; kb = c << 5; }
        else if (c < nch0 + nch1) { s = 1; kb = (c - nch0) << 5; }
        else { s = 2; kb = (c - nch0 - nch1) << 5; }
        const uint32_t base = sb + stage * STAGE_B;
        {
            const __nv_bfloat16* bsrc = wt + wof[s] +
                (lsel ? (size_t)128 * Ks[s] : 0) + (size_t)lrow * Ks[s] + kb;
            const uint32_t bpl = base + (lsel ? 3 : 2) * PLANE_B;
#pragma unroll
            for (int j = 0; j < 4; j++) cp16(bpl + swz(lrow, j), bsrc + j * 8);
        }
        if (srcF[s] == nullptr) {
            const __nv_bfloat16* asrc =
                (lsel ? srcL[s] : srcH[s]) + (size_t)gi[s] * 128 + kb;
            const uint32_t apl = base + (lsel ? PLANE_B : 0);
#pragma unroll
            for (int j = 0; j < 4; j++) cp16(apl + swz(lrow, j), asrc + j * 8);
        } else {
            const float sc = sc_[s];
            const float* ap = srcF[s] + (size_t)gi[s] * Ks[s] + kb + lsel * 16;
            float4 x = *(const float4*)(ap);
            float4 y = *(const float4*)(ap + 4);
            float4 z = *(const float4*)(ap + 8);
            float4 u = *(const float4*)(ap + 12);
            float v[16] = {x.x, x.y, x.z, x.w, y.x, y.y, y.z, y.w,
                           z.x, z.y, z.z, z.w, u.x, u.y, u.z, u.w};
            uint32_t hw_[8], lw_[8];
#pragma unroll
            for (int j = 0; j < 8; j++) {
                float a0 = v[2 * j] * sc, a1 = v[2 * j + 1] * sc;
                __nv_bfloat16 h0 = __float2bfloat16(a0);
                __nv_bfloat16 h1 = __float2bfloat16(a1);
                __nv_bfloat162 hp; hp.x = h0; hp.y = h1;
                __nv_bfloat162 lp;
                lp.x = __float2bfloat16(a0 - __bfloat162float(h0));
                lp.y = __float2bfloat16(a1 - __bfloat162float(h1));
                hw_[j] = *reinterpret_cast<uint32_t*>(&hp);
                lw_[j] = *reinterpret_cast<uint32_t*>(&lp);
            }
            const uint32_t aH0 = base + swz(lrow, lsel * 2);
            const uint32_t aH1 = base + swz(lrow, lsel * 2 + 1);
            asm volatile("st.shared.v4.b32 [%0], {%1,%2,%3,%4};"
                         :: "r"(aH0), "r"(hw_[0]), "r"(hw_[1]), "r"(hw_[2]), "r"(hw_[3]) : "memory");
            asm volatile("st.shared.v4.b32 [%0], {%1,%2,%3,%4};"
                         :: "r"(aH1), "r"(hw_[4]), "r"(hw_[5]), "r"(hw_[6]), "r"(hw_[7]) : "memory");
            asm volatile("st.shared.v4.b32 [%0], {%1,%2,%3,%4};"
                         :: "r"(aH0 + PLANE_B), "r"(lw_[0]), "r"(lw_[1]), "r"(lw_[2]), "r"(lw_[3]) : "memory");
            asm volatile("st.shared.v4.b32 [%0], {%1,%2,%3,%4};"
                         :: "r"(aH1 + PLANE_B), "r"(lw_[4]), "r"(lw_[5]), "r"(lw_[6]), "r"(lw_[7]) : "memory");
        }
    };

    const int laneR = lane & 15;
    const int xorA = (laneR >> 1) & 3;
    const int cA0  = lane >> 4;
    const int n_off = (((lane >> 4) & 1) * 8) + (lane & 7);
    const int xorB = (n_off >> 1) & 3;
    const int cB0  = (lane >> 3) & 1;

    auto computeAt = [&](uint32_t aHiB, uint32_t aLoB, uint32_t bHiB, uint32_t bLoB) {
        const uint32_t aRow = aHiB + (uint32_t)(rowG * 64 + laneR) * 64;
        const uint32_t aRowL = aLoB + (uint32_t)(rowG * 64 + laneR) * 64;
        const uint32_t bRow = bHiB + (uint32_t)(colG * 32 + n_off) * 64;
        const uint32_t bRowL = bLoB + (uint32_t)(colG * 32 + n_off) * 64;
#pragma unroll
        for (int ks = 0; ks < 2; ks++) {
            const uint32_t aC = (uint32_t)((cA0 + 2 * ks) ^ xorA) * 16;
            const uint32_t bC = (uint32_t)((cB0 + 2 * ks) ^ xorB) * 16;
            uint32_t bh[4][2], bl[4][2];
#pragma unroll
            for (int np = 0; np < 2; np++) {
                uint32_t r4[4];
                ldsm_x4(r4, bRow + np * (16 * 64) + bC);
                bh[np * 2][0] = r4[0]; bh[np * 2][1] = r4[1];
                bh[np * 2 + 1][0] = r4[2]; bh[np * 2 + 1][1] = r4[3];
                ldsm_x4(r4, bRowL + np * (16 * 64) + bC);
                bl[np * 2][0] = r4[0]; bl[np * 2][1] = r4[1];
                bl[np * 2 + 1][0] = r4[2]; bl[np * 2 + 1][1] = r4[3];
            }
#pragma unroll
            for (int mt = 0; mt < 4; mt++) {
                uint32_t ah[4], al[4];
                ldsm_x4(ah, aRow + mt * (16 * 64) + aC);
                ldsm_x4(al, aRowL + mt * (16 * 64) + aC);
#pragma unroll
                for (int nt = 0; nt < 4; nt++) {
                    mma_bf16(acc[mt][nt], ah, bh[nt]);
                    mma_bf16(acc[mt][nt], ah, bl[nt]);
                    mma_bf16(acc[mt][nt], al, bh[nt]);
                }
            }
        }
    };

    issue(0, 0);
    CP_COMMIT();
    if (ntot > 1) issue(1, 1);
    CP_COMMIT();
    int st_ = 0;
#pragma unroll 1
    for (int c = 0; c < ntot; c++) {
        CP_WAIT1();
        __syncthreads();
        if (c + 2 < ntot) {
            int s2 = st_ + 2; if (s2 >= NSTAGE) s2 -= NSTAGE;
            issue(c + 2, s2);
        }
        CP_COMMIT();
        const uint32_t base = sb + st_ * STAGE_B;
        computeAt(base, base + PLANE_B, base + 2 * PLANE_B, base + 3 * PLANE_B);
        if (++st_ == NSTAGE) st_ = 0;
    }

    const int rIn = lane >> 2;
    const int cIn = (lane & 3) * 2;

    // store acc tile (+bias+gathers, relu) into smem planes 0-7 (hi 0-3, lo 4-7)
    auto storeTileSmem = [&](const float* bs,
                             const float* ga0, const int* gai0,
                             const float* ga1, const int* gai1) {
#pragma unroll
        for (int mt = 0; mt < 4; mt++) {
            const int r0 = row0 + rowG * 64 + mt * 16 + rIn;
            const int r1 = r0 + 8;
            const bool v0r = r0 < M, v1r = r1 < M;
            int q0 = v0r ? r0 : M - 1, q1 = v1r ? r1 : M - 1;
            const float *g00 = nullptr, *g01 = nullptr, *g10 = nullptr, *g11 = nullptr;
            if (ga0) {
                g00 = ga0 + (size_t)__ldg(&gai0[q0]) * H_;
                g01 = ga0 + (size_t)__ldg(&gai0[q1]) * H_;
            }
            if (ga1) {
                g10 = ga1 + (size_t)__ldg(&gai1[q0]) * H_;
                g11 = ga1 + (size_t)__ldg(&gai1[q1]) * H_;
            }
#pragma unroll
            for (int nt = 0; nt < 4; nt++) {
                const int col = colG * 32 + nt * 8 + cIn;
                const float b0 = __ldg(&bs[col]), b1 = __ldg(&bs[col + 1]);
                float o00 = acc[mt][nt][0] + b0, o01 = acc[mt][nt][1] + b1;
                float o10 = acc[mt][nt][2] + b0, o11 = acc[mt][nt][3] + b1;
                if (g00) { float2 g = *(const float2*)(g00 + col); o00 += g.x; o01 += g.y; }
                if (g10) { float2 g = *(const float2*)(g10 + col); o00 += g.x; o01 += g.y; }
                if (g01) { float2 g = *(const float2*)(g01 + col); o10 += g.x; o11 += g.y; }
                if (g11) { float2 g = *(const float2*)(g11 + col); o10 += g.x; o11 += g.y; }
                o00 = fmaxf(o00, 0.f); o01 = fmaxf(o01, 0.f);
                o10 = fmaxf(o10, 0.f); o11 = fmaxf(o11, 0.f);
                const int la0 = rowG * 64 + mt * 16 + rIn;
                const int la1 = la0 + 8;
                const uint32_t pHi = sb + (uint32_t)colG * PLANE_B;
                const uint32_t pLo = pHi + 4u * PLANE_B;
                __nv_bfloat162 hp, lp;
                hp.x = __float2bfloat16(o00); hp.y = __float2bfloat16(o01);
                lp.x = __float2bfloat16(o00 - __bfloat162float(hp.x));
                lp.y = __float2bfloat16(o01 - __bfloat162float(hp.y));
                uint32_t a0 = swz(la0, nt) + (uint32_t)cIn * 2;
                asm volatile("st.shared.b32 [%0], %1;" :: "r"(pHi + a0), "r"(*(uint32_t*)&hp) : "memory");
                asm volatile("st.shared.b32 [%0], %1;" :: "r"(pLo + a0), "r"(*(uint32_t*)&lp) : "memory");
                hp.x = __float2bfloat16(o10); hp.y = __float2bfloat16(o11);
                lp.x = __float2bfloat16(o10 - __bfloat162float(hp.x));
                lp.y = __float2bfloat16(o11 - __bfloat162float(hp.y));
                uint32_t a1 = swz(la1, nt) + (uint32_t)cIn * 2;
                asm volatile("st.shared.b32 [%0], %1;" :: "r"(pHi + a1), "r"(*(uint32_t*)&hp) : "memory");
                asm volatile("st.shared.b32 [%0], %1;" :: "r"(pLo + a1), "r"(*(uint32_t*)&lp) : "memory");
            }
        }
    };

    // chained in-smem GEMM: acc = tile(planes 0-7) @ wt[woff]
    auto issueChB = [&](int woff, int j) {
        const __nv_bfloat16* bsrc = wt + woff +
            (lsel ? (size_t)128 * 128 : 0) + (size_t)lrow * 128 + j * 32;
        const uint32_t bpl = sb + (uint32_t)(8 + (j & 1) * 2 + lsel) * PLANE_B;
#pragma unroll
        for (int jj = 0; jj < 4; jj++) cp16(bpl + swz(lrow, jj), bsrc + jj * 8);
    };
    auto chainCompute = [&](int woff) {
#pragma unroll
        for (int mt = 0; mt < 4; mt++)
#pragma unroll
            for (int nt = 0; nt < 4; nt++)
#pragma unroll
                for (int j = 0; j < 4; j++) acc[mt][nt][j] = 0.0f;
        issueChB(woff, 0); CP_COMMIT();
        issueChB(woff, 1); CP_COMMIT();
        CP_WAIT1();
        __syncthreads();            // tile stores + B0 visible
#pragma unroll 1
        for (int j = 0; j < 4; j++) {
            if (j > 0) {
                __syncthreads();    // previous B buffer fully consumed
                if (j + 1 < 4) { issueChB(woff, j + 1); CP_COMMIT(); CP_WAIT1(); }
                else CP_WAIT0();
                __syncthreads();    // Bj visible
            }
            const uint32_t aHi = sb + (uint32_t)j * PLANE_B;
            const uint32_t bHi = sb + (uint32_t)(8 + (j & 1) * 2) * PLANE_B;
            computeAt(aHi, aHi + 4 * PLANE_B, bHi, bHi + PLANE_B);
        }
    };

    if (!fused) {
        // ---- normal epilogue: write to DRAM ----
#pragma unroll
        for (int mt = 0; mt < 4; mt++) {
            const int r0 = row0 + rowG * 64 + mt * 16 + rIn;
            const int r1 = r0 + 8;
            const bool v0r = r0 < M, v1r = r1 < M;
            const float *g00 = nullptr, *g01 = nullptr, *g10 = nullptr, *g11 = nullptr;
            if (GA0) {
                if (v0r) g00 = GA0 + (size_t)__ldg(&GAI0[r0]) * H_;
                if (v1r) g01 = GA0 + (size_t)__ldg(&GAI0[r1]) * H_;
            }
            if (GA1) {
                if (v0r) g10 = GA1 + (size_t)__ldg(&GAI1[r0]) * H_;
                if (v1r) g11 = GA1 + (size_t)__ldg(&GAI1[r1]) * H_;
            }
#pragma unroll
            for (int nt = 0; nt < 4; nt++) {
                const int col = colG * 32 + nt * 8 + cIn;
                const float b0 = __ldg(&bias[col]), b1 = __ldg(&bias[col + 1]);
                float o00 = acc[mt][nt][0] + b0, o01 = acc[mt][nt][1] + b1;
                float o10 = acc[mt][nt][2] + b0, o11 = acc[mt][nt][3] + b1;
                if (g00) { float2 g = *(const float2*)(g00 + col); o00 += g.x; o01 += g.y; }
                if (g10) { float2 g = *(const float2*)(g10 + col); o00 += g.x; o01 += g.y; }
                if (g01) { float2 g = *(const float2*)(g01 + col); o10 += g.x; o11 += g.y; }
                if (g11) { float2 g = *(const float2*)(g11 + col); o10 += g.x; o11 += g.y; }
                if (doRelu) {
                    o00 = fmaxf(o00, 0.f); o01 = fmaxf(o01, 0.f);
                    o10 = fmaxf(o10, 0.f); o11 = fmaxf(o11, 0.f);
                }
                if (Cf) {
                    if (v0r) *(float2*)(Cf + (size_t)r0 * H_ + col) = make_float2(o00, o01);
                    if (v1r) *(float2*)(Cf + (size_t)r1 * H_ + col) = make_float2(o10, o11);
                } else {
                    if (v0r) {
                        __nv_bfloat162 hp, lp;
                        hp.x = __float2bfloat16(o00); hp.y = __float2bfloat16(o01);
                        lp.x = __float2bfloat16(o00 - __bfloat162float(hp.x));
                        lp.y = __float2bfloat16(o01 - __bfloat162float(hp.y));
                        *(__nv_bfloat162*)(Ch + (size_t)r0 * H_ + col) = hp;
                        *(__nv_bfloat162*)(Cl + (size_t)r0 * H_ + col) = lp;
                    }
                    if (v1r) {
                        __nv_bfloat162 hp, lp;
                        hp.x = __float2bfloat16(o10); hp.y = __float2bfloat16(o11);
                        lp.x = __float2bfloat16(o10 - __bfloat162float(hp.x));
                        lp.y = __float2bfloat16(o11 - __bfloat162float(hp.y));
                        *(__nv_bfloat162*)(Ch + (size_t)r1 * H_ + col) = hp;
                        *(__nv_bfloat162*)(Cl + (size_t)r1 * H_ + col) = lp;
                    }
                }
            }
        }
        return;
    }

    // ---- chain mode ----
    __syncthreads();                              // pipeline smem reads complete
    storeTileSmem(bias, GA0, GAI0, GA1, GAI1);    // tile1 = relu(mainloop + P0 + b0)
    chainCompute(cW);                             // acc = tile1 @ Wcomb1
    __syncthreads();                              // planes 0-7 fully consumed
    storeTileSmem(cB, cGA0, cGAI0, cGA1, cGAI1);  // tile2 = relu(acc + P1 + b1)
    chainCompute(fhW1);                           // acc = tile2 @ h1_W

    // head dot epilogue
    {
        float h0[4], h1[4];
#pragma unroll
        for (int mt = 0; mt < 4; mt++) { h0[mt] = 0.f; h1[mt] = 0.f; }
#pragma unroll
        for (int mt = 0; mt < 4; mt++)
#pragma unroll
            for (int nt = 0; nt < 4; nt++) {
                const int col = colG * 32 + nt * 8 + cIn;
                const float b0 = __ldg(&fhB1[col]), b1 = __ldg(&fhB1[col + 1]);
                const float w20 = __ldg(&hw2[col]), w21 = __ldg(&hw2[col + 1]);
                h0[mt] = fmaf(fmaxf(acc[mt][nt][0] + b0, 0.f), w20, h0[mt]);
                h0[mt] = fmaf(fmaxf(acc[mt][nt][1] + b1, 0.f), w21, h0[mt]);
                h1[mt] = fmaf(fmaxf(acc[mt][nt][2] + b0, 0.f), w20, h1[mt]);
                h1[mt] = fmaf(fmaxf(acc[mt][nt][3] + b1, 0.f), w21, h1[mt]);
            }
#pragma unroll
        for (int mt = 0; mt < 4; mt++) {
            h0[mt] += __shfl_xor_sync(0xffffffffu, h0[mt], 1);
            h0[mt] += __shfl_xor_sync(0xffffffffu, h0[mt], 2);
            h1[mt] += __shfl_xor_sync(0xffffffffu, h1[mt], 1);
            h1[mt] += __shfl_xor_sync(0xffffffffu, h1[mt], 2);
        }
        __syncthreads();
        if ((lane & 3) == 0) {
#pragma unroll
            for (int mt = 0; mt < 4; mt++) {
                atomicAdd(&partial[rowG * 64 + mt * 16 + rIn], h0[mt]);
                atomicAdd(&partial[rowG * 64 + mt * 16 + rIn + 8], h1[mt]);
            }
        }
        __syncthreads();
        if (tid < 128) {
            const int r = row0 + tid;
            if (r < M) hout[r] = partial[tid] + __ldg(&hb2[0]);
        }
    }
}

// ---------------------------------------------------------------------------
extern "C" void kernel_launch(void* const* d_in, const int* in_sizes, int n_in,
                              void* d_out, int out_size) {
    const float* tx_x         = (const float*)d_in[0];
    const int*   e_card       = (const int*)d_in[3];
    const int*   e_merch      = (const int*)d_in[5];
    const float* card_emb     = (const float*)d_in[7];
    const float* merch_emb    = (const float*)d_in[8];
    const float* card_proj_W  = (const float*)d_in[9];
    const float* card_proj_b  = (const float*)d_in[10];
    const float* merch_proj_W = (const float*)d_in[11];
    const float* merch_proj_b = (const float*)d_in[12];
    const float* tx_W         = (const float*)d_in[13];
    const float* tx_b         = (const float*)d_in[14];
    const float* conv_Wl      = (const float*)d_in[15];
    const float* conv_bl      = (const float*)d_in[16];
    const float* conv_Wr      = (const float*)d_in[17];
    const float* h1_W         = (const float*)d_in[18];
    const float* h1_b         = (const float*)d_in[19];
    const float* h2_W         = (const float*)d_in[20];
    const float* h2_b         = (const float*)d_in[21];
    float* out = (float*)d_out;

    __nv_bfloat16 *atx0, *acard[2], *amerch[2], *wt;
    float *pc0, *pm0, *pc1, *pm1, *aggc, *aggm, *invc, *invm, *bcomb, *zbias;
    cudaGetSymbolAddress((void**)&atx0,      g_atx0);
    cudaGetSymbolAddress((void**)&acard[0],  g_acard0);
    cudaGetSymbolAddress((void**)&acard[1],  g_acard1);
    cudaGetSymbolAddress((void**)&amerch[0], g_amerch0);
    cudaGetSymbolAddress((void**)&amerch[1], g_amerch1);
    cudaGetSymbolAddress((void**)&pc0,   g_pcard0);
    cudaGetSymbolAddress((void**)&pm0,   g_pmerch0);
    cudaGetSymbolAddress((void**)&pc1,   g_pcard1);
    cudaGetSymbolAddress((void**)&pm1,   g_pmerch1);
    cudaGetSymbolAddress((void**)&aggc,  g_aggc);
    cudaGetSymbolAddress((void**)&aggm,  g_aggm);
    cudaGetSymbolAddress((void**)&invc,  g_invc);
    cudaGetSymbolAddress((void**)&invm,  g_invm);
    cudaGetSymbolAddress((void**)&bcomb, g_bcomb);
    cudaGetSymbolAddress((void**)&zbias, g_zbias);
    cudaGetSymbolAddress((void**)&wt,    g_wt);

    const size_t PTX = (size_t)N_TX * H_;
    const size_t PCD = (size_t)N_CARD * H_;
    const size_t PMR = (size_t)N_MERCH * H_;

    cudaFuncSetAttribute(mma_gemm, cudaFuncAttributeMaxDynamicSharedMemorySize, SMEM_BYTES);

    cudaStream_t st = 0;
    const int E = in_sizes[3];

    PrepArgs pa;
    {
        int i = 0;
        auto ent = [&](const float* s1, const float* s2, int K, int off) {
            pa.e[i].s1 = s1; pa.e[i].s2 = s2; pa.e[i].K = K; pa.e[i].off = off; i++;
        };
        const size_t WSZ = (size_t)H_ * H_;
        ent(tx_W,         nullptr, 128, OFF_TXW);
        ent(card_proj_W,  nullptr,  64, OFF_CPROJ);
        ent(merch_proj_W, nullptr,  64, OFF_MPROJ);
        ent(h1_W,         nullptr, 128, OFF_H1);
        for (int l = 0; l < 2; l++) {
            const float* Wl0 = conv_Wl + (size_t)(l * 4 + 0) * WSZ;
            const float* Wl1 = conv_Wl + (size_t)(l * 4 + 1) * WSZ;
            const float* Wl2 = conv_Wl + (size_t)(l * 4 + 2) * WSZ;
            const float* Wl3 = conv_Wl + (size_t)(l * 4 + 3) * WSZ;
            const float* Wr0 = conv_Wr + (size_t)(l * 4 + 0) * WSZ;
            const float* Wr1 = conv_Wr + (size_t)(l * 4 + 1) * WSZ;
            const float* Wr2 = conv_Wr + (size_t)(l * 4 + 2) * WSZ;
            const float* Wr3 = conv_Wr + (size_t)(l * 4 + 3) * WSZ;
            ent(Wl0, nullptr, 128, OFF_LAYER(l, 0));
            ent(Wl2, nullptr, 128, OFF_LAYER(l, 1));
            ent(Wr0, Wr2,     128, OFF_LAYER(l, 2));
            ent(Wl1, nullptr, 128, OFF_LAYER(l, 3));
            ent(Wr1, nullptr, 128, OFF_LAYER(l, 4));
            ent(Wl3, nullptr, 128, OFF_LAYER(l, 5));
            ent(Wr3, nullptr, 128, OFF_LAYER(l, 6));
        }
    }

    auto blocks = [](int m) { return (m + 127) / 128; };
    const __nv_bfloat16* NB = nullptr;
    const float* NF = nullptr;
    const int* NI = nullptr;

    // launches 0..4 then encoder tx GEMM at index 5 (ncu -s 5 -c 1)
    prep_weights<<<18, 256, 0, st>>>(pa, wt);                                   // 0
    cudaMemsetAsync(invc, 0, N_CARD * sizeof(float), st);                       // 1
    cudaMemsetAsync(invm, 0, N_MERCH * sizeof(float), st);                      // 2
    cudaMemsetAsync(aggc, 0, PCD * sizeof(float), st);                          // 3
    cudaMemsetAsync(aggm, 0, PMR * sizeof(float), st);                          // 4
    mma_gemm<<<blocks(N_TX), 256, SMEM_BYTES, st>>>(N_TX,                       // 5 <- profiled
        tx_x, NB, NB, nullptr, nullptr, OFF_TXW, 128,
        nullptr, NB, NB, nullptr, 0, 0,
        nullptr, NB, NB, 0, 0,
        wt, tx_b, atx0, atx0 + PTX, 1, nullptr,
        NF, NI, NF, NI,
        0, nullptr, NF, NI, NF, NI,
        0, nullptr, nullptr, nullptr, nullptr);
    count_kernel<<<(E + 255) / 256, 256, 0, st>>>(e_card, e_merch, invc, invm, E);
    invert_kernel<<<(N_CARD + 255) / 256, 256, 0, st>>>(invc, N_CARD);
    invert_kernel<<<(N_MERCH + 255) / 256, 256, 0, st>>>(invm, N_MERCH);
    combine_bias<<<1, 256, 0, st>>>(conv_bl, bcomb);
    mma_gemm<<<blocks(N_CARD), 256, SMEM_BYTES, st>>>(N_CARD,
        card_emb, NB, NB, nullptr, nullptr, OFF_CPROJ, 64,
        nullptr, NB, NB, nullptr, 0, 0,
        nullptr, NB, NB, 0, 0,
        wt, card_proj_b, acard[0], acard[0] + PCD, 0, nullptr,
        NF, NI, NF, NI, 0, nullptr, NF, NI, NF, NI,
        0, nullptr, nullptr, nullptr, nullptr);
    mma_gemm<<<blocks(N_MERCH), 256, SMEM_BYTES, st>>>(N_MERCH,
        merch_emb, NB, NB, nullptr, nullptr, OFF_MPROJ, 64,
        nullptr, NB, NB, nullptr, 0, 0,
        nullptr, NB, NB, 0, 0,
        wt, merch_proj_b, amerch[0], amerch[0] + PMR, 0, nullptr,
        NF, NI, NF, NI, 0, nullptr, NF, NI, NF, NI,
        0, nullptr, nullptr, nullptr, nullptr);
    // scatter h_tx0 -> agg (feeds layer-0 card/merch updates)
    scatter_kernel<<<(N_EDGE * 32 + 255) / 256, 256, 0, st>>>(
        atx0, atx0 + PTX, e_card, e_merch, aggc, aggm);

    // P0 (for layer-0 tx) from encoder card/merch outputs
    mma_gemm<<<blocks(N_CARD), 256, SMEM_BYTES, st>>>(N_CARD,
        nullptr, acard[0], acard[0] + PCD, nullptr, nullptr, OFF_LAYER(0, 0), 128,
        nullptr, NB, NB, nullptr, 0, 0,
        nullptr, NB, NB, 0, 0,
        wt, zbias, nullptr, nullptr, 0, pc0,
        NF, NI, NF, NI, 0, nullptr, NF, NI, NF, NI,
        0, nullptr, nullptr, nullptr, nullptr);
    mma_gemm<<<blocks(N_MERCH), 256, SMEM_BYTES, st>>>(N_MERCH,
        nullptr, amerch[0], amerch[0] + PMR, nullptr, nullptr, OFF_LAYER(0, 1), 128,
        nullptr, NB, NB, nullptr, 0, 0,
        nullptr, NB, NB, 0, 0,
        wt, zbias, nullptr, nullptr, 0, pm0,
        NF, NI, NF, NI, 0, nullptr, NF, NI, NF, NI,
        0, nullptr, nullptr, nullptr, nullptr);
    // layer-0 card/merch updates -> h_card1, h_merch1
    mma_gemm<<<blocks(N_CARD), 256, SMEM_BYTES, st>>>(N_CARD,
        aggc, NB, NB, nullptr, invc, OFF_LAYER(0, 3), 128,
        nullptr, acard[0], acard[0] + PCD, nullptr, OFF_LAYER(0, 4), 128,
        nullptr, NB, NB, 0, 0,
        wt, conv_bl + 1 * H_, acard[1], acard[1] + PCD, 1, nullptr,
        NF, NI, NF, NI, 0, nullptr, NF, NI, NF, NI,
        0, nullptr, nullptr, nullptr, nullptr);
    mma_gemm<<<blocks(N_MERCH), 256, SMEM_BYTES, st>>>(N_MERCH,
        aggm, NB, NB, nullptr, invm, OFF_LAYER(0, 5), 128,
        nullptr, amerch[0], amerch[0] + PMR, nullptr, OFF_LAYER(0, 6), 128,
        nullptr, NB, NB, 0, 0,
        wt, conv_bl + 3 * H_, amerch[1], amerch[1] + PMR, 1, nullptr,
        NF, NI, NF, NI, 0, nullptr, NF, NI, NF, NI,
        0, nullptr, nullptr, nullptr, nullptr);
    // P1 (for layer-1 tx) from updated card/merch
    mma_gemm<<<blocks(N_CARD), 256, SMEM_BYTES, st>>>(N_CARD,
        nullptr, acard[1], acard[1] + PCD, nullptr, nullptr, OFF_LAYER(1, 0), 128,
        nullptr, NB, NB, nullptr, 0, 0,
        nullptr, NB, NB, 0, 0,
        wt, zbias, nullptr, nullptr, 0, pc1,
        NF, NI, NF, NI, 0, nullptr, NF, NI, NF, NI,
        0, nullptr, nullptr, nullptr, nullptr);
    mma_gemm<<<blocks(N_MERCH), 256, SMEM_BYTES, st>>>(N_MERCH,
        nullptr, amerch[1], amerch[1] + PMR, nullptr, nullptr, OFF_LAYER(1, 1), 128,
        nullptr, NB, NB, nullptr, 0, 0,
        nullptr, NB, NB, 0, 0,
        wt, zbias, nullptr, nullptr, 0, pm1,
        NF, NI, NF, NI, 0, nullptr, NF, NI, NF, NI,
        0, nullptr, nullptr, nullptr, nullptr);

    // MEGA: layer-0 tx -> layer-1 tx -> head, all in-smem chained
    mma_gemm<<<blocks(N_TX), 256, SMEM_BYTES, st>>>(N_TX,
        nullptr, atx0, atx0 + PTX, nullptr, nullptr, OFF_LAYER(0, 2), 128,
        nullptr, NB, NB, nullptr, 0, 0,
        nullptr, NB, NB, 0, 0,
        wt, bcomb, nullptr, nullptr, 1, nullptr,
        pc0, e_card, pm0, e_merch,
        OFF_LAYER(1, 2), bcomb + H_, pc1, e_card, pm1, e_merch,
        OFF_H1, h1_b, h2_W, h2_b, out);
}

// round 14
// speedup vs baseline: 1.7601x; 1.0571x over previous
#include <cuda_runtime.h>
#include <cuda_bf16.h>
#include <cstdint>
#include <cstddef>

// ---------------------------------------------------------------------------
// HeteroSAGE on GB300 — Round 14: chain-to-fp32 for P projections
//  * encoders chain  h0 -> P0 = h0@Wl(l,0)  (h0 also written to DRAM)
//  * node updates chain h1 -> P1 (h1 never hits DRAM; only P1 consumed)
//  * mega kernel (layer0 tx -> layer1 tx -> head) unchanged from R13
// ---------------------------------------------------------------------------

namespace {
constexpr int H_      = 128;
constexpr int N_TX    = 200000;
constexpr int N_CARD  = 50000;
constexpr int N_MERCH = 10000;
constexpr int N_EDGE  = 200000;
constexpr int PLANE_B = 128 * 64;            // 8192 B
constexpr int STAGE_B = 4 * PLANE_B;         // 32768
constexpr int NSTAGE  = 3;
constexpr int SMEM_BYTES = NSTAGE * STAGE_B + 512;

constexpr int SZ128 = 2 * 128 * 128;
constexpr int SZ64  = 2 * 128 * 64;
constexpr int OFF_TXW   = 0;
constexpr int OFF_CPROJ = OFF_TXW + SZ128;
constexpr int OFF_MPROJ = OFF_CPROJ + SZ64;
constexpr int OFF_H1    = OFF_MPROJ + SZ64;
constexpr int OFF_L0    = OFF_H1 + SZ128;
constexpr int WT_TOTAL  = OFF_L0 + 14 * SZ128;
__host__ __device__ constexpr int OFF_LAYER(int l, int j) { return OFF_L0 + (l * 7 + j) * SZ128; }
}

// ---------------- scratch ----------------------------------------------------
__device__ __align__(16) __nv_bfloat16 g_atx0[2 * (size_t)N_TX * H_];
__device__ __align__(16) __nv_bfloat16 g_acard0[2 * (size_t)N_CARD * H_];
__device__ __align__(16) __nv_bfloat16 g_amerch0[2 * (size_t)N_MERCH * H_];
__device__ __align__(16) float g_pcard0[(size_t)N_CARD * H_];
__device__ __align__(16) float g_pmerch0[(size_t)N_MERCH * H_];
__device__ __align__(16) float g_pcard1[(size_t)N_CARD * H_];
__device__ __align__(16) float g_pmerch1[(size_t)N_MERCH * H_];
__device__ float g_aggc[(size_t)N_CARD * H_];
__device__ float g_aggm[(size_t)N_MERCH * H_];
__device__ float g_invc[N_CARD];
__device__ float g_invm[N_MERCH];
__device__ float g_bcomb[2 * H_];
__device__ float g_zbias[H_];
__device__ __align__(16) __nv_bfloat16 g_wt[WT_TOTAL];

// ---------------- PTX helpers ------------------------------------------------
__device__ __forceinline__ uint32_t smem_u32(const void* p) {
    uint32_t a;
    asm("{ .reg .u64 t; cvta.to.shared.u64 t, %1; cvt.u32.u64 %0, t; }" : "=r"(a) : "l"(p));
    return a;
}
__device__ __forceinline__ void ldsm_x4(uint32_t* r, uint32_t addr) {
    asm volatile("ldmatrix.sync.aligned.m8n8.x4.shared.b16 {%0,%1,%2,%3}, [%4];"
                 : "=r"(r[0]), "=r"(r[1]), "=r"(r[2]), "=r"(r[3]) : "r"(addr));
}
__device__ __forceinline__ void mma_bf16(float* c, const uint32_t* a, const uint32_t* b) {
    asm volatile(
        "mma.sync.aligned.m16n8k16.row.col.f32.bf16.bf16.f32 "
        "{%0,%1,%2,%3}, {%4,%5,%6,%7}, {%8,%9}, {%0,%1,%2,%3};"
        : "+f"(c[0]), "+f"(c[1]), "+f"(c[2]), "+f"(c[3])
        : "r"(a[0]), "r"(a[1]), "r"(a[2]), "r"(a[3]), "r"(b[0]), "r"(b[1]));
}
__device__ __forceinline__ void cp16(uint32_t dst, const void* src) {
    asm volatile("cp.async.cg.shared.global [%0], [%1], 16;" :: "r"(dst), "l"(src) : "memory");
}
#define CP_COMMIT()  asm volatile("cp.async.commit_group;" ::: "memory")
#define CP_WAIT1()   asm volatile("cp.async.wait_group 1;" ::: "memory")
#define CP_WAIT0()   asm volatile("cp.async.wait_group 0;" ::: "memory")

__device__ __forceinline__ uint32_t swz(int r, int c) {
    return (uint32_t)r * 64u + (uint32_t)(((c ^ (r >> 1)) & 3) * 16);
}

// ---------------- small kernels ----------------------------------------------
__global__ void count_kernel(const int* __restrict__ ec, const int* __restrict__ em,
                             float* __restrict__ cc, float* __restrict__ cm, int E) {
    int i = blockIdx.x * blockDim.x + threadIdx.x;
    if (i < E) {
        atomicAdd(&cc[ec[i]], 1.0f);
        atomicAdd(&cm[em[i]], 1.0f);
    }
}

__global__ void invert_kernel(float* __restrict__ c, int n) {
    int i = blockIdx.x * blockDim.x + threadIdx.x;
    if (i < n) c[i] = 1.0f / fmaxf(c[i], 1.0f);
}

__global__ void combine_bias(const float* __restrict__ bl, float* __restrict__ bc) {
    int i = blockIdx.x * blockDim.x + threadIdx.x;
    if (i < 2 * H_) {
        int l = i >> 7, j = i & 127;
        bc[i] = bl[(l * 4 + 0) * H_ + j] + bl[(l * 4 + 2) * H_ + j];
    }
}

__global__ void scatter_kernel(const __nv_bfloat16* __restrict__ th,
                               const __nv_bfloat16* __restrict__ tl,
                               const int* __restrict__ ec, const int* __restrict__ em,
                               float* __restrict__ aggc, float* __restrict__ aggm) {
    int idx = blockIdx.x * blockDim.x + threadIdx.x;
    if (idx >= N_EDGE * 32) return;
    int e = idx >> 5, q = idx & 31;
    int f = q * 4;
    const size_t base = (size_t)e * H_ + f;
    uint2 hv = *(const uint2*)(th + base);
    uint2 lv = *(const uint2*)(tl + base);
    __nv_bfloat162 h0 = *reinterpret_cast<__nv_bfloat162*>(&hv.x);
    __nv_bfloat162 h1 = *reinterpret_cast<__nv_bfloat162*>(&hv.y);
    __nv_bfloat162 l0 = *reinterpret_cast<__nv_bfloat162*>(&lv.x);
    __nv_bfloat162 l1 = *reinterpret_cast<__nv_bfloat162*>(&lv.y);
    float v0 = __bfloat162float(h0.x) + __bfloat162float(l0.x);
    float v1 = __bfloat162float(h0.y) + __bfloat162float(l0.y);
    float v2 = __bfloat162float(h1.x) + __bfloat162float(l1.x);
    float v3 = __bfloat162float(h1.y) + __bfloat162float(l1.y);
    float* pc = aggc + (size_t)__ldg(&ec[e]) * H_ + f;
    asm volatile("red.global.add.v4.f32 [%0], {%1,%2,%3,%4};"
                 :: "l"(pc), "f"(v0), "f"(v1), "f"(v2), "f"(v3) : "memory");
    float* pm = aggm + (size_t)__ldg(&em[e]) * H_ + f;
    asm volatile("red.global.add.v4.f32 [%0], {%1,%2,%3,%4};"
                 :: "l"(pm), "f"(v0), "f"(v1), "f"(v2), "f"(v3) : "memory");
}

struct PrepEnt { const float* s1; const float* s2; int K; int off; };
struct PrepArgs { PrepEnt e[18]; };

__global__ void prep_weights(PrepArgs pa, __nv_bfloat16* __restrict__ wt) {
    PrepEnt en = pa.e[blockIdx.x];
    int total = 128 * en.K;
    for (int i = threadIdx.x; i < total; i += blockDim.x) {
        int n = i / en.K, k = i - n * en.K;
        float v = en.s1[(size_t)k * H_ + n];
        if (en.s2) v += en.s2[(size_t)k * H_ + n];
        __nv_bfloat16 h = __float2bfloat16(v);
        float r = v - __bfloat162float(h);
        wt[en.off + (size_t)n * en.K + k] = h;
        wt[en.off + (size_t)128 * en.K + (size_t)n * en.K + k] = __float2bfloat16(r);
    }
}

// ---------------------------------------------------------------------------
// 128x128 tile, 256 threads, KC=32 chunks, 3-stage cp.async pipeline.
// Modes:
//  normal: write Ch/Cl (bf16 planes) or Cf (fp32).
//  chain-F (cCf != null): [optional normal write], then tile -> smem ->
//    @wt[cW] -> (+cB) fp32 to cCf.
//  chain-head (hout != null): tile -> smem -> @wt[cW] (+cB +cGA*) relu ->
//    smem -> @wt[fhW1] (+fhB1) relu dot hw2 -> hout.
// ---------------------------------------------------------------------------
__global__ __launch_bounds__(256, 2) void mma_gemm(
    int M,
    const float* __restrict__ A0f, const __nv_bfloat16* __restrict__ A0h,
    const __nv_bfloat16* __restrict__ A0l,
    const int* __restrict__ I0, const float* __restrict__ S0, int w0, int K0,
    const float* __restrict__ A1f, const __nv_bfloat16* __restrict__ A1h,
    const __nv_bfloat16* __restrict__ A1l,
    const int* __restrict__ I1, int w1, int K1,
    const float* __restrict__ A2f, const __nv_bfloat16* __restrict__ A2h,
    const __nv_bfloat16* __restrict__ A2l, int w2, int K2,
    const __nv_bfloat16* __restrict__ wt,
    const float* __restrict__ bias,
    __nv_bfloat16* __restrict__ Ch, __nv_bfloat16* __restrict__ Cl, int doRelu,
    float* __restrict__ Cf,
    const float* __restrict__ GA0, const int* __restrict__ GAI0,
    const float* __restrict__ GA1, const int* __restrict__ GAI1,
    int cW, const float* __restrict__ cB,
    const float* __restrict__ cGA0, const int* __restrict__ cGAI0,
    const float* __restrict__ cGA1, const int* __restrict__ cGAI1,
    float* __restrict__ cCf,
    int fhW1, const float* __restrict__ fhB1,
    const float* __restrict__ hw2, const float* __restrict__ hb2,
    float* __restrict__ hout) {
    extern __shared__ __align__(16) char smem_raw[];
    const uint32_t sb = smem_u32(smem_raw);
    float* partial = (float*)(smem_raw + NSTAGE * STAGE_B);

    const int tid = threadIdx.x, warp = tid >> 5, lane = tid & 31;
    const int rowG = warp >> 2, colG = warp & 3;
    const int row0 = blockIdx.x * 128;
    const bool chainHead = (hout != nullptr);
    const bool chainF = (cCf != nullptr);
    if (chainHead && tid < 128) partial[tid] = 0.0f;

    const float* srcF[3] = {A0f, A1f, A2f};
    const __nv_bfloat16* srcH[3] = {A0h, A1h, A2h};
    const __nv_bfloat16* srcL[3] = {A0l, A1l, A2l};
    const int Ks[3] = {K0, K1, K2};
    const int wof[3] = {w0, w1, w2};
    const int nch0 = K0 >> 5, nch1 = K1 >> 5, nch2 = K2 >> 5;
    const int ntot = nch0 + nch1 + nch2;

    const int lrow = tid >> 1, lsel = tid & 1;
    int gi[3];
    float sc_[3];
    {
        int r = row0 + lrow;
        if (r >= M) r = M - 1;
        int g0 = r, g1 = r;
        if (I0) g0 = __ldg(&I0[r]);
        if (I1) g1 = __ldg(&I1[r]);
        gi[0] = g0; gi[1] = g1; gi[2] = r;
        sc_[0] = S0 ? __ldg(&S0[g0]) : 1.0f;
        sc_[1] = 1.0f; sc_[2] = 1.0f;
    }

    float acc[4][4][4];
#pragma unroll
    for (int mt = 0; mt < 4; mt++)
#pragma unroll
        for (int nt = 0; nt < 4; nt++)
#pragma unroll
            for (int j = 0; j < 4; j++) acc[mt][nt][j] = 0.0f;

    auto issue = [&](int c, int stage) {
        int s, kb;
        if (c < nch0) { s = 0; kb = c << 5; }
        else if (c < nch0 + nch1) { s = 1; kb = (c - nch0) << 5; }
        else { s = 2; kb = (c - nch0 - nch1) << 5; }
        const uint32_t base = sb + stage * STAGE_B;
        {
            const __nv_bfloat16* bsrc = wt + wof[s] +
                (lsel ? (size_t)128 * Ks[s] : 0) + (size_t)lrow * Ks[s] + kb;
            const uint32_t bpl = base + (lsel ? 3 : 2) * PLANE_B;
#pragma unroll
            for (int j = 0; j < 4; j++) cp16(bpl + swz(lrow, j), bsrc + j * 8);
        }
        if (srcF[s] == nullptr) {
            const __nv_bfloat16* asrc =
                (lsel ? srcL[s] : srcH[s]) + (size_t)gi[s] * 128 + kb;
            const uint32_t apl = base + (lsel ? PLANE_B : 0);
#pragma unroll
            for (int j = 0; j < 4; j++) cp16(apl + swz(lrow, j), asrc + j * 8);
        } else {
            const float sc = sc_[s];
            const float* ap = srcF[s] + (size_t)gi[s] * Ks[s] + kb + lsel * 16;
            float4 x = *(const float4*)(ap);
            float4 y = *(const float4*)(ap + 4);
            float4 z = *(const float4*)(ap + 8);
            float4 u = *(const float4*)(ap + 12);
            float v[16] = {x.x, x.y, x.z, x.w, y.x, y.y, y.z, y.w,
                           z.x, z.y, z.z, z.w, u.x, u.y, u.z, u.w};
            uint32_t hw_[8], lw_[8];
#pragma unroll
            for (int j = 0; j < 8; j++) {
                float a0 = v[2 * j] * sc, a1 = v[2 * j + 1] * sc;
                __nv_bfloat16 h0 = __float2bfloat16(a0);
                __nv_bfloat16 h1 = __float2bfloat16(a1);
                __nv_bfloat162 hp; hp.x = h0; hp.y = h1;
                __nv_bfloat162 lp;
                lp.x = __float2bfloat16(a0 - __bfloat162float(h0));
                lp.y = __float2bfloat16(a1 - __bfloat162float(h1));
                hw_[j] = *reinterpret_cast<uint32_t*>(&hp);
                lw_[j] = *reinterpret_cast<uint32_t*>(&lp);
            }
            const uint32_t aH0 = base + swz(lrow, lsel * 2);
            const uint32_t aH1 = base + swz(lrow, lsel * 2 + 1);
            asm volatile("st.shared.v4.b32 [%0], {%1,%2,%3,%4};"
                         :: "r"(aH0), "r"(hw_[0]), "r"(hw_[1]), "r"(hw_[2]), "r"(hw_[3]) : "memory");
            asm volatile("st.shared.v4.b32 [%0], {%1,%2,%3,%4};"
                         :: "r"(aH1), "r"(hw_[4]), "r"(hw_[5]), "r"(hw_[6]), "r"(hw_[7]) : "memory");
            asm volatile("st.shared.v4.b32 [%0], {%1,%2,%3,%4};"
                         :: "r"(aH0 + PLANE_B), "r"(lw_[0]), "r"(lw_[1]), "r"(lw_[2]), "r"(lw_[3]) : "memory");
            asm volatile("st.shared.v4.b32 [%0], {%1,%2,%3,%4};"
                         :: "r"(aH1 + PLANE_B), "r"(lw_[4]), "r"(lw_[5]), "r"(lw_[6]), "r"(lw_[7]) : "memory");
        }
    };

    const int laneR = lane & 15;
    const int xorA = (laneR >> 1) & 3;
    const int cA0  = lane >> 4;
    const int n_off = (((lane >> 4) & 1) * 8) + (lane & 7);
    const int xorB = (n_off >> 1) & 3;
    const int cB0  = (lane >> 3) & 1;

    auto computeAt = [&](uint32_t aHiB, uint32_t aLoB, uint32_t bHiB, uint32_t bLoB) {
        const uint32_t aRow = aHiB + (uint32_t)(rowG * 64 + laneR) * 64;
        const uint32_t aRowL = aLoB + (uint32_t)(rowG * 64 + laneR) * 64;
        const uint32_t bRow = bHiB + (uint32_t)(colG * 32 + n_off) * 64;
        const uint32_t bRowL = bLoB + (uint32_t)(colG * 32 + n_off) * 64;
#pragma unroll
        for (int ks = 0; ks < 2; ks++) {
            const uint32_t aC = (uint32_t)((cA0 + 2 * ks) ^ xorA) * 16;
            const uint32_t bC = (uint32_t)((cB0 + 2 * ks) ^ xorB) * 16;
            uint32_t bh[4][2], bl[4][2];
#pragma unroll
            for (int np = 0; np < 2; np++) {
                uint32_t r4[4];
                ldsm_x4(r4, bRow + np * (16 * 64) + bC);
                bh[np * 2][0] = r4[0]; bh[np * 2][1] = r4[1];
                bh[np * 2 + 1][0] = r4[2]; bh[np * 2 + 1][1] = r4[3];
                ldsm_x4(r4, bRowL + np * (16 * 64) + bC);
                bl[np * 2][0] = r4[0]; bl[np * 2][1] = r4[1];
                bl[np * 2 + 1][0] = r4[2]; bl[np * 2 + 1][1] = r4[3];
            }
#pragma unroll
            for (int mt = 0; mt < 4; mt++) {
                uint32_t ah[4], al[4];
                ldsm_x4(ah, aRow + mt * (16 * 64) + aC);
                ldsm_x4(al, aRowL + mt * (16 * 64) + aC);
#pragma unroll
                for (int nt = 0; nt < 4; nt++) {
                    mma_bf16(acc[mt][nt], ah, bh[nt]);
                    mma_bf16(acc[mt][nt], ah, bl[nt]);
                    mma_bf16(acc[mt][nt], al, bh[nt]);
                }
            }
        }
    };

    issue(0, 0);
    CP_COMMIT();
    if (ntot > 1) issue(1, 1);
    CP_COMMIT();
    int st_ = 0;
#pragma unroll 1
    for (int c = 0; c < ntot; c++) {
        CP_WAIT1();
        __syncthreads();
        if (c + 2 < ntot) {
            int s2 = st_ + 2; if (s2 >= NSTAGE) s2 -= NSTAGE;
            issue(c + 2, s2);
        }
        CP_COMMIT();
        const uint32_t base = sb + st_ * STAGE_B;
        computeAt(base, base + PLANE_B, base + 2 * PLANE_B, base + 3 * PLANE_B);
        if (++st_ == NSTAGE) st_ = 0;
    }

    const int rIn = lane >> 2;
    const int cIn = (lane & 3) * 2;

    // ---- normal DRAM write (also used pre-chain for encoders) ----
    if (Ch != nullptr || Cf != nullptr) {
#pragma unroll
        for (int mt = 0; mt < 4; mt++) {
            const int r0 = row0 + rowG * 64 + mt * 16 + rIn;
            const int r1 = r0 + 8;
            const bool v0r = r0 < M, v1r = r1 < M;
            const float *g00 = nullptr, *g01 = nullptr, *g10 = nullptr, *g11 = nullptr;
            if (GA0) {
                if (v0r) g00 = GA0 + (size_t)__ldg(&GAI0[r0]) * H_;
                if (v1r) g01 = GA0 + (size_t)__ldg(&GAI0[r1]) * H_;
            }
            if (GA1) {
                if (v0r) g10 = GA1 + (size_t)__ldg(&GAI1[r0]) * H_;
                if (v1r) g11 = GA1 + (size_t)__ldg(&GAI1[r1]) * H_;
            }
#pragma unroll
            for (int nt = 0; nt < 4; nt++) {
                const int col = colG * 32 + nt * 8 + cIn;
                const float b0 = __ldg(&bias[col]), b1 = __ldg(&bias[col + 1]);
                float o00 = acc[mt][nt][0] + b0, o01 = acc[mt][nt][1] + b1;
                float o10 = acc[mt][nt][2] + b0, o11 = acc[mt][nt][3] + b1;
                if (g00) { float2 g = *(const float2*)(g00 + col); o00 += g.x; o01 += g.y; }
                if (g10) { float2 g = *(const float2*)(g10 + col); o00 += g.x; o01 += g.y; }
                if (g01) { float2 g = *(const float2*)(g01 + col); o10 += g.x; o11 += g.y; }
                if (g11) { float2 g = *(const float2*)(g11 + col); o10 += g.x; o11 += g.y; }
                if (doRelu) {
                    o00 = fmaxf(o00, 0.f); o01 = fmaxf(o01, 0.f);
                    o10 = fmaxf(o10, 0.f); o11 = fmaxf(o11, 0.f);
                }
                if (Cf) {
                    if (v0r) *(float2*)(Cf + (size_t)r0 * H_ + col) = make_float2(o00, o01);
                    if (v1r) *(float2*)(Cf + (size_t)r1 * H_ + col) = make_float2(o10, o11);
                } else {
                    if (v0r) {
                        __nv_bfloat162 hp, lp;
                        hp.x = __float2bfloat16(o00); hp.y = __float2bfloat16(o01);
                        lp.x = __float2bfloat16(o00 - __bfloat162float(hp.x));
                        lp.y = __float2bfloat16(o01 - __bfloat162float(hp.y));
                        *(__nv_bfloat162*)(Ch + (size_t)r0 * H_ + col) = hp;
                        *(__nv_bfloat162*)(Cl + (size_t)r0 * H_ + col) = lp;
                    }
                    if (v1r) {
                        __nv_bfloat162 hp, lp;
                        hp.x = __float2bfloat16(o10); hp.y = __float2bfloat16(o11);
                        lp.x = __float2bfloat16(o10 - __bfloat162float(hp.x));
                        lp.y = __float2bfloat16(o11 - __bfloat162float(hp.y));
                        *(__nv_bfloat162*)(Ch + (size_t)r1 * H_ + col) = hp;
                        *(__nv_bfloat162*)(Cl + (size_t)r1 * H_ + col) = lp;
                    }
                }
            }
        }
    }
    if (!chainHead && !chainF) return;

    // ---- store tile (+bias+gathers, optional relu) into smem planes 0-7 ----
    auto storeTileSmem = [&](const float* bs,
                             const float* ga0, const int* gai0,
                             const float* ga1, const int* gai1, int rl) {
#pragma unroll
        for (int mt = 0; mt < 4; mt++) {
            const int r0 = row0 + rowG * 64 + mt * 16 + rIn;
            const int r1 = r0 + 8;
            int q0 = (r0 < M) ? r0 : M - 1, q1 = (r1 < M) ? r1 : M - 1;
            const float *g00 = nullptr, *g01 = nullptr, *g10 = nullptr, *g11 = nullptr;
            if (ga0) {
                g00 = ga0 + (size_t)__ldg(&gai0[q0]) * H_;
                g01 = ga0 + (size_t)__ldg(&gai0[q1]) * H_;
            }
            if (ga1) {
                g10 = ga1 + (size_t)__ldg(&gai1[q0]) * H_;
                g11 = ga1 + (size_t)__ldg(&gai1[q1]) * H_;
            }
#pragma unroll
            for (int nt = 0; nt < 4; nt++) {
                const int col = colG * 32 + nt * 8 + cIn;
                const float b0 = __ldg(&bs[col]), b1 = __ldg(&bs[col + 1]);
                float o00 = acc[mt][nt][0] + b0, o01 = acc[mt][nt][1] + b1;
                float o10 = acc[mt][nt][2] + b0, o11 = acc[mt][nt][3] + b1;
                if (g00) { float2 g = *(const float2*)(g00 + col); o00 += g.x; o01 += g.y; }
                if (g10) { float2 g = *(const float2*)(g10 + col); o00 += g.x; o01 += g.y; }
                if (g01) { float2 g = *(const float2*)(g01 + col); o10 += g.x; o11 += g.y; }
                if (g11) { float2 g = *(const float2*)(g11 + col); o10 += g.x; o11 += g.y; }
                if (rl) {
                    o00 = fmaxf(o00, 0.f); o01 = fmaxf(o01, 0.f);
                    o10 = fmaxf(o10, 0.f); o11 = fmaxf(o11, 0.f);
                }
                const int la0 = rowG * 64 + mt * 16 + rIn;
                const int la1 = la0 + 8;
                const uint32_t pHi = sb + (uint32_t)colG * PLANE_B;
                const uint32_t pLo = pHi + 4u * PLANE_B;
                __nv_bfloat162 hp, lp;
                hp.x = __float2bfloat16(o00); hp.y = __float2bfloat16(o01);
                lp.x = __float2bfloat16(o00 - __bfloat162float(hp.x));
                lp.y = __float2bfloat16(o01 - __bfloat162float(hp.y));
                uint32_t a0 = swz(la0, nt) + (uint32_t)cIn * 2;
                asm volatile("st.shared.b32 [%0], %1;" :: "r"(pHi + a0), "r"(*(uint32_t*)&hp) : "memory");
                asm volatile("st.shared.b32 [%0], %1;" :: "r"(pLo + a0), "r"(*(uint32_t*)&lp) : "memory");
                hp.x = __float2bfloat16(o10); hp.y = __float2bfloat16(o11);
                lp.x = __float2bfloat16(o10 - __bfloat162float(hp.x));
                lp.y = __float2bfloat16(o11 - __bfloat162float(hp.y));
                uint32_t a1 = swz(la1, nt) + (uint32_t)cIn * 2;
                asm volatile("st.shared.b32 [%0], %1;" :: "r"(pHi + a1), "r"(*(uint32_t*)&hp) : "memory");
                asm volatile("st.shared.b32 [%0], %1;" :: "r"(pLo + a1), "r"(*(uint32_t*)&lp) : "memory");
            }
        }
    };

    auto issueChB = [&](int woff, int j) {
        const __nv_bfloat16* bsrc = wt + woff +
            (lsel ? (size_t)128 * 128 : 0) + (size_t)lrow * 128 + j * 32;
        const uint32_t bpl = sb + (uint32_t)(8 + (j & 1) * 2 + lsel) * PLANE_B;
#pragma unroll
        for (int jj = 0; jj < 4; jj++) cp16(bpl + swz(lrow, jj), bsrc + jj * 8);
    };
    auto chainCompute = [&](int woff) {
#pragma unroll
        for (int mt = 0; mt < 4; mt++)
#pragma unroll
            for (int nt = 0; nt < 4; nt++)
#pragma unroll
                for (int j = 0; j < 4; j++) acc[mt][nt][j] = 0.0f;
        issueChB(woff, 0); CP_COMMIT();
        issueChB(woff, 1); CP_COMMIT();
        CP_WAIT1();
        __syncthreads();
#pragma unroll 1
        for (int j = 0; j < 4; j++) {
            if (j > 0) {
                __syncthreads();
                if (j + 1 < 4) { issueChB(woff, j + 1); CP_COMMIT(); CP_WAIT1(); }
                else CP_WAIT0();
                __syncthreads();
            }
            const uint32_t aHi = sb + (uint32_t)j * PLANE_B;
            const uint32_t bHi = sb + (uint32_t)(8 + (j & 1) * 2) * PLANE_B;
            computeAt(aHi, aHi + 4 * PLANE_B, bHi, bHi + PLANE_B);
        }
    };

    // ---- chain stage 1 ----
    __syncthreads();                                   // pipeline reads done
    storeTileSmem(bias, GA0, GAI0, GA1, GAI1, doRelu); // tile1
    chainCompute(cW);                                  // acc = tile1 @ wt[cW]

    if (chainF) {
        // write acc (+cB) as fp32 to cCf
#pragma unroll
        for (int mt = 0; mt < 4; mt++) {
            const int r0 = row0 + rowG * 64 + mt * 16 + rIn;
            const int r1 = r0 + 8;
#pragma unroll
            for (int nt = 0; nt < 4; nt++) {
                const int col = colG * 32 + nt * 8 + cIn;
                const float b0 = __ldg(&cB[col]), b1 = __ldg(&cB[col + 1]);
                if (r0 < M)
                    *(float2*)(cCf + (size_t)r0 * H_ + col) =
                        make_float2(acc[mt][nt][0] + b0, acc[mt][nt][1] + b1);
                if (r1 < M)
                    *(float2*)(cCf + (size_t)r1 * H_ + col) =
                        make_float2(acc[mt][nt][2] + b0, acc[mt][nt][3] + b1);
            }
        }
        return;
    }

    // ---- chain stage 2 + head ----
    __syncthreads();                                   // planes 0-7 consumed
    storeTileSmem(cB, cGA0, cGAI0, cGA1, cGAI1, 1);    // tile2
    chainCompute(fhW1);                                // acc = tile2 @ h1_W
    {
        float h0[4], h1[4];
#pragma unroll
        for (int mt = 0; mt < 4; mt++) { h0[mt] = 0.f; h1[mt] = 0.f; }
#pragma unroll
        for (int mt = 0; mt < 4; mt++)
#pragma unroll
            for (int nt = 0; nt < 4; nt++) {
                const int col = colG * 32 + nt * 8 + cIn;
                const float b0 = __ldg(&fhB1[col]), b1 = __ldg(&fhB1[col + 1]);
                const float w20 = __ldg(&hw2[col]), w21 = __ldg(&hw2[col + 1]);
                h0[mt] = fmaf(fmaxf(acc[mt][nt][0] + b0, 0.f), w20, h0[mt]);
                h0[mt] = fmaf(fmaxf(acc[mt][nt][1] + b1, 0.f), w21, h0[mt]);
                h1[mt] = fmaf(fmaxf(acc[mt][nt][2] + b0, 0.f), w20, h1[mt]);
                h1[mt] = fmaf(fmaxf(acc[mt][nt][3] + b1, 0.f), w21, h1[mt]);
            }
#pragma unroll
        for (int mt = 0; mt < 4; mt++) {
            h0[mt] += __shfl_xor_sync(0xffffffffu, h0[mt], 1);
            h0[mt] += __shfl_xor_sync(0xffffffffu, h0[mt], 2);
            h1[mt] += __shfl_xor_sync(0xffffffffu, h1[mt], 1);
            h1[mt] += __shfl_xor_sync(0xffffffffu, h1[mt], 2);
        }
        __syncthreads();
        if ((lane & 3) == 0) {
#pragma unroll
            for (int mt = 0; mt < 4; mt++) {
                atomicAdd(&partial[rowG * 64 + mt * 16 + rIn], h0[mt]);
                atomicAdd(&partial[rowG * 64 + mt * 16 + rIn + 8], h1[mt]);
            }
        }
        __syncthreads();
        if (tid < 128) {
            const int r = row0 + tid;
            if (r < M) hout[r] = partial[tid] + __ldg(&hb2[0]);
        }
    }
}

// ---------------------------------------------------------------------------
extern "C" void kernel_launch(void* const* d_in, const int* in_sizes, int n_in,
                              void* d_out, int out_size) {
    const float* tx_x         = (const float*)d_in[0];
    const int*   e_card       = (const int*)d_in[3];
    const int*   e_merch      = (const int*)d_in[5];
    const float* card_emb     = (const float*)d_in[7];
    const float* merch_emb    = (const float*)d_in[8];
    const float* card_proj_W  = (const float*)d_in[9];
    const float* card_proj_b  = (const float*)d_in[10];
    const float* merch_proj_W = (const float*)d_in[11];
    const float* merch_proj_b = (const float*)d_in[12];
    const float* tx_W         = (const float*)d_in[13];
    const float* tx_b         = (const float*)d_in[14];
    const float* conv_Wl      = (const float*)d_in[15];
    const float* conv_bl      = (const float*)d_in[16];
    const float* conv_Wr      = (const float*)d_in[17];
    const float* h1_W         = (const float*)d_in[18];
    const float* h1_b         = (const float*)d_in[19];
    const float* h2_W         = (const float*)d_in[20];
    const float* h2_b         = (const float*)d_in[21];
    float* out = (float*)d_out;

    __nv_bfloat16 *atx0, *acard0, *amerch0, *wt;
    float *pc0, *pm0, *pc1, *pm1, *aggc, *aggm, *invc, *invm, *bcomb, *zbias;
    cudaGetSymbolAddress((void**)&atx0,    g_atx0);
    cudaGetSymbolAddress((void**)&acard0,  g_acard0);
    cudaGetSymbolAddress((void**)&amerch0, g_amerch0);
    cudaGetSymbolAddress((void**)&pc0,   g_pcard0);
    cudaGetSymbolAddress((void**)&pm0,   g_pmerch0);
    cudaGetSymbolAddress((void**)&pc1,   g_pcard1);
    cudaGetSymbolAddress((void**)&pm1,   g_pmerch1);
    cudaGetSymbolAddress((void**)&aggc,  g_aggc);
    cudaGetSymbolAddress((void**)&aggm,  g_aggm);
    cudaGetSymbolAddress((void**)&invc,  g_invc);
    cudaGetSymbolAddress((void**)&invm,  g_invm);
    cudaGetSymbolAddress((void**)&bcomb, g_bcomb);
    cudaGetSymbolAddress((void**)&zbias, g_zbias);
    cudaGetSymbolAddress((void**)&wt,    g_wt);

    const size_t PTX = (size_t)N_TX * H_;
    const size_t PCD = (size_t)N_CARD * H_;
    const size_t PMR = (size_t)N_MERCH * H_;

    cudaFuncSetAttribute(mma_gemm, cudaFuncAttributeMaxDynamicSharedMemorySize, SMEM_BYTES);

    cudaStream_t st = 0;
    const int E = in_sizes[3];

    PrepArgs pa;
    {
        int i = 0;
        auto ent = [&](const float* s1, const float* s2, int K, int off) {
            pa.e[i].s1 = s1; pa.e[i].s2 = s2; pa.e[i].K = K; pa.e[i].off = off; i++;
        };
        const size_t WSZ = (size_t)H_ * H_;
        ent(tx_W,         nullptr, 128, OFF_TXW);
        ent(card_proj_W,  nullptr,  64, OFF_CPROJ);
        ent(merch_proj_W, nullptr,  64, OFF_MPROJ);
        ent(h1_W,         nullptr, 128, OFF_H1);
        for (int l = 0; l < 2; l++) {
            const float* Wl0 = conv_Wl + (size_t)(l * 4 + 0) * WSZ;
            const float* Wl1 = conv_Wl + (size_t)(l * 4 + 1) * WSZ;
            const float* Wl2 = conv_Wl + (size_t)(l * 4 + 2) * WSZ;
            const float* Wl3 = conv_Wl + (size_t)(l * 4 + 3) * WSZ;
            const float* Wr0 = conv_Wr + (size_t)(l * 4 + 0) * WSZ;
            const float* Wr1 = conv_Wr + (size_t)(l * 4 + 1) * WSZ;
            const float* Wr2 = conv_Wr + (size_t)(l * 4 + 2) * WSZ;
            const float* Wr3 = conv_Wr + (size_t)(l * 4 + 3) * WSZ;
            ent(Wl0, nullptr, 128, OFF_LAYER(l, 0));
            ent(Wl2, nullptr, 128, OFF_LAYER(l, 1));
            ent(Wr0, Wr2,     128, OFF_LAYER(l, 2));
            ent(Wl1, nullptr, 128, OFF_LAYER(l, 3));
            ent(Wr1, nullptr, 128, OFF_LAYER(l, 4));
            ent(Wl3, nullptr, 128, OFF_LAYER(l, 5));
            ent(Wr3, nullptr, 128, OFF_LAYER(l, 6));
        }
    }

    auto blocks = [](int m) { return (m + 127) / 128; };
    const __nv_bfloat16* NB = nullptr;
    const float* NF = nullptr;
    const int* NI = nullptr;
    float* NFo = nullptr;

    // launches 0..4 then encoder tx GEMM at index 5 (ncu -s 5 -c 1)
    prep_weights<<<18, 256, 0, st>>>(pa, wt);                                   // 0
    cudaMemsetAsync(invc, 0, N_CARD * sizeof(float), st);                       // 1
    cudaMemsetAsync(invm, 0, N_MERCH * sizeof(float), st);                      // 2
    cudaMemsetAsync(aggc, 0, PCD * sizeof(float), st);                          // 3
    cudaMemsetAsync(aggm, 0, PMR * sizeof(float), st);                          // 4
    mma_gemm<<<blocks(N_TX), 256, SMEM_BYTES, st>>>(N_TX,                       // 5 <- profiled
        tx_x, NB, NB, nullptr, nullptr, OFF_TXW, 128,
        nullptr, NB, NB, nullptr, 0, 0,
        nullptr, NB, NB, 0, 0,
        wt, tx_b, atx0, atx0 + PTX, 1, nullptr,
        NF, NI, NF, NI,
        0, nullptr, NF, NI, NF, NI, NFo,
        0, nullptr, nullptr, nullptr, nullptr);
    count_kernel<<<(E + 255) / 256, 256, 0, st>>>(e_card, e_merch, invc, invm, E);
    invert_kernel<<<(N_CARD + 255) / 256, 256, 0, st>>>(invc, N_CARD);
    invert_kernel<<<(N_MERCH + 255) / 256, 256, 0, st>>>(invm, N_MERCH);
    combine_bias<<<1, 256, 0, st>>>(conv_bl, bcomb);
    // card encoder + chained P0_card (no relu on encoder output)
    mma_gemm<<<blocks(N_CARD), 256, SMEM_BYTES, st>>>(N_CARD,
        card_emb, NB, NB, nullptr, nullptr, OFF_CPROJ, 64,
        nullptr, NB, NB, nullptr, 0, 0,
        nullptr, NB, NB, 0, 0,
        wt, card_proj_b, acard0, acard0 + PCD, 0, nullptr,
        NF, NI, NF, NI,
        OFF_LAYER(0, 0), zbias, NF, NI, NF, NI, pc0,
        0, nullptr, nullptr, nullptr, nullptr);
    // merch encoder + chained P0_merch
    mma_gemm<<<blocks(N_MERCH), 256, SMEM_BYTES, st>>>(N_MERCH,
        merch_emb, NB, NB, nullptr, nullptr, OFF_MPROJ, 64,
        nullptr, NB, NB, nullptr, 0, 0,
        nullptr, NB, NB, 0, 0,
        wt, merch_proj_b, amerch0, amerch0 + PMR, 0, nullptr,
        NF, NI, NF, NI,
        OFF_LAYER(0, 1), zbias, NF, NI, NF, NI, pm0,
        0, nullptr, nullptr, nullptr, nullptr);
    // scatter h_tx0 -> agg
    scatter_kernel<<<(N_EDGE * 32 + 255) / 256, 256, 0, st>>>(
        atx0, atx0 + PTX, e_card, e_merch, aggc, aggm);

    // layer-0 card update (relu) + chained P1_card; h_card1 never hits DRAM
    mma_gemm<<<blocks(N_CARD), 256, SMEM_BYTES, st>>>(N_CARD,
        aggc, NB, NB, nullptr, invc, OFF_LAYER(0, 3), 128,
        nullptr, acard0, acard0 + PCD, nullptr, OFF_LAYER(0, 4), 128,
        nullptr, NB, NB, 0, 0,
        wt, conv_bl + 1 * H_, nullptr, nullptr, 1, nullptr,
        NF, NI, NF, NI,
        OFF_LAYER(1, 0), zbias, NF, NI, NF, NI, pc1,
        0, nullptr, nullptr, nullptr, nullptr);
    // layer-0 merch update + chained P1_merch
    mma_gemm<<<blocks(N_MERCH), 256, SMEM_BYTES, st>>>(N_MERCH,
        aggm, NB, NB, nullptr, invm, OFF_LAYER(0, 5), 128,
        nullptr, amerch0, amerch0 + PMR, nullptr, OFF_LAYER(0, 6), 128,
        nullptr, NB, NB, 0, 0,
        wt, conv_bl + 3 * H_, nullptr, nullptr, 1, nullptr,
        NF, NI, NF, NI,
        OFF_LAYER(1, 1), zbias, NF, NI, NF, NI, pm1,
        0, nullptr, nullptr, nullptr, nullptr);

    // MEGA: layer-0 tx -> layer-1 tx -> head (unchanged from R13)
    mma_gemm<<<blocks(N_TX), 256, SMEM_BYTES, st>>>(N_TX,
        nullptr, atx0, atx0 + PTX, nullptr, nullptr, OFF_LAYER(0, 2), 128,
        nullptr, NB, NB, nullptr, 0, 0,
        nullptr, NB, NB, 0, 0,
        wt, bcomb, nullptr, nullptr, 1, nullptr,
        pc0, e_card, pm0, e_merch,
        OFF_LAYER(1, 2), bcomb + H_, pc1, e_card, pm1, e_merch, NFo,
        OFF_H1, h1_b, h2_W, h2_b, out);
}

// round 15
// speedup vs baseline: 1.8626x; 1.0582x over previous
#include <cuda_runtime.h>
#include <cuda_bf16.h>
#include <cstdint>
#include <cstddef>

// ---------------------------------------------------------------------------
// HeteroSAGE on GB300 — Round 15: small-kernel fusion + stream overlap
//  * count fused into scatter (q==0 thread); inversion inlined into S0 path
//  * side stream (event fork/join): combine_bias + card/merch encoders (+P0)
//    overlap enc_tx + scatter on the main stream
//  * GEMM core + chain modes unchanged from R14
// ---------------------------------------------------------------------------

namespace {
constexpr int H_      = 128;
constexpr int N_TX    = 200000;
constexpr int N_CARD  = 50000;
constexpr int N_MERCH = 10000;
constexpr int N_EDGE  = 200000;
constexpr int PLANE_B = 128 * 64;            // 8192 B
constexpr int STAGE_B = 4 * PLANE_B;         // 32768
constexpr int NSTAGE  = 3;
constexpr int SMEM_BYTES = NSTAGE * STAGE_B + 512;

constexpr int SZ128 = 2 * 128 * 128;
constexpr int SZ64  = 2 * 128 * 64;
constexpr int OFF_TXW   = 0;
constexpr int OFF_CPROJ = OFF_TXW + SZ128;
constexpr int OFF_MPROJ = OFF_CPROJ + SZ64;
constexpr int OFF_H1    = OFF_MPROJ + SZ64;
constexpr int OFF_L0    = OFF_H1 + SZ128;
constexpr int WT_TOTAL  = OFF_L0 + 14 * SZ128;
__host__ __device__ constexpr int OFF_LAYER(int l, int j) { return OFF_L0 + (l * 7 + j) * SZ128; }
}

// ---------------- scratch ----------------------------------------------------
__device__ __align__(16) __nv_bfloat16 g_atx0[2 * (size_t)N_TX * H_];
__device__ __align__(16) __nv_bfloat16 g_acard0[2 * (size_t)N_CARD * H_];
__device__ __align__(16) __nv_bfloat16 g_amerch0[2 * (size_t)N_MERCH * H_];
__device__ __align__(16) float g_pcard0[(size_t)N_CARD * H_];
__device__ __align__(16) float g_pmerch0[(size_t)N_MERCH * H_];
__device__ __align__(16) float g_pcard1[(size_t)N_CARD * H_];
__device__ __align__(16) float g_pmerch1[(size_t)N_MERCH * H_];
__device__ float g_aggc[(size_t)N_CARD * H_];
__device__ float g_aggm[(size_t)N_MERCH * H_];
__device__ float g_cntc[N_CARD];
__device__ float g_cntm[N_MERCH];
__device__ float g_bcomb[2 * H_];
__device__ float g_zbias[H_];
__device__ __align__(16) __nv_bfloat16 g_wt[WT_TOTAL];

// ---------------- PTX helpers ------------------------------------------------
__device__ __forceinline__ uint32_t smem_u32(const void* p) {
    uint32_t a;
    asm("{ .reg .u64 t; cvta.to.shared.u64 t, %1; cvt.u32.u64 %0, t; }" : "=r"(a) : "l"(p));
    return a;
}
__device__ __forceinline__ void ldsm_x4(uint32_t* r, uint32_t addr) {
    asm volatile("ldmatrix.sync.aligned.m8n8.x4.shared.b16 {%0,%1,%2,%3}, [%4];"
                 : "=r"(r[0]), "=r"(r[1]), "=r"(r[2]), "=r"(r[3]) : "r"(addr));
}
__device__ __forceinline__ void mma_bf16(float* c, const uint32_t* a, const uint32_t* b) {
    asm volatile(
        "mma.sync.aligned.m16n8k16.row.col.f32.bf16.bf16.f32 "
        "{%0,%1,%2,%3}, {%4,%5,%6,%7}, {%8,%9}, {%0,%1,%2,%3};"
        : "+f"(c[0]), "+f"(c[1]), "+f"(c[2]), "+f"(c[3])
        : "r"(a[0]), "r"(a[1]), "r"(a[2]), "r"(a[3]), "r"(b[0]), "r"(b[1]));
}
__device__ __forceinline__ void cp16(uint32_t dst, const void* src) {
    asm volatile("cp.async.cg.shared.global [%0], [%1], 16;" :: "r"(dst), "l"(src) : "memory");
}
#define CP_COMMIT()  asm volatile("cp.async.commit_group;" ::: "memory")
#define CP_WAIT1()   asm volatile("cp.async.wait_group 1;" ::: "memory")
#define CP_WAIT0()   asm volatile("cp.async.wait_group 0;" ::: "memory")

__device__ __forceinline__ uint32_t swz(int r, int c) {
    return (uint32_t)r * 64u + (uint32_t)(((c ^ (r >> 1)) & 3) * 16);
}

// ---------------- small kernels ----------------------------------------------
__global__ void combine_bias(const float* __restrict__ bl, float* __restrict__ bc) {
    int i = blockIdx.x * blockDim.x + threadIdx.x;
    if (i < 2 * H_) {
        int l = i >> 7, j = i & 127;
        bc[i] = bl[(l * 4 + 0) * H_ + j] + bl[(l * 4 + 2) * H_ + j];
    }
}

// scatter + fused degree count (q==0 thread counts the edge)
__global__ void scatter_kernel(const __nv_bfloat16* __restrict__ th,
                               const __nv_bfloat16* __restrict__ tl,
                               const int* __restrict__ ec, const int* __restrict__ em,
                               float* __restrict__ aggc, float* __restrict__ aggm,
                               float* __restrict__ cntc, float* __restrict__ cntm) {
    int idx = blockIdx.x * blockDim.x + threadIdx.x;
    if (idx >= N_EDGE * 32) return;
    int e = idx >> 5, q = idx & 31;
    int f = q * 4;
    const int dc = __ldg(&ec[e]), dm = __ldg(&em[e]);
    if (q == 0) {
        atomicAdd(&cntc[dc], 1.0f);
        atomicAdd(&cntm[dm], 1.0f);
    }
    const size_t base = (size_t)e * H_ + f;
    uint2 hv = *(const uint2*)(th + base);
    uint2 lv = *(const uint2*)(tl + base);
    __nv_bfloat162 h0 = *reinterpret_cast<__nv_bfloat162*>(&hv.x);
    __nv_bfloat162 h1 = *reinterpret_cast<__nv_bfloat162*>(&hv.y);
    __nv_bfloat162 l0 = *reinterpret_cast<__nv_bfloat162*>(&lv.x);
    __nv_bfloat162 l1 = *reinterpret_cast<__nv_bfloat162*>(&lv.y);
    float v0 = __bfloat162float(h0.x) + __bfloat162float(l0.x);
    float v1 = __bfloat162float(h0.y) + __bfloat162float(l0.y);
    float v2 = __bfloat162float(h1.x) + __bfloat162float(l1.x);
    float v3 = __bfloat162float(h1.y) + __bfloat162float(l1.y);
    float* pc = aggc + (size_t)dc * H_ + f;
    asm volatile("red.global.add.v4.f32 [%0], {%1,%2,%3,%4};"
                 :: "l"(pc), "f"(v0), "f"(v1), "f"(v2), "f"(v3) : "memory");
    float* pm = aggm + (size_t)dm * H_ + f;
    asm volatile("red.global.add.v4.f32 [%0], {%1,%2,%3,%4};"
                 :: "l"(pm), "f"(v0), "f"(v1), "f"(v2), "f"(v3) : "memory");
}

struct PrepEnt { const float* s1; const float* s2; int K; int off; };
struct PrepArgs { PrepEnt e[18]; };

__global__ void prep_weights(PrepArgs pa, __nv_bfloat16* __restrict__ wt) {
    PrepEnt en = pa.e[blockIdx.x];
    int total = 128 * en.K;
    for (int i = threadIdx.x; i < total; i += blockDim.x) {
        int n = i / en.K, k = i - n * en.K;
        float v = en.s1[(size_t)k * H_ + n];
        if (en.s2) v += en.s2[(size_t)k * H_ + n];
        __nv_bfloat16 h = __float2bfloat16(v);
        float r = v - __bfloat162float(h);
        wt[en.off + (size_t)n * en.K + k] = h;
        wt[en.off + (size_t)128 * en.K + (size_t)n * en.K + k] = __float2bfloat16(r);
    }
}

// ---------------------------------------------------------------------------
// 128x128 tile, 256 threads, KC=32 chunks, 3-stage cp.async pipeline.
// S0 now holds raw degree counts; the scale applied is 1/max(S0[g0],1).
// Modes identical to R14 (normal / chain-F / chain-head).
// ---------------------------------------------------------------------------
__global__ __launch_bounds__(256, 2) void mma_gemm(
    int M,
    const float* __restrict__ A0f, const __nv_bfloat16* __restrict__ A0h,
    const __nv_bfloat16* __restrict__ A0l,
    const int* __restrict__ I0, const float* __restrict__ S0, int w0, int K0,
    const float* __restrict__ A1f, const __nv_bfloat16* __restrict__ A1h,
    const __nv_bfloat16* __restrict__ A1l,
    const int* __restrict__ I1, int w1, int K1,
    const float* __restrict__ A2f, const __nv_bfloat16* __restrict__ A2h,
    const __nv_bfloat16* __restrict__ A2l, int w2, int K2,
    const __nv_bfloat16* __restrict__ wt,
    const float* __restrict__ bias,
    __nv_bfloat16* __restrict__ Ch, __nv_bfloat16* __restrict__ Cl, int doRelu,
    float* __restrict__ Cf,
    const float* __restrict__ GA0, const int* __restrict__ GAI0,
    const float* __restrict__ GA1, const int* __restrict__ GAI1,
    int cW, const float* __restrict__ cB,
    const float* __restrict__ cGA0, const int* __restrict__ cGAI0,
    const float* __restrict__ cGA1, const int* __restrict__ cGAI1,
    float* __restrict__ cCf,
    int fhW1, const float* __restrict__ fhB1,
    const float* __restrict__ hw2, const float* __restrict__ hb2,
    float* __restrict__ hout) {
    extern __shared__ __align__(16) char smem_raw[];
    const uint32_t sb = smem_u32(smem_raw);
    float* partial = (float*)(smem_raw + NSTAGE * STAGE_B);

    const int tid = threadIdx.x, warp = tid >> 5, lane = tid & 31;
    const int rowG = warp >> 2, colG = warp & 3;
    const int row0 = blockIdx.x * 128;
    const bool chainHead = (hout != nullptr);
    const bool chainF = (cCf != nullptr);
    if (chainHead && tid < 128) partial[tid] = 0.0f;

    const float* srcF[3] = {A0f, A1f, A2f};
    const __nv_bfloat16* srcH[3] = {A0h, A1h, A2h};
    const __nv_bfloat16* srcL[3] = {A0l, A1l, A2l};
    const int Ks[3] = {K0, K1, K2};
    const int wof[3] = {w0, w1, w2};
    const int nch0 = K0 >> 5, nch1 = K1 >> 5, nch2 = K2 >> 5;
    const int ntot = nch0 + nch1 + nch2;

    const int lrow = tid >> 1, lsel = tid & 1;
    int gi[3];
    float sc_[3];
    {
        int r = row0 + lrow;
        if (r >= M) r = M - 1;
        int g0 = r, g1 = r;
        if (I0) g0 = __ldg(&I0[r]);
        if (I1) g1 = __ldg(&I1[r]);
        gi[0] = g0; gi[1] = g1; gi[2] = r;
        sc_[0] = S0 ? (1.0f / fmaxf(__ldg(&S0[g0]), 1.0f)) : 1.0f;
        sc_[1] = 1.0f; sc_[2] = 1.0f;
    }

    float acc[4][4][4];
#pragma unroll
    for (int mt = 0; mt < 4; mt++)
#pragma unroll
        for (int nt = 0; nt < 4; nt++)
#pragma unroll
            for (int j = 0; j < 4; j++) acc[mt][nt][j] = 0.0f;

    auto issue = [&](int c, int stage) {
        int s, kb;
        if (c < nch0) { s = 0; kb = c << 5; }
        else if (c < nch0 + nch1) { s = 1; kb = (c - nch0) << 5; }
        else { s = 2; kb = (c - nch0 - nch1) << 5; }
        const uint32_t base = sb + stage * STAGE_B;
        {
            const __nv_bfloat16* bsrc = wt + wof[s] +
                (lsel ? (size_t)128 * Ks[s] : 0) + (size_t)lrow * Ks[s] + kb;
            const uint32_t bpl = base + (lsel ? 3 : 2) * PLANE_B;
#pragma unroll
            for (int j = 0; j < 4; j++) cp16(bpl + swz(lrow, j), bsrc + j * 8);
        }
        if (srcF[s] == nullptr) {
            const __nv_bfloat16* asrc =
                (lsel ? srcL[s] : srcH[s]) + (size_t)gi[s] * 128 + kb;
            const uint32_t apl = base + (lsel ? PLANE_B : 0);
#pragma unroll
            for (int j = 0; j < 4; j++) cp16(apl + swz(lrow, j), asrc + j * 8);
        } else {
            const float sc = sc_[s];
            const float* ap = srcF[s] + (size_t)gi[s] * Ks[s] + kb + lsel * 16;
            float4 x = *(const float4*)(ap);
            float4 y = *(const float4*)(ap + 4);
            float4 z = *(const float4*)(ap + 8);
            float4 u = *(const float4*)(ap + 12);
            float v[16] = {x.x, x.y, x.z, x.w, y.x, y.y, y.z, y.w,
                           z.x, z.y, z.z, z.w, u.x, u.y, u.z, u.w};
            uint32_t hw_[8], lw_[8];
#pragma unroll
            for (int j = 0; j < 8; j++) {
                float a0 = v[2 * j] * sc, a1 = v[2 * j + 1] * sc;
                __nv_bfloat16 h0 = __float2bfloat16(a0);
                __nv_bfloat16 h1 = __float2bfloat16(a1);
                __nv_bfloat162 hp; hp.x = h0; hp.y = h1;
                __nv_bfloat162 lp;
                lp.x = __float2bfloat16(a0 - __bfloat162float(h0));
                lp.y = __float2bfloat16(a1 - __bfloat162float(h1));
                hw_[j] = *reinterpret_cast<uint32_t*>(&hp);
                lw_[j] = *reinterpret_cast<uint32_t*>(&lp);
            }
            const uint32_t aH0 = base + swz(lrow, lsel * 2);
            const uint32_t aH1 = base + swz(lrow, lsel * 2 + 1);
            asm volatile("st.shared.v4.b32 [%0], {%1,%2,%3,%4};"
                         :: "r"(aH0), "r"(hw_[0]), "r"(hw_[1]), "r"(hw_[2]), "r"(hw_[3]) : "memory");
            asm volatile("st.shared.v4.b32 [%0], {%1,%2,%3,%4};"
                         :: "r"(aH1), "r"(hw_[4]), "r"(hw_[5]), "r"(hw_[6]), "r"(hw_[7]) : "memory");
            asm volatile("st.shared.v4.b32 [%0], {%1,%2,%3,%4};"
                         :: "r"(aH0 + PLANE_B), "r"(lw_[0]), "r"(lw_[1]), "r"(lw_[2]), "r"(lw_[3]) : "memory");
            asm volatile("st.shared.v4.b32 [%0], {%1,%2,%3,%4};"
                         :: "r"(aH1 + PLANE_B), "r"(lw_[4]), "r"(lw_[5]), "r"(lw_[6]), "r"(lw_[7]) : "memory");
        }
    };

    const int laneR = lane & 15;
    const int xorA = (laneR >> 1) & 3;
    const int cA0  = lane >> 4;
    const int n_off = (((lane >> 4) & 1) * 8) + (lane & 7);
    const int xorB = (n_off >> 1) & 3;
    const int cB0  = (lane >> 3) & 1;

    auto computeAt = [&](uint32_t aHiB, uint32_t aLoB, uint32_t bHiB, uint32_t bLoB) {
        const uint32_t aRow = aHiB + (uint32_t)(rowG * 64 + laneR) * 64;
        const uint32_t aRowL = aLoB + (uint32_t)(rowG * 64 + laneR) * 64;
        const uint32_t bRow = bHiB + (uint32_t)(colG * 32 + n_off) * 64;
        const uint32_t bRowL = bLoB + (uint32_t)(colG * 32 + n_off) * 64;
#pragma unroll
        for (int ks = 0; ks < 2; ks++) {
            const uint32_t aC = (uint32_t)((cA0 + 2 * ks) ^ xorA) * 16;
            const uint32_t bC = (uint32_t)((cB0 + 2 * ks) ^ xorB) * 16;
            uint32_t bh[4][2], bl[4][2];
#pragma unroll
            for (int np = 0; np < 2; np++) {
                uint32_t r4[4];
                ldsm_x4(r4, bRow + np * (16 * 64) + bC);
                bh[np * 2][0] = r4[0]; bh[np * 2][1] = r4[1];
                bh[np * 2 + 1][0] = r4[2]; bh[np * 2 + 1][1] = r4[3];
                ldsm_x4(r4, bRowL + np * (16 * 64) + bC);
                bl[np * 2][0] = r4[0]; bl[np * 2][1] = r4[1];
                bl[np * 2 + 1][0] = r4[2]; bl[np * 2 + 1][1] = r4[3];
            }
#pragma unroll
            for (int mt = 0; mt < 4; mt++) {
                uint32_t ah[4], al[4];
                ldsm_x4(ah, aRow + mt * (16 * 64) + aC);
                ldsm_x4(al, aRowL + mt * (16 * 64) + aC);
#pragma unroll
                for (int nt = 0; nt < 4; nt++) {
                    mma_bf16(acc[mt][nt], ah, bh[nt]);
                    mma_bf16(acc[mt][nt], ah, bl[nt]);
                    mma_bf16(acc[mt][nt], al, bh[nt]);
                }
            }
        }
    };

    issue(0, 0);
    CP_COMMIT();
    if (ntot > 1) issue(1, 1);
    CP_COMMIT();
    int st_ = 0;
#pragma unroll 1
    for (int c = 0; c < ntot; c++) {
        CP_WAIT1();
        __syncthreads();
        if (c + 2 < ntot) {
            int s2 = st_ + 2; if (s2 >= NSTAGE) s2 -= NSTAGE;
            issue(c + 2, s2);
        }
        CP_COMMIT();
        const uint32_t base = sb + st_ * STAGE_B;
        computeAt(base, base + PLANE_B, base + 2 * PLANE_B, base + 3 * PLANE_B);
        if (++st_ == NSTAGE) st_ = 0;
    }

    const int rIn = lane >> 2;
    const int cIn = (lane & 3) * 2;

    // ---- normal DRAM write (also used pre-chain for encoders) ----
    if (Ch != nullptr || Cf != nullptr) {
#pragma unroll
        for (int mt = 0; mt < 4; mt++) {
            const int r0 = row0 + rowG * 64 + mt * 16 + rIn;
            const int r1 = r0 + 8;
            const bool v0r = r0 < M, v1r = r1 < M;
            const float *g00 = nullptr, *g01 = nullptr, *g10 = nullptr, *g11 = nullptr;
            if (GA0) {
                if (v0r) g00 = GA0 + (size_t)__ldg(&GAI0[r0]) * H_;
                if (v1r) g01 = GA0 + (size_t)__ldg(&GAI0[r1]) * H_;
            }
            if (GA1) {
                if (v0r) g10 = GA1 + (size_t)__ldg(&GAI1[r0]) * H_;
                if (v1r) g11 = GA1 + (size_t)__ldg(&GAI1[r1]) * H_;
            }
#pragma unroll
            for (int nt = 0; nt < 4; nt++) {
                const int col = colG * 32 + nt * 8 + cIn;
                const float b0 = __ldg(&bias[col]), b1 = __ldg(&bias[col + 1]);
                float o00 = acc[mt][nt][0] + b0, o01 = acc[mt][nt][1] + b1;
                float o10 = acc[mt][nt][2] + b0, o11 = acc[mt][nt][3] + b1;
                if (g00) { float2 g = *(const float2*)(g00 + col); o00 += g.x; o01 += g.y; }
                if (g10) { float2 g = *(const float2*)(g10 + col); o00 += g.x; o01 += g.y; }
                if (g01) { float2 g = *(const float2*)(g01 + col); o10 += g.x; o11 += g.y; }
                if (g11) { float2 g = *(const float2*)(g11 + col); o10 += g.x; o11 += g.y; }
                if (doRelu) {
                    o00 = fmaxf(o00, 0.f); o01 = fmaxf(o01, 0.f);
                    o10 = fmaxf(o10, 0.f); o11 = fmaxf(o11, 0.f);
                }
                if (Cf) {
                    if (v0r) *(float2*)(Cf + (size_t)r0 * H_ + col) = make_float2(o00, o01);
                    if (v1r) *(float2*)(Cf + (size_t)r1 * H_ + col) = make_float2(o10, o11);
                } else {
                    if (v0r) {
                        __nv_bfloat162 hp, lp;
                        hp.x = __float2bfloat16(o00); hp.y = __float2bfloat16(o01);
                        lp.x = __float2bfloat16(o00 - __bfloat162float(hp.x));
                        lp.y = __float2bfloat16(o01 - __bfloat162float(hp.y));
                        *(__nv_bfloat162*)(Ch + (size_t)r0 * H_ + col) = hp;
                        *(__nv_bfloat162*)(Cl + (size_t)r0 * H_ + col) = lp;
                    }
                    if (v1r) {
                        __nv_bfloat162 hp, lp;
                        hp.x = __float2bfloat16(o10); hp.y = __float2bfloat16(o11);
                        lp.x = __float2bfloat16(o10 - __bfloat162float(hp.x));
                        lp.y = __float2bfloat16(o11 - __bfloat162float(hp.y));
                        *(__nv_bfloat162*)(Ch + (size_t)r1 * H_ + col) = hp;
                        *(__nv_bfloat162*)(Cl + (size_t)r1 * H_ + col) = lp;
                    }
                }
            }
        }
    }
    if (!chainHead && !chainF) return;

    auto storeTileSmem = [&](const float* bs,
                             const float* ga0, const int* gai0,
                             const float* ga1, const int* gai1, int rl) {
#pragma unroll
        for (int mt = 0; mt < 4; mt++) {
            const int r0 = row0 + rowG * 64 + mt * 16 + rIn;
            const int r1 = r0 + 8;
            int q0 = (r0 < M) ? r0 : M - 1, q1 = (r1 < M) ? r1 : M - 1;
            const float *g00 = nullptr, *g01 = nullptr, *g10 = nullptr, *g11 = nullptr;
            if (ga0) {
                g00 = ga0 + (size_t)__ldg(&gai0[q0]) * H_;
                g01 = ga0 + (size_t)__ldg(&gai0[q1]) * H_;
            }
            if (ga1) {
                g10 = ga1 + (size_t)__ldg(&gai1[q0]) * H_;
                g11 = ga1 + (size_t)__ldg(&gai1[q1]) * H_;
            }
#pragma unroll
            for (int nt = 0; nt < 4; nt++) {
                const int col = colG * 32 + nt * 8 + cIn;
                const float b0 = __ldg(&bs[col]), b1 = __ldg(&bs[col + 1]);
                float o00 = acc[mt][nt][0] + b0, o01 = acc[mt][nt][1] + b1;
                float o10 = acc[mt][nt][2] + b0, o11 = acc[mt][nt][3] + b1;
                if (g00) { float2 g = *(const float2*)(g00 + col); o00 += g.x; o01 += g.y; }
                if (g10) { float2 g = *(const float2*)(g10 + col); o00 += g.x; o01 += g.y; }
                if (g01) { float2 g = *(const float2*)(g01 + col); o10 += g.x; o11 += g.y; }
                if (g11) { float2 g = *(const float2*)(g11 + col); o10 += g.x; o11 += g.y; }
                if (rl) {
                    o00 = fmaxf(o00, 0.f); o01 = fmaxf(o01, 0.f);
                    o10 = fmaxf(o10, 0.f); o11 = fmaxf(o11, 0.f);
                }
                const int la0 = rowG * 64 + mt * 16 + rIn;
                const int la1 = la0 + 8;
                const uint32_t pHi = sb + (uint32_t)colG * PLANE_B;
                const uint32_t pLo = pHi + 4u * PLANE_B;
                __nv_bfloat162 hp, lp;
                hp.x = __float2bfloat16(o00); hp.y = __float2bfloat16(o01);
                lp.x = __float2bfloat16(o00 - __bfloat162float(hp.x));
                lp.y = __float2bfloat16(o01 - __bfloat162float(hp.y));
                uint32_t a0 = swz(la0, nt) + (uint32_t)cIn * 2;
                asm volatile("st.shared.b32 [%0], %1;" :: "r"(pHi + a0), "r"(*(uint32_t*)&hp) : "memory");
                asm volatile("st.shared.b32 [%0], %1;" :: "r"(pLo + a0), "r"(*(uint32_t*)&lp) : "memory");
                hp.x = __float2bfloat16(o10); hp.y = __float2bfloat16(o11);
                lp.x = __float2bfloat16(o10 - __bfloat162float(hp.x));
                lp.y = __float2bfloat16(o11 - __bfloat162float(hp.y));
                uint32_t a1 = swz(la1, nt) + (uint32_t)cIn * 2;
                asm volatile("st.shared.b32 [%0], %1;" :: "r"(pHi + a1), "r"(*(uint32_t*)&hp) : "memory");
                asm volatile("st.shared.b32 [%0], %1;" :: "r"(pLo + a1), "r"(*(uint32_t*)&lp) : "memory");
            }
        }
    };

    auto issueChB = [&](int woff, int j) {
        const __nv_bfloat16* bsrc = wt + woff +
            (lsel ? (size_t)128 * 128 : 0) + (size_t)lrow * 128 + j * 32;
        const uint32_t bpl = sb + (uint32_t)(8 + (j & 1) * 2 + lsel) * PLANE_B;
#pragma unroll
        for (int jj = 0; jj < 4; jj++) cp16(bpl + swz(lrow, jj), bsrc + jj * 8);
    };
    auto chainCompute = [&](int woff) {
#pragma unroll
        for (int mt = 0; mt < 4; mt++)
#pragma unroll
            for (int nt = 0; nt < 4; nt++)
#pragma unroll
                for (int j = 0; j < 4; j++) acc[mt][nt][j] = 0.0f;
        issueChB(woff, 0); CP_COMMIT();
        issueChB(woff, 1); CP_COMMIT();
        CP_WAIT1();
        __syncthreads();
#pragma unroll 1
        for (int j = 0; j < 4; j++) {
            if (j > 0) {
                __syncthreads();
                if (j + 1 < 4) { issueChB(woff, j + 1); CP_COMMIT(); CP_WAIT1(); }
                else CP_WAIT0();
                __syncthreads();
            }
            const uint32_t aHi = sb + (uint32_t)j * PLANE_B;
            const uint32_t bHi = sb + (uint32_t)(8 + (j & 1) * 2) * PLANE_B;
            computeAt(aHi, aHi + 4 * PLANE_B, bHi, bHi + PLANE_B);
        }
    };

    // ---- chain stage 1 ----
    __syncthreads();
    storeTileSmem(bias, GA0, GAI0, GA1, GAI1, doRelu);
    chainCompute(cW);

    if (chainF) {
#pragma unroll
        for (int mt = 0; mt < 4; mt++) {
            const int r0 = row0 + rowG * 64 + mt * 16 + rIn;
            const int r1 = r0 + 8;
#pragma unroll
            for (int nt = 0; nt < 4; nt++) {
                const int col = colG * 32 + nt * 8 + cIn;
                const float b0 = __ldg(&cB[col]), b1 = __ldg(&cB[col + 1]);
                if (r0 < M)
                    *(float2*)(cCf + (size_t)r0 * H_ + col) =
                        make_float2(acc[mt][nt][0] + b0, acc[mt][nt][1] + b1);
                if (r1 < M)
                    *(float2*)(cCf + (size_t)r1 * H_ + col) =
                        make_float2(acc[mt][nt][2] + b0, acc[mt][nt][3] + b1);
            }
        }
        return;
    }

    // ---- chain stage 2 + head ----
    __syncthreads();
    storeTileSmem(cB, cGA0, cGAI0, cGA1, cGAI1, 1);
    chainCompute(fhW1);
    {
        float h0[4], h1[4];
#pragma unroll
        for (int mt = 0; mt < 4; mt++) { h0[mt] = 0.f; h1[mt] = 0.f; }
#pragma unroll
        for (int mt = 0; mt < 4; mt++)
#pragma unroll
            for (int nt = 0; nt < 4; nt++) {
                const int col = colG * 32 + nt * 8 + cIn;
                const float b0 = __ldg(&fhB1[col]), b1 = __ldg(&fhB1[col + 1]);
                const float w20 = __ldg(&hw2[col]), w21 = __ldg(&hw2[col + 1]);
                h0[mt] = fmaf(fmaxf(acc[mt][nt][0] + b0, 0.f), w20, h0[mt]);
                h0[mt] = fmaf(fmaxf(acc[mt][nt][1] + b1, 0.f), w21, h0[mt]);
                h1[mt] = fmaf(fmaxf(acc[mt][nt][2] + b0, 0.f), w20, h1[mt]);
                h1[mt] = fmaf(fmaxf(acc[mt][nt][3] + b1, 0.f), w21, h1[mt]);
            }
#pragma unroll
        for (int mt = 0; mt < 4; mt++) {
            h0[mt] += __shfl_xor_sync(0xffffffffu, h0[mt], 1);
            h0[mt] += __shfl_xor_sync(0xffffffffu, h0[mt], 2);
            h1[mt] += __shfl_xor_sync(0xffffffffu, h1[mt], 1);
            h1[mt] += __shfl_xor_sync(0xffffffffu, h1[mt], 2);
        }
        __syncthreads();
        if ((lane & 3) == 0) {
#pragma unroll
            for (int mt = 0; mt < 4; mt++) {
                atomicAdd(&partial[rowG * 64 + mt * 16 + rIn], h0[mt]);
                atomicAdd(&partial[rowG * 64 + mt * 16 + rIn + 8], h1[mt]);
            }
        }
        __syncthreads();
        if (tid < 128) {
            const int r = row0 + tid;
            if (r < M) hout[r] = partial[tid] + __ldg(&hb2[0]);
        }
    }
}

// ---------------------------------------------------------------------------
extern "C" void kernel_launch(void* const* d_in, const int* in_sizes, int n_in,
                              void* d_out, int out_size) {
    const float* tx_x         = (const float*)d_in[0];
    const int*   e_card       = (const int*)d_in[3];
    const int*   e_merch      = (const int*)d_in[5];
    const float* card_emb     = (const float*)d_in[7];
    const float* merch_emb    = (const float*)d_in[8];
    const float* card_proj_W  = (const float*)d_in[9];
    const float* card_proj_b  = (const float*)d_in[10];
    const float* merch_proj_W = (const float*)d_in[11];
    const float* merch_proj_b = (const float*)d_in[12];
    const float* tx_W         = (const float*)d_in[13];
    const float* tx_b         = (const float*)d_in[14];
    const float* conv_Wl      = (const float*)d_in[15];
    const float* conv_bl      = (const float*)d_in[16];
    const float* conv_Wr      = (const float*)d_in[17];
    const float* h1_W         = (const float*)d_in[18];
    const float* h1_b         = (const float*)d_in[19];
    const float* h2_W         = (const float*)d_in[20];
    const float* h2_b         = (const float*)d_in[21];
    float* out = (float*)d_out;

    __nv_bfloat16 *atx0, *acard0, *amerch0, *wt;
    float *pc0, *pm0, *pc1, *pm1, *aggc, *aggm, *cntc, *cntm, *bcomb, *zbias;
    cudaGetSymbolAddress((void**)&atx0,    g_atx0);
    cudaGetSymbolAddress((void**)&acard0,  g_acard0);
    cudaGetSymbolAddress((void**)&amerch0, g_amerch0);
    cudaGetSymbolAddress((void**)&pc0,   g_pcard0);
    cudaGetSymbolAddress((void**)&pm0,   g_pmerch0);
    cudaGetSymbolAddress((void**)&pc1,   g_pcard1);
    cudaGetSymbolAddress((void**)&pm1,   g_pmerch1);
    cudaGetSymbolAddress((void**)&aggc,  g_aggc);
    cudaGetSymbolAddress((void**)&aggm,  g_aggm);
    cudaGetSymbolAddress((void**)&cntc,  g_cntc);
    cudaGetSymbolAddress((void**)&cntm,  g_cntm);
    cudaGetSymbolAddress((void**)&bcomb, g_bcomb);
    cudaGetSymbolAddress((void**)&zbias, g_zbias);
    cudaGetSymbolAddress((void**)&wt,    g_wt);

    const size_t PTX = (size_t)N_TX * H_;
    const size_t PCD = (size_t)N_CARD * H_;
    const size_t PMR = (size_t)N_MERCH * H_;

    cudaFuncSetAttribute(mma_gemm, cudaFuncAttributeMaxDynamicSharedMemorySize, SMEM_BYTES);

    cudaStream_t s0 = 0;
    const int E = in_sizes[3];

    PrepArgs pa;
    {
        int i = 0;
        auto ent = [&](const float* s1, const float* s2, int K, int off) {
            pa.e[i].s1 = s1; pa.e[i].s2 = s2; pa.e[i].K = K; pa.e[i].off = off; i++;
        };
        const size_t WSZ = (size_t)H_ * H_;
        ent(tx_W,         nullptr, 128, OFF_TXW);
        ent(card_proj_W,  nullptr,  64, OFF_CPROJ);
        ent(merch_proj_W, nullptr,  64, OFF_MPROJ);
        ent(h1_W,         nullptr, 128, OFF_H1);
        for (int l = 0; l < 2; l++) {
            const float* Wl0 = conv_Wl + (size_t)(l * 4 + 0) * WSZ;
            const float* Wl1 = conv_Wl + (size_t)(l * 4 + 1) * WSZ;
            const float* Wl2 = conv_Wl + (size_t)(l * 4 + 2) * WSZ;
            const float* Wl3 = conv_Wl + (size_t)(l * 4 + 3) * WSZ;
            const float* Wr0 = conv_Wr + (size_t)(l * 4 + 0) * WSZ;
            const float* Wr1 = conv_Wr + (size_t)(l * 4 + 1) * WSZ;
            const float* Wr2 = conv_Wr + (size_t)(l * 4 + 2) * WSZ;
            const float* Wr3 = conv_Wr + (size_t)(l * 4 + 3) * WSZ;
            ent(Wl0, nullptr, 128, OFF_LAYER(l, 0));
            ent(Wl2, nullptr, 128, OFF_LAYER(l, 1));
            ent(Wr0, Wr2,     128, OFF_LAYER(l, 2));
            ent(Wl1, nullptr, 128, OFF_LAYER(l, 3));
            ent(Wr1, nullptr, 128, OFF_LAYER(l, 4));
            ent(Wl3, nullptr, 128, OFF_LAYER(l, 5));
            ent(Wr3, nullptr, 128, OFF_LAYER(l, 6));
        }
    }

    auto blocks = [](int m) { return (m + 127) / 128; };
    const __nv_bfloat16* NB = nullptr;
    const float* NF = nullptr;
    const int* NI = nullptr;
    float* NFo = nullptr;

    // side stream + fork/join events (created per call; graph-capture legal)
    cudaStream_t sx;
    cudaStreamCreateWithFlags(&sx, cudaStreamNonBlocking);
    cudaEvent_t evFork, evJoin;
    cudaEventCreateWithFlags(&evFork, cudaEventDisableTiming);
    cudaEventCreateWithFlags(&evJoin, cudaEventDisableTiming);

    // ---- s0 prologue: weight prep + zero buffers ----
    prep_weights<<<18, 256, 0, s0>>>(pa, wt);
    cudaMemsetAsync(cntc, 0, N_CARD * sizeof(float), s0);
    cudaMemsetAsync(cntm, 0, N_MERCH * sizeof(float), s0);
    cudaMemsetAsync(aggc, 0, PCD * sizeof(float), s0);
    cudaMemsetAsync(aggm, 0, PMR * sizeof(float), s0);
    cudaEventRecord(evFork, s0);
    cudaStreamWaitEvent(sx, evFork, 0);

    // ---- s0: tx encoder -> scatter(+count) ----
    mma_gemm<<<blocks(N_TX), 256, SMEM_BYTES, s0>>>(N_TX,
        tx_x, NB, NB, nullptr, nullptr, OFF_TXW, 128,
        nullptr, NB, NB, nullptr, 0, 0,
        nullptr, NB, NB, 0, 0,
        wt, tx_b, atx0, atx0 + PTX, 1, nullptr,
        NF, NI, NF, NI,
        0, nullptr, NF, NI, NF, NI, NFo,
        0, nullptr, nullptr, nullptr, nullptr);
    scatter_kernel<<<(N_EDGE * 32 + 255) / 256, 256, 0, s0>>>(
        atx0, atx0 + PTX, e_card, e_merch, aggc, aggm, cntc, cntm);

    // ---- sx (overlapped): combine_bias, card/merch encoders (+P0 chains) ----
    combine_bias<<<1, 256, 0, sx>>>(conv_bl, bcomb);
    mma_gemm<<<blocks(N_CARD), 256, SMEM_BYTES, sx>>>(N_CARD,
        card_emb, NB, NB, nullptr, nullptr, OFF_CPROJ, 64,
        nullptr, NB, NB, nullptr, 0, 0,
        nullptr, NB, NB, 0, 0,
        wt, card_proj_b, acard0, acard0 + PCD, 0, nullptr,
        NF, NI, NF, NI,
        OFF_LAYER(0, 0), zbias, NF, NI, NF, NI, pc0,
        0, nullptr, nullptr, nullptr, nullptr);
    mma_gemm<<<blocks(N_MERCH), 256, SMEM_BYTES, sx>>>(N_MERCH,
        merch_emb, NB, NB, nullptr, nullptr, OFF_MPROJ, 64,
        nullptr, NB, NB, nullptr, 0, 0,
        nullptr, NB, NB, 0, 0,
        wt, merch_proj_b, amerch0, amerch0 + PMR, 0, nullptr,
        NF, NI, NF, NI,
        OFF_LAYER(0, 1), zbias, NF, NI, NF, NI, pm0,
        0, nullptr, nullptr, nullptr, nullptr);
    cudaEventRecord(evJoin, sx);
    cudaStreamWaitEvent(s0, evJoin, 0);

    // ---- s0: layer-0 node updates (+P1 chains); h1 never hits DRAM ----
    mma_gemm<<<blocks(N_CARD), 256, SMEM_BYTES, s0>>>(N_CARD,
        aggc, NB, NB, nullptr, cntc, OFF_LAYER(0, 3), 128,
        nullptr, acard0, acard0 + PCD, nullptr, OFF_LAYER(0, 4), 128,
        nullptr, NB, NB, 0, 0,
        wt, conv_bl + 1 * H_, nullptr, nullptr, 1, nullptr,
        NF, NI, NF, NI,
        OFF_LAYER(1, 0), zbias, NF, NI, NF, NI, pc1,
        0, nullptr, nullptr, nullptr, nullptr);
    mma_gemm<<<blocks(N_MERCH), 256, SMEM_BYTES, s0>>>(N_MERCH,
        aggm, NB, NB, nullptr, cntm, OFF_LAYER(0, 5), 128,
        nullptr, amerch0, amerch0 + PMR, nullptr, OFF_LAYER(0, 6), 128,
        nullptr, NB, NB, 0, 0,
        wt, conv_bl + 3 * H_, nullptr, nullptr, 1, nullptr,
        NF, NI, NF, NI,
        OFF_LAYER(1, 1), zbias, NF, NI, NF, NI, pm1,
        0, nullptr, nullptr, nullptr, nullptr);

    // ---- s0: MEGA (layer-0 tx -> layer-1 tx -> head) ----
    mma_gemm<<<blocks(N_TX), 256, SMEM_BYTES, s0>>>(N_TX,
        nullptr, atx0, atx0 + PTX, nullptr, nullptr, OFF_LAYER(0, 2), 128,
        nullptr, NB, NB, nullptr, 0, 0,
        nullptr, NB, NB, 0, 0,
        wt, bcomb, nullptr, nullptr, 1, nullptr,
        pc0, e_card, pm0, e_merch,
        OFF_LAYER(1, 2), bcomb + H_, pc1, e_card, pm1, e_merch, NFo,
        OFF_H1, h1_b, h2_W, h2_b, out);

    cudaEventDestroy(evFork);
    cudaEventDestroy(evJoin);
    cudaStreamDestroy(sx);
}

// round 17
// speedup vs baseline: 1.8778x; 1.0082x over previous
#include <cuda_runtime.h>
#include <cuda_bf16.h>
#include <cstdint>
#include <cstddef>

// ---------------------------------------------------------------------------
// HeteroSAGE on GB300 — Round 17 (= R16 with legal capture fork):
//  * side streams forked from s0 via event BEFORE first work (capture rule)
//  * enc_tx split in halves; scatter h0 (sy) overlaps enc h1 (s0)
//  * combine_bias folded into prep_weights; GEMM core unchanged
// ---------------------------------------------------------------------------

namespace {
constexpr int H_      = 128;
constexpr int N_TX    = 200000;
constexpr int N_CARD  = 50000;
constexpr int N_MERCH = 10000;
constexpr int N_EDGE  = 200000;
constexpr int HALF    = 100000;
constexpr int PLANE_B = 128 * 64;            // 8192 B
constexpr int STAGE_B = 4 * PLANE_B;         // 32768
constexpr int NSTAGE  = 3;
constexpr int SMEM_BYTES = NSTAGE * STAGE_B + 512;

constexpr int SZ128 = 2 * 128 * 128;
constexpr int SZ64  = 2 * 128 * 64;
constexpr int OFF_TXW   = 0;
constexpr int OFF_CPROJ = OFF_TXW + SZ128;
constexpr int OFF_MPROJ = OFF_CPROJ + SZ64;
constexpr int OFF_H1    = OFF_MPROJ + SZ64;
constexpr int OFF_L0    = OFF_H1 + SZ128;
constexpr int WT_TOTAL  = OFF_L0 + 14 * SZ128;
__host__ __device__ constexpr int OFF_LAYER(int l, int j) { return OFF_L0 + (l * 7 + j) * SZ128; }
}

// ---------------- scratch ----------------------------------------------------
__device__ __align__(16) __nv_bfloat16 g_atx0[2 * (size_t)N_TX * H_];
__device__ __align__(16) __nv_bfloat16 g_acard0[2 * (size_t)N_CARD * H_];
__device__ __align__(16) __nv_bfloat16 g_amerch0[2 * (size_t)N_MERCH * H_];
__device__ __align__(16) float g_pcard0[(size_t)N_CARD * H_];
__device__ __align__(16) float g_pmerch0[(size_t)N_MERCH * H_];
__device__ __align__(16) float g_pcard1[(size_t)N_CARD * H_];
__device__ __align__(16) float g_pmerch1[(size_t)N_MERCH * H_];
__device__ float g_aggc[(size_t)N_CARD * H_];
__device__ float g_aggm[(size_t)N_MERCH * H_];
__device__ float g_cntc[N_CARD];
__device__ float g_cntm[N_MERCH];
__device__ float g_bcomb[2 * H_];
__device__ float g_zbias[H_];
__device__ __align__(16) __nv_bfloat16 g_wt[WT_TOTAL];

// ---------------- PTX helpers ------------------------------------------------
__device__ __forceinline__ uint32_t smem_u32(const void* p) {
    uint32_t a;
    asm("{ .reg .u64 t; cvta.to.shared.u64 t, %1; cvt.u32.u64 %0, t; }" : "=r"(a) : "l"(p));
    return a;
}
__device__ __forceinline__ void ldsm_x4(uint32_t* r, uint32_t addr) {
    asm volatile("ldmatrix.sync.aligned.m8n8.x4.shared.b16 {%0,%1,%2,%3}, [%4];"
                 : "=r"(r[0]), "=r"(r[1]), "=r"(r[2]), "=r"(r[3]) : "r"(addr));
}
__device__ __forceinline__ void mma_bf16(float* c, const uint32_t* a, const uint32_t* b) {
    asm volatile(
        "mma.sync.aligned.m16n8k16.row.col.f32.bf16.bf16.f32 "
        "{%0,%1,%2,%3}, {%4,%5,%6,%7}, {%8,%9}, {%0,%1,%2,%3};"
        : "+f"(c[0]), "+f"(c[1]), "+f"(c[2]), "+f"(c[3])
        : "r"(a[0]), "r"(a[1]), "r"(a[2]), "r"(a[3]), "r"(b[0]), "r"(b[1]));
}
__device__ __forceinline__ void cp16(uint32_t dst, const void* src) {
    asm volatile("cp.async.cg.shared.global [%0], [%1], 16;" :: "r"(dst), "l"(src) : "memory");
}
#define CP_COMMIT()  asm volatile("cp.async.commit_group;" ::: "memory")
#define CP_WAIT1()   asm volatile("cp.async.wait_group 1;" ::: "memory")
#define CP_WAIT0()   asm volatile("cp.async.wait_group 0;" ::: "memory")

__device__ __forceinline__ uint32_t swz(int r, int c) {
    return (uint32_t)r * 64u + (uint32_t)(((c ^ (r >> 1)) & 3) * 16);
}

// ---------------- small kernels ----------------------------------------------
// zero agg/cnt buffers (replaces 4 memsets; capture-friendly on side stream)
__global__ void zero_buffers(float* __restrict__ aggc, float* __restrict__ aggm,
                             float* __restrict__ cntc, float* __restrict__ cntm) {
    int i = blockIdx.x * blockDim.x + threadIdx.x;
    int tc = N_CARD * H_, tm = N_MERCH * H_;
    if (i < tc) aggc[i] = 0.0f;
    if (i < tm) aggm[i] = 0.0f;
    if (i < N_CARD) cntc[i] = 0.0f;
    if (i < N_MERCH) cntm[i] = 0.0f;
}

// scatter + fused degree count over edge range [eoff, eoff+ecnt)
__global__ void scatter_kernel(const __nv_bfloat16* __restrict__ th,
                               const __nv_bfloat16* __restrict__ tl,
                               const int* __restrict__ ec, const int* __restrict__ em,
                               float* __restrict__ aggc, float* __restrict__ aggm,
                               float* __restrict__ cntc, float* __restrict__ cntm,
                               int eoff, int ecnt) {
    int idx = blockIdx.x * blockDim.x + threadIdx.x;
    if (idx >= ecnt * 32) return;
    int e = eoff + (idx >> 5), q = idx & 31;
    int f = q * 4;
    const int dc = __ldg(&ec[e]), dm = __ldg(&em[e]);
    if (q == 0) {
        atomicAdd(&cntc[dc], 1.0f);
        atomicAdd(&cntm[dm], 1.0f);
    }
    const size_t base = (size_t)e * H_ + f;
    uint2 hv = *(const uint2*)(th + base);
    uint2 lv = *(const uint2*)(tl + base);
    __nv_bfloat162 h0 = *reinterpret_cast<__nv_bfloat162*>(&hv.x);
    __nv_bfloat162 h1 = *reinterpret_cast<__nv_bfloat162*>(&hv.y);
    __nv_bfloat162 l0 = *reinterpret_cast<__nv_bfloat162*>(&lv.x);
    __nv_bfloat162 l1 = *reinterpret_cast<__nv_bfloat162*>(&lv.y);
    float v0 = __bfloat162float(h0.x) + __bfloat162float(l0.x);
    float v1 = __bfloat162float(h0.y) + __bfloat162float(l0.y);
    float v2 = __bfloat162float(h1.x) + __bfloat162float(l1.x);
    float v3 = __bfloat162float(h1.y) + __bfloat162float(l1.y);
    float* pc = aggc + (size_t)dc * H_ + f;
    asm volatile("red.global.add.v4.f32 [%0], {%1,%2,%3,%4};"
                 :: "l"(pc), "f"(v0), "f"(v1), "f"(v2), "f"(v3) : "memory");
    float* pm = aggm + (size_t)dm * H_ + f;
    asm volatile("red.global.add.v4.f32 [%0], {%1,%2,%3,%4};"
                 :: "l"(pm), "f"(v0), "f"(v1), "f"(v2), "f"(v3) : "memory");
}

struct PrepEnt { const float* s1; const float* s2; int K; int off; };
struct PrepArgs { PrepEnt e[18]; const float* bl; float* bc; };

__global__ void prep_weights(PrepArgs pa, __nv_bfloat16* __restrict__ wt) {
    if (blockIdx.x == 18) {   // fused combine_bias
        int i = threadIdx.x;
        if (i < 2 * H_) {
            int l = i >> 7, j = i & 127;
            pa.bc[i] = pa.bl[(l * 4 + 0) * H_ + j] + pa.bl[(l * 4 + 2) * H_ + j];
        }
        return;
    }
    PrepEnt en = pa.e[blockIdx.x];
    int total = 128 * en.K;
    for (int i = threadIdx.x; i < total; i += blockDim.x) {
        int n = i / en.K, k = i - n * en.K;
        float v = en.s1[(size_t)k * H_ + n];
        if (en.s2) v += en.s2[(size_t)k * H_ + n];
        __nv_bfloat16 h = __float2bfloat16(v);
        float r = v - __bfloat162float(h);
        wt[en.off + (size_t)n * en.K + k] = h;
        wt[en.off + (size_t)128 * en.K + (size_t)n * en.K + k] = __float2bfloat16(r);
    }
}

// ---------------------------------------------------------------------------
// 128x128 tile, 256 threads, KC=32 chunks, 3-stage cp.async pipeline.
// S0 holds raw degree counts; scale = 1/max(S0[g0],1).
// Modes: normal / chain-F (cCf) / chain-head (hout).
// ---------------------------------------------------------------------------
__global__ __launch_bounds__(256, 2) void mma_gemm(
    int M,
    const float* __restrict__ A0f, const __nv_bfloat16* __restrict__ A0h,
    const __nv_bfloat16* __restrict__ A0l,
    const int* __restrict__ I0, const float* __restrict__ S0, int w0, int K0,
    const float* __restrict__ A1f, const __nv_bfloat16* __restrict__ A1h,
    const __nv_bfloat16* __restrict__ A1l,
    const int* __restrict__ I1, int w1, int K1,
    const float* __restrict__ A2f, const __nv_bfloat16* __restrict__ A2h,
    const __nv_bfloat16* __restrict__ A2l, int w2, int K2,
    const __nv_bfloat16* __restrict__ wt,
    const float* __restrict__ bias,
    __nv_bfloat16* __restrict__ Ch, __nv_bfloat16* __restrict__ Cl, int doRelu,
    float* __restrict__ Cf,
    const float* __restrict__ GA0, const int* __restrict__ GAI0,
    const float* __restrict__ GA1, const int* __restrict__ GAI1,
    int cW, const float* __restrict__ cB,
    const float* __restrict__ cGA0, const int* __restrict__ cGAI0,
    const float* __restrict__ cGA1, const int* __restrict__ cGAI1,
    float* __restrict__ cCf,
    int fhW1, const float* __restrict__ fhB1,
    const float* __restrict__ hw2, const float* __restrict__ hb2,
    float* __restrict__ hout) {
    extern __shared__ __align__(16) char smem_raw[];
    const uint32_t sb = smem_u32(smem_raw);
    float* partial = (float*)(smem_raw + NSTAGE * STAGE_B);

    const int tid = threadIdx.x, warp = tid >> 5, lane = tid & 31;
    const int rowG = warp >> 2, colG = warp & 3;
    const int row0 = blockIdx.x * 128;
    const bool chainHead = (hout != nullptr);
    const bool chainF = (cCf != nullptr);
    if (chainHead && tid < 128) partial[tid] = 0.0f;

    const float* srcF[3] = {A0f, A1f, A2f};
    const __nv_bfloat16* srcH[3] = {A0h, A1h, A2h};
    const __nv_bfloat16* srcL[3] = {A0l, A1l, A2l};
    const int Ks[3] = {K0, K1, K2};
    const int wof[3] = {w0, w1, w2};
    const int nch0 = K0 >> 5, nch1 = K1 >> 5, nch2 = K2 >> 5;
    const int ntot = nch0 + nch1 + nch2;

    const int lrow = tid >> 1, lsel = tid & 1;
    int gi[3];
    float sc_[3];
    {
        int r = row0 + lrow;
        if (r >= M) r = M - 1;
        int g0 = r, g1 = r;
        if (I0) g0 = __ldg(&I0[r]);
        if (I1) g1 = __ldg(&I1[r]);
        gi[0] = g0; gi[1] = g1; gi[2] = r;
        sc_[0] = S0 ? (1.0f / fmaxf(__ldg(&S0[g0]), 1.0f)) : 1.0f;
        sc_[1] = 1.0f; sc_[2] = 1.0f;
    }

    float acc[4][4][4];
#pragma unroll
    for (int mt = 0; mt < 4; mt++)
#pragma unroll
        for (int nt = 0; nt < 4; nt++)
#pragma unroll
            for (int j = 0; j < 4; j++) acc[mt][nt][j] = 0.0f;

    auto issue = [&](int c, int stage) {
        int s, kb;
        if (c < nch0) { s = 0; kb = c << 5; }
        else if (c < nch0 + nch1) { s = 1; kb = (c - nch0) << 5; }
        else { s = 2; kb = (c - nch0 - nch1) << 5; }
        const uint32_t base = sb + stage * STAGE_B;
        {
            const __nv_bfloat16* bsrc = wt + wof[s] +
                (lsel ? (size_t)128 * Ks[s] : 0) + (size_t)lrow * Ks[s] + kb;
            const uint32_t bpl = base + (lsel ? 3 : 2) * PLANE_B;
#pragma unroll
            for (int j = 0; j < 4; j++) cp16(bpl + swz(lrow, j), bsrc + j * 8);
        }
        if (srcF[s] == nullptr) {
            const __nv_bfloat16* asrc =
                (lsel ? srcL[s] : srcH[s]) + (size_t)gi[s] * 128 + kb;
            const uint32_t apl = base + (lsel ? PLANE_B : 0);
#pragma unroll
            for (int j = 0; j < 4; j++) cp16(apl + swz(lrow, j), asrc + j * 8);
        } else {
            const float sc = sc_[s];
            const float* ap = srcF[s] + (size_t)gi[s] * Ks[s] + kb + lsel * 16;
            float4 x = *(const float4*)(ap);
            float4 y = *(const float4*)(ap + 4);
            float4 z = *(const float4*)(ap + 8);
            float4 u = *(const float4*)(ap + 12);
            float v[16] = {x.x, x.y, x.z, x.w, y.x, y.y, y.z, y.w,
                           z.x, z.y, z.z, z.w, u.x, u.y, u.z, u.w};
            uint32_t hw_[8], lw_[8];
#pragma unroll
            for (int j = 0; j < 8; j++) {
                float a0 = v[2 * j] * sc, a1 = v[2 * j + 1] * sc;
                __nv_bfloat16 h0 = __float2bfloat16(a0);
                __nv_bfloat16 h1 = __float2bfloat16(a1);
                __nv_bfloat162 hp; hp.x = h0; hp.y = h1;
                __nv_bfloat162 lp;
                lp.x = __float2bfloat16(a0 - __bfloat162float(h0));
                lp.y = __float2bfloat16(a1 - __bfloat162float(h1));
                hw_[j] = *reinterpret_cast<uint32_t*>(&hp);
                lw_[j] = *reinterpret_cast<uint32_t*>(&lp);
            }
            const uint32_t aH0 = base + swz(lrow, lsel * 2);
            const uint32_t aH1 = base + swz(lrow, lsel * 2 + 1);
            asm volatile("st.shared.v4.b32 [%0], {%1,%2,%3,%4};"
                         :: "r"(aH0), "r"(hw_[0]), "r"(hw_[1]), "r"(hw_[2]), "r"(hw_[3]) : "memory");
            asm volatile("st.shared.v4.b32 [%0], {%1,%2,%3,%4};"
                         :: "r"(aH1), "r"(hw_[4]), "r"(hw_[5]), "r"(hw_[6]), "r"(hw_[7]) : "memory");
            asm volatile("st.shared.v4.b32 [%0], {%1,%2,%3,%4};"
                         :: "r"(aH0 + PLANE_B), "r"(lw_[0]), "r"(lw_[1]), "r"(lw_[2]), "r"(lw_[3]) : "memory");
            asm volatile("st.shared.v4.b32 [%0], {%1,%2,%3,%4};"
                         :: "r"(aH1 + PLANE_B), "r"(lw_[4]), "r"(lw_[5]), "r"(lw_[6]), "r"(lw_[7]) : "memory");
        }
    };

    const int laneR = lane & 15;
    const int xorA = (laneR >> 1) & 3;
    const int cA0  = lane >> 4;
    const int n_off = (((lane >> 4) & 1) * 8) + (lane & 7);
    const int xorB = (n_off >> 1) & 3;
    const int cB0  = (lane >> 3) & 1;

    auto computeAt = [&](uint32_t aHiB, uint32_t aLoB, uint32_t bHiB, uint32_t bLoB) {
        const uint32_t aRow = aHiB + (uint32_t)(rowG * 64 + laneR) * 64;
        const uint32_t aRowL = aLoB + (uint32_t)(rowG * 64 + laneR) * 64;
        const uint32_t bRow = bHiB + (uint32_t)(colG * 32 + n_off) * 64;
        const uint32_t bRowL = bLoB + (uint32_t)(colG * 32 + n_off) * 64;
#pragma unroll
        for (int ks = 0; ks < 2; ks++) {
            const uint32_t aC = (uint32_t)((cA0 + 2 * ks) ^ xorA) * 16;
            const uint32_t bC = (uint32_t)((cB0 + 2 * ks) ^ xorB) * 16;
            uint32_t bh[4][2], bl[4][2];
#pragma unroll
            for (int np = 0; np < 2; np++) {
                uint32_t r4[4];
                ldsm_x4(r4, bRow + np * (16 * 64) + bC);
                bh[np * 2][0] = r4[0]; bh[np * 2][1] = r4[1];
                bh[np * 2 + 1][0] = r4[2]; bh[np * 2 + 1][1] = r4[3];
                ldsm_x4(r4, bRowL + np * (16 * 64) + bC);
                bl[np * 2][0] = r4[0]; bl[np * 2][1] = r4[1];
                bl[np * 2 + 1][0] = r4[2]; bl[np * 2 + 1][1] = r4[3];
            }
#pragma unroll
            for (int mt = 0; mt < 4; mt++) {
                uint32_t ah[4], al[4];
                ldsm_x4(ah, aRow + mt * (16 * 64) + aC);
                ldsm_x4(al, aRowL + mt * (16 * 64) + aC);
#pragma unroll
                for (int nt = 0; nt < 4; nt++) {
                    mma_bf16(acc[mt][nt], ah, bh[nt]);
                    mma_bf16(acc[mt][nt], ah, bl[nt]);
                    mma_bf16(acc[mt][nt], al, bh[nt]);
                }
            }
        }
    };

    issue(0, 0);
    CP_COMMIT();
    if (ntot > 1) issue(1, 1);
    CP_COMMIT();
    int st_ = 0;
#pragma unroll 1
    for (int c = 0; c < ntot; c++) {
        CP_WAIT1();
        __syncthreads();
        if (c + 2 < ntot) {
            int s2 = st_ + 2; if (s2 >= NSTAGE) s2 -= NSTAGE;
            issue(c + 2, s2);
        }
        CP_COMMIT();
        const uint32_t base = sb + st_ * STAGE_B;
        computeAt(base, base + PLANE_B, base + 2 * PLANE_B, base + 3 * PLANE_B);
        if (++st_ == NSTAGE) st_ = 0;
    }

    const int rIn = lane >> 2;
    const int cIn = (lane & 3) * 2;

    if (Ch != nullptr || Cf != nullptr) {
#pragma unroll
        for (int mt = 0; mt < 4; mt++) {
            const int r0 = row0 + rowG * 64 + mt * 16 + rIn;
            const int r1 = r0 + 8;
            const bool v0r = r0 < M, v1r = r1 < M;
            const float *g00 = nullptr, *g01 = nullptr, *g10 = nullptr, *g11 = nullptr;
            if (GA0) {
                if (v0r) g00 = GA0 + (size_t)__ldg(&GAI0[r0]) * H_;
                if (v1r) g01 = GA0 + (size_t)__ldg(&GAI0[r1]) * H_;
            }
            if (GA1) {
                if (v0r) g10 = GA1 + (size_t)__ldg(&GAI1[r0]) * H_;
                if (v1r) g11 = GA1 + (size_t)__ldg(&GAI1[r1]) * H_;
            }
#pragma unroll
            for (int nt = 0; nt < 4; nt++) {
                const int col = colG * 32 + nt * 8 + cIn;
                const float b0 = __ldg(&bias[col]), b1 = __ldg(&bias[col + 1]);
                float o00 = acc[mt][nt][0] + b0, o01 = acc[mt][nt][1] + b1;
                float o10 = acc[mt][nt][2] + b0, o11 = acc[mt][nt][3] + b1;
                if (g00) { float2 g = *(const float2*)(g00 + col); o00 += g.x; o01 += g.y; }
                if (g10) { float2 g = *(const float2*)(g10 + col); o00 += g.x; o01 += g.y; }
                if (g01) { float2 g = *(const float2*)(g01 + col); o10 += g.x; o11 += g.y; }
                if (g11) { float2 g = *(const float2*)(g11 + col); o10 += g.x; o11 += g.y; }
                if (doRelu) {
                    o00 = fmaxf(o00, 0.f); o01 = fmaxf(o01, 0.f);
                    o10 = fmaxf(o10, 0.f); o11 = fmaxf(o11, 0.f);
                }
                if (Cf) {
                    if (v0r) *(float2*)(Cf + (size_t)r0 * H_ + col) = make_float2(o00, o01);
                    if (v1r) *(float2*)(Cf + (size_t)r1 * H_ + col) = make_float2(o10, o11);
                } else {
                    if (v0r) {
                        __nv_bfloat162 hp, lp;
                        hp.x = __float2bfloat16(o00); hp.y = __float2bfloat16(o01);
                        lp.x = __float2bfloat16(o00 - __bfloat162float(hp.x));
                        lp.y = __float2bfloat16(o01 - __bfloat162float(hp.y));
                        *(__nv_bfloat162*)(Ch + (size_t)r0 * H_ + col) = hp;
                        *(__nv_bfloat162*)(Cl + (size_t)r0 * H_ + col) = lp;
                    }
                    if (v1r) {
                        __nv_bfloat162 hp, lp;
                        hp.x = __float2bfloat16(o10); hp.y = __float2bfloat16(o11);
                        lp.x = __float2bfloat16(o10 - __bfloat162float(hp.x));
                        lp.y = __float2bfloat16(o11 - __bfloat162float(hp.y));
                        *(__nv_bfloat162*)(Ch + (size_t)r1 * H_ + col) = hp;
                        *(__nv_bfloat162*)(Cl + (size_t)r1 * H_ + col) = lp;
                    }
                }
            }
        }
    }
    if (!chainHead && !chainF) return;

    auto storeTileSmem = [&](const float* bs,
                             const float* ga0, const int* gai0,
                             const float* ga1, const int* gai1, int rl) {
#pragma unroll
        for (int mt = 0; mt < 4; mt++) {
            const int r0 = row0 + rowG * 64 + mt * 16 + rIn;
            const int r1 = r0 + 8;
            int q0 = (r0 < M) ? r0 : M - 1, q1 = (r1 < M) ? r1 : M - 1;
            const float *g00 = nullptr, *g01 = nullptr, *g10 = nullptr, *g11 = nullptr;
            if (ga0) {
                g00 = ga0 + (size_t)__ldg(&gai0[q0]) * H_;
                g01 = ga0 + (size_t)__ldg(&gai0[q1]) * H_;
            }
            if (ga1) {
                g10 = ga1 + (size_t)__ldg(&gai1[q0]) * H_;
                g11 = ga1 + (size_t)__ldg(&gai1[q1]) * H_;
            }
#pragma unroll
            for (int nt = 0; nt < 4; nt++) {
                const int col = colG * 32 + nt * 8 + cIn;
                const float b0 = __ldg(&bs[col]), b1 = __ldg(&bs[col + 1]);
                float o00 = acc[mt][nt][0] + b0, o01 = acc[mt][nt][1] + b1;
                float o10 = acc[mt][nt][2] + b0, o11 = acc[mt][nt][3] + b1;
                if (g00) { float2 g = *(const float2*)(g00 + col); o00 += g.x; o01 += g.y; }
                if (g10) { float2 g = *(const float2*)(g10 + col); o00 += g.x; o01 += g.y; }
                if (g01) { float2 g = *(const float2*)(g01 + col); o10 += g.x; o11 += g.y; }
                if (g11) { float2 g = *(const float2*)(g11 + col); o10 += g.x; o11 += g.y; }
                if (rl) {
                    o00 = fmaxf(o00, 0.f); o01 = fmaxf(o01, 0.f);
                    o10 = fmaxf(o10, 0.f); o11 = fmaxf(o11, 0.f);
                }
                const int la0 = rowG * 64 + mt * 16 + rIn;
                const int la1 = la0 + 8;
                const uint32_t pHi = sb + (uint32_t)colG * PLANE_B;
                const uint32_t pLo = pHi + 4u * PLANE_B;
                __nv_bfloat162 hp, lp;
                hp.x = __float2bfloat16(o00); hp.y = __float2bfloat16(o01);
                lp.x = __float2bfloat16(o00 - __bfloat162float(hp.x));
                lp.y = __float2bfloat16(o01 - __bfloat162float(hp.y));
                uint32_t a0 = swz(la0, nt) + (uint32_t)cIn * 2;
                asm volatile("st.shared.b32 [%0], %1;" :: "r"(pHi + a0), "r"(*(uint32_t*)&hp) : "memory");
                asm volatile("st.shared.b32 [%0], %1;" :: "r"(pLo + a0), "r"(*(uint32_t*)&lp) : "memory");
                hp.x = __float2bfloat16(o10); hp.y = __float2bfloat16(o11);
                lp.x = __float2bfloat16(o10 - __bfloat162float(hp.x));
                lp.y = __float2bfloat16(o11 - __bfloat162float(hp.y));
                uint32_t a1 = swz(la1, nt) + (uint32_t)cIn * 2;
                asm volatile("st.shared.b32 [%0], %1;" :: "r"(pHi + a1), "r"(*(uint32_t*)&hp) : "memory");
                asm volatile("st.shared.b32 [%0], %1;" :: "r"(pLo + a1), "r"(*(uint32_t*)&lp) : "memory");
            }
        }
    };

    auto issueChB = [&](int woff, int j) {
        const __nv_bfloat16* bsrc = wt + woff +
            (lsel ? (size_t)128 * 128 : 0) + (size_t)lrow * 128 + j * 32;
        const uint32_t bpl = sb + (uint32_t)(8 + (j & 1) * 2 + lsel) * PLANE_B;
#pragma unroll
        for (int jj = 0; jj < 4; jj++) cp16(bpl + swz(lrow, jj), bsrc + jj * 8);
    };
    auto chainCompute = [&](int woff) {
#pragma unroll
        for (int mt = 0; mt < 4; mt++)
#pragma unroll
            for (int nt = 0; nt < 4; nt++)
#pragma unroll
                for (int j = 0; j < 4; j++) acc[mt][nt][j] = 0.0f;
        issueChB(woff, 0); CP_COMMIT();
        issueChB(woff, 1); CP_COMMIT();
        CP_WAIT1();
        __syncthreads();
#pragma unroll 1
        for (int j = 0; j < 4; j++) {
            if (j > 0) {
                __syncthreads();
                if (j + 1 < 4) { issueChB(woff, j + 1); CP_COMMIT(); CP_WAIT1(); }
                else CP_WAIT0();
                __syncthreads();
            }
            const uint32_t aHi = sb + (uint32_t)j * PLANE_B;
            const uint32_t bHi = sb + (uint32_t)(8 + (j & 1) * 2) * PLANE_B;
            computeAt(aHi, aHi + 4 * PLANE_B, bHi, bHi + PLANE_B);
        }
    };

    // ---- chain stage 1 ----
    __syncthreads();
    storeTileSmem(bias, GA0, GAI0, GA1, GAI1, doRelu);
    chainCompute(cW);

    if (chainF) {
#pragma unroll
        for (int mt = 0; mt < 4; mt++) {
            const int r0 = row0 + rowG * 64 + mt * 16 + rIn;
            const int r1 = r0 + 8;
#pragma unroll
            for (int nt = 0; nt < 4; nt++) {
                const int col = colG * 32 + nt * 8 + cIn;
                const float b0 = __ldg(&cB[col]), b1 = __ldg(&cB[col + 1]);
                if (r0 < M)
                    *(float2*)(cCf + (size_t)r0 * H_ + col) =
                        make_float2(acc[mt][nt][0] + b0, acc[mt][nt][1] + b1);
                if (r1 < M)
                    *(float2*)(cCf + (size_t)r1 * H_ + col) =
                        make_float2(acc[mt][nt][2] + b0, acc[mt][nt][3] + b1);
            }
        }
        return;
    }

    // ---- chain stage 2 + head ----
    __syncthreads();
    storeTileSmem(cB, cGA0, cGAI0, cGA1, cGAI1, 1);
    chainCompute(fhW1);
    {
        float h0[4], h1[4];
#pragma unroll
        for (int mt = 0; mt < 4; mt++) { h0[mt] = 0.f; h1[mt] = 0.f; }
#pragma unroll
        for (int mt = 0; mt < 4; mt++)
#pragma unroll
            for (int nt = 0; nt < 4; nt++) {
                const int col = colG * 32 + nt * 8 + cIn;
                const float b0 = __ldg(&fhB1[col]), b1 = __ldg(&fhB1[col + 1]);
                const float w20 = __ldg(&hw2[col]), w21 = __ldg(&hw2[col + 1]);
                h0[mt] = fmaf(fmaxf(acc[mt][nt][0] + b0, 0.f), w20, h0[mt]);
                h0[mt] = fmaf(fmaxf(acc[mt][nt][1] + b1, 0.f), w21, h0[mt]);
                h1[mt] = fmaf(fmaxf(acc[mt][nt][2] + b0, 0.f), w20, h1[mt]);
                h1[mt] = fmaf(fmaxf(acc[mt][nt][3] + b1, 0.f), w21, h1[mt]);
            }
#pragma unroll
        for (int mt = 0; mt < 4; mt++) {
            h0[mt] += __shfl_xor_sync(0xffffffffu, h0[mt], 1);
            h0[mt] += __shfl_xor_sync(0xffffffffu, h0[mt], 2);
            h1[mt] += __shfl_xor_sync(0xffffffffu, h1[mt], 1);
            h1[mt] += __shfl_xor_sync(0xffffffffu, h1[mt], 2);
        }
        __syncthreads();
        if ((lane & 3) == 0) {
#pragma unroll
            for (int mt = 0; mt < 4; mt++) {
                atomicAdd(&partial[rowG * 64 + mt * 16 + rIn], h0[mt]);
                atomicAdd(&partial[rowG * 64 + mt * 16 + rIn + 8], h1[mt]);
            }
        }
        __syncthreads();
        if (tid < 128) {
            const int r = row0 + tid;
            if (r < M) hout[r] = partial[tid] + __ldg(&hb2[0]);
        }
    }
}

// ---------------------------------------------------------------------------
extern "C" void kernel_launch(void* const* d_in, const int* in_sizes, int n_in,
                              void* d_out, int out_size) {
    const float* tx_x         = (const float*)d_in[0];
    const int*   e_card       = (const int*)d_in[3];
    const int*   e_merch      = (const int*)d_in[5];
    const float* card_emb     = (const float*)d_in[7];
    const float* merch_emb    = (const float*)d_in[8];
    const float* card_proj_W  = (const float*)d_in[9];
    const float* card_proj_b  = (const float*)d_in[10];
    const float* merch_proj_W = (const float*)d_in[11];
    const float* merch_proj_b = (const float*)d_in[12];
    const float* tx_W         = (const float*)d_in[13];
    const float* tx_b         = (const float*)d_in[14];
    const float* conv_Wl      = (const float*)d_in[15];
    const float* conv_bl      = (const float*)d_in[16];
    const float* conv_Wr      = (const float*)d_in[17];
    const float* h1_W         = (const float*)d_in[18];
    const float* h1_b         = (const float*)d_in[19];
    const float* h2_W         = (const float*)d_in[20];
    const float* h2_b         = (const float*)d_in[21];
    float* out = (float*)d_out;

    __nv_bfloat16 *atx0, *acard0, *amerch0, *wt;
    float *pc0, *pm0, *pc1, *pm1, *aggc, *aggm, *cntc, *cntm, *bcomb, *zbias;
    cudaGetSymbolAddress((void**)&atx0,    g_atx0);
    cudaGetSymbolAddress((void**)&acard0,  g_acard0);
    cudaGetSymbolAddress((void**)&amerch0, g_amerch0);
    cudaGetSymbolAddress((void**)&pc0,   g_pcard0);
    cudaGetSymbolAddress((void**)&pm0,   g_pmerch0);
    cudaGetSymbolAddress((void**)&pc1,   g_pcard1);
    cudaGetSymbolAddress((void**)&pm1,   g_pmerch1);
    cudaGetSymbolAddress((void**)&aggc,  g_aggc);
    cudaGetSymbolAddress((void**)&aggm,  g_aggm);
    cudaGetSymbolAddress((void**)&cntc,  g_cntc);
    cudaGetSymbolAddress((void**)&cntm,  g_cntm);
    cudaGetSymbolAddress((void**)&bcomb, g_bcomb);
    cudaGetSymbolAddress((void**)&zbias, g_zbias);
    cudaGetSymbolAddress((void**)&wt,    g_wt);

    const size_t PTX = (size_t)N_TX * H_;
    const size_t PCD = (size_t)N_CARD * H_;
    const size_t PMR = (size_t)N_MERCH * H_;

    cudaFuncSetAttribute(mma_gemm, cudaFuncAttributeMaxDynamicSharedMemorySize, SMEM_BYTES);

    cudaStream_t s0 = 0;

    PrepArgs pa;
    {
        int i = 0;
        auto ent = [&](const float* s1, const float* s2, int K, int off) {
            pa.e[i].s1 = s1; pa.e[i].s2 = s2; pa.e[i].K = K; pa.e[i].off = off; i++;
        };
        const size_t WSZ = (size_t)H_ * H_;
        ent(tx_W,         nullptr, 128, OFF_TXW);
        ent(card_proj_W,  nullptr,  64, OFF_CPROJ);
        ent(merch_proj_W, nullptr,  64, OFF_MPROJ);
        ent(h1_W,         nullptr, 128, OFF_H1);
        for (int l = 0; l < 2; l++) {
            const float* Wl0 = conv_Wl + (size_t)(l * 4 + 0) * WSZ;
            const float* Wl1 = conv_Wl + (size_t)(l * 4 + 1) * WSZ;
            const float* Wl2 = conv_Wl + (size_t)(l * 4 + 2) * WSZ;
            const float* Wl3 = conv_Wl + (size_t)(l * 4 + 3) * WSZ;
            const float* Wr0 = conv_Wr + (size_t)(l * 4 + 0) * WSZ;
            const float* Wr1 = conv_Wr + (size_t)(l * 4 + 1) * WSZ;
            const float* Wr2 = conv_Wr + (size_t)(l * 4 + 2) * WSZ;
            const float* Wr3 = conv_Wr + (size_t)(l * 4 + 3) * WSZ;
            ent(Wl0, nullptr, 128, OFF_LAYER(l, 0));
            ent(Wl2, nullptr, 128, OFF_LAYER(l, 1));
            ent(Wr0, Wr2,     128, OFF_LAYER(l, 2));
            ent(Wl1, nullptr, 128, OFF_LAYER(l, 3));
            ent(Wr1, nullptr, 128, OFF_LAYER(l, 4));
            ent(Wl3, nullptr, 128, OFF_LAYER(l, 5));
            ent(Wr3, nullptr, 128, OFF_LAYER(l, 6));
        }
        pa.bl = conv_bl;
        pa.bc = bcomb;
    }

    auto blocks = [](int m) { return (m + 127) / 128; };
    const __nv_bfloat16* NB = nullptr;
    const float* NF = nullptr;
    const int* NI = nullptr;
    float* NFo = nullptr;

    cudaStream_t sx, sy;
    cudaStreamCreateWithFlags(&sx, cudaStreamNonBlocking);
    cudaStreamCreateWithFlags(&sy, cudaStreamNonBlocking);
    cudaEvent_t evRoot, evPrep, evH0, evEnc, evS0, evZ;
    cudaEventCreateWithFlags(&evRoot, cudaEventDisableTiming);
    cudaEventCreateWithFlags(&evPrep, cudaEventDisableTiming);
    cudaEventCreateWithFlags(&evH0,   cudaEventDisableTiming);
    cudaEventCreateWithFlags(&evEnc,  cudaEventDisableTiming);
    cudaEventCreateWithFlags(&evS0,   cudaEventDisableTiming);
    cudaEventCreateWithFlags(&evZ,    cudaEventDisableTiming);

    // fork both side streams from s0 FIRST (stream-capture requirement)
    cudaEventRecord(evRoot, s0);
    cudaStreamWaitEvent(sy, evRoot, 0);
    cudaStreamWaitEvent(sx, evRoot, 0);

    // sy: zero agg/cnt buffers (single kernel, overlaps prep on s0)
    zero_buffers<<<(N_CARD * H_ + 255) / 256, 256, 0, sy>>>(aggc, aggm, cntc, cntm);
    cudaEventRecord(evZ, sy);

    // s0: weight prep (includes bias combine)
    prep_weights<<<19, 256, 0, s0>>>(pa, wt);
    cudaEventRecord(evPrep, s0);
    cudaStreamWaitEvent(sx, evPrep, 0);
    cudaStreamWaitEvent(sy, evPrep, 0);

    // s0: tx encoder half 0 (rows [0, HALF))
    mma_gemm<<<blocks(HALF), 256, SMEM_BYTES, s0>>>(HALF,
        tx_x, NB, NB, nullptr, nullptr, OFF_TXW, 128,
        nullptr, NB, NB, nullptr, 0, 0,
        nullptr, NB, NB, 0, 0,
        wt, tx_b, atx0, atx0 + PTX, 1, nullptr,
        NF, NI, NF, NI,
        0, nullptr, NF, NI, NF, NI, NFo,
        0, nullptr, nullptr, nullptr, nullptr);
    cudaEventRecord(evH0, s0);

    // sy: scatter half 0 (edges [0, HALF)) — overlaps enc half 1 on s0
    cudaStreamWaitEvent(sy, evH0, 0);
    scatter_kernel<<<(HALF * 32 + 255) / 256, 256, 0, sy>>>(
        atx0, atx0 + PTX, e_card, e_merch, aggc, aggm, cntc, cntm, 0, HALF);
    cudaEventRecord(evS0, sy);

    // s0: tx encoder half 1 (rows [HALF, N_TX))
    mma_gemm<<<blocks(N_TX - HALF), 256, SMEM_BYTES, s0>>>(N_TX - HALF,
        tx_x + (size_t)HALF * H_, NB, NB, nullptr, nullptr, OFF_TXW, 128,
        nullptr, NB, NB, nullptr, 0, 0,
        nullptr, NB, NB, 0, 0,
        wt, tx_b, atx0 + (size_t)HALF * H_, atx0 + PTX + (size_t)HALF * H_, 1, nullptr,
        NF, NI, NF, NI,
        0, nullptr, NF, NI, NF, NI, NFo,
        0, nullptr, nullptr, nullptr, nullptr);

    // sx (overlapped): card/merch encoders (+P0 chains)
    mma_gemm<<<blocks(N_CARD), 256, SMEM_BYTES, sx>>>(N_CARD,
        card_emb, NB, NB, nullptr, nullptr, OFF_CPROJ, 64,
        nullptr, NB, NB, nullptr, 0, 0,
        nullptr, NB, NB, 0, 0,
        wt, card_proj_b, acard0, acard0 + PCD, 0, nullptr,
        NF, NI, NF, NI,
        OFF_LAYER(0, 0), zbias, NF, NI, NF, NI, pc0,
        0, nullptr, nullptr, nullptr, nullptr);
    mma_gemm<<<blocks(N_MERCH), 256, SMEM_BYTES, sx>>>(N_MERCH,
        merch_emb, NB, NB, nullptr, nullptr, OFF_MPROJ, 64,
        nullptr, NB, NB, nullptr, 0, 0,
        nullptr, NB, NB, 0, 0,
        wt, merch_proj_b, amerch0, amerch0 + PMR, 0, nullptr,
        NF, NI, NF, NI,
        OFF_LAYER(0, 1), zbias, NF, NI, NF, NI, pm0,
        0, nullptr, nullptr, nullptr, nullptr);
    cudaEventRecord(evEnc, sx);

    // s0: scatter half 1 (needs zero_buffers + enc half 1)
    cudaStreamWaitEvent(s0, evZ, 0);
    scatter_kernel<<<(HALF * 32 + 255) / 256, 256, 0, s0>>>(
        atx0, atx0 + PTX, e_card, e_merch, aggc, aggm, cntc, cntm, HALF, N_EDGE - HALF);

    // join: node updates need both scatters + encoders
    cudaStreamWaitEvent(s0, evS0, 0);
    cudaStreamWaitEvent(s0, evEnc, 0);

    mma_gemm<<<blocks(N_CARD), 256, SMEM_BYTES, s0>>>(N_CARD,
        aggc, NB, NB, nullptr, cntc, OFF_LAYER(0, 3), 128,
        nullptr, acard0, acard0 + PCD, nullptr, OFF_LAYER(0, 4), 128,
        nullptr, NB, NB, 0, 0,
        wt, conv_bl + 1 * H_, nullptr, nullptr, 1, nullptr,
        NF, NI, NF, NI,
        OFF_LAYER(1, 0), zbias, NF, NI, NF, NI, pc1,
        0, nullptr, nullptr, nullptr, nullptr);
    mma_gemm<<<blocks(N_MERCH), 256, SMEM_BYTES, s0>>>(N_MERCH,
        aggm, NB, NB, nullptr, cntm, OFF_LAYER(0, 5), 128,
        nullptr, amerch0, amerch0 + PMR, nullptr, OFF_LAYER(0, 6), 128,
        nullptr, NB, NB, 0, 0,
        wt, conv_bl + 3 * H_, nullptr, nullptr, 1, nullptr,
        NF, NI, NF, NI,
        OFF_LAYER(1, 1), zbias, NF, NI, NF, NI, pm1,
        0, nullptr, nullptr, nullptr, nullptr);

    // MEGA: layer-0 tx -> layer-1 tx -> head
    mma_gemm<<<blocks(N_TX), 256, SMEM_BYTES, s0>>>(N_TX,
        nullptr, atx0, atx0 + PTX, nullptr, nullptr, OFF_LAYER(0, 2), 128,
        nullptr, NB, NB, nullptr, 0, 0,
        nullptr, NB, NB, 0, 0,
        wt, bcomb, nullptr, nullptr, 1, nullptr,
        pc0, e_card, pm0, e_merch,
        OFF_LAYER(1, 2), bcomb + H_, pc1, e_card, pm1, e_merch, NFo,
        OFF_H1, h1_b, h2_W, h2_b, out);

    cudaEventDestroy(evRoot);
    cudaEventDestroy(evPrep);
    cudaEventDestroy(evH0);
    cudaEventDestroy(evEnc);
    cudaEventDestroy(evS0);
    cudaEventDestroy(evZ);
    cudaStreamDestroy(sx);
    cudaStreamDestroy(sy);
}